// round 1
// baseline (speedup 1.0000x reference)
#include <cuda_runtime.h>
#include <math.h>

// ---------------- fixed problem shapes ----------------
#define NN   4
#define CC   1024
#define DD   768
#define HH   12
#define EE   32
#define MM   4
#define PP   256
#define RR   (NN*PP)     // 1024
#define KBL  12          // EMB/BLOCK
#define NOUT 97

// ---------------- scratch (static device globals; no runtime alloc) ----------
__device__ float g_ent_emb[NN*EE*DD];        // [n,E,d]
__device__ float g_ent_att[NN*EE*HH*CC];     // [n,E,h,c]
__device__ float g_ht_att [NN*PP*CC];        // [n,P,c]
__device__ float g_rs     [RR*DD];           // [R,d]
__device__ float g_hs2    [RR*DD];
__device__ float g_ts2    [RR*DD];

// ---------------- packed fp32x2 helpers (Blackwell FFMA2 path) --------------
__device__ __forceinline__ unsigned long long dup_f32x2(float x) {
    unsigned long long r;
    asm("mov.b64 %0, {%1, %1};" : "=l"(r) : "f"(x));
    return r;
}
__device__ __forceinline__ unsigned long long fma_f32x2(unsigned long long a,
                                                        unsigned long long b,
                                                        unsigned long long c) {
    unsigned long long d;
    asm("fma.rn.f32x2 %0, %1, %2, %3;" : "=l"(d) : "l"(a), "l"(b), "l"(c));
    return d;
}
__device__ __forceinline__ float2 unpack_f32x2(unsigned long long v) {
    float lo, hi;
    asm("mov.b64 {%0, %1}, %2;" : "=f"(lo), "=f"(hi) : "l"(v));
    return make_float2(lo, hi);
}

// ============================================================================
// K1: entity embeddings = logsumexp over M mentions
// grid: NN*EE blocks, 256 threads
// ============================================================================
__global__ void k_ent_emb(const float* __restrict__ seq,
                          const int*   __restrict__ mpos) {
    int be = blockIdx.x;            // b*EE + e
    int b  = be / EE;
    const int* mp = mpos + be*MM;
    int p0 = mp[0], p1 = mp[1], p2 = mp[2], p3 = mp[3];
    const float* sb = seq + (long)b*CC*DD;
    for (int dd = threadIdx.x; dd < DD; dd += blockDim.x) {
        float v0 = sb[p0*DD+dd], v1 = sb[p1*DD+dd];
        float v2 = sb[p2*DD+dd], v3 = sb[p3*DD+dd];
        float mx = fmaxf(fmaxf(v0, v1), fmaxf(v2, v3));
        float s  = expf(v0-mx) + expf(v1-mx) + expf(v2-mx) + expf(v3-mx);
        g_ent_emb[be*DD + dd] = mx + logf(s);
    }
}

// ============================================================================
// K2: entity attention = mean over M mention attention rows
// grid: NN*EE*HH blocks, 256 threads
// ============================================================================
__global__ void k_ent_att(const float* __restrict__ att,
                          const int*   __restrict__ mpos) {
    int id = blockIdx.x;            // (b*EE+e)*HH + hd
    int hd = id % HH;
    int be = id / HH;
    int b  = be / EE;
    const int* mp = mpos + be*MM;
    const float* ab = att + (long)(b*HH + hd)*CC*CC;
    float* ob = g_ent_att + (long)id*CC;
    int q0 = mp[0]*CC, q1 = mp[1]*CC, q2 = mp[2]*CC, q3 = mp[3]*CC;
    for (int c = threadIdx.x; c < CC; c += blockDim.x) {
        float s = ab[q0+c] + ab[q1+c] + ab[q2+c] + ab[q3+c];
        ob[c] = s * 0.25f;
    }
}

// ============================================================================
// K3: ht_att = mean_h(h_att * t_att), then row-normalize over c
// grid: NN*PP blocks, 256 threads
// ============================================================================
__global__ void k_ht_att(const int* __restrict__ hts) {
    int bp = blockIdx.x;            // b*PP + p
    int b  = bp / PP;
    int eh = hts[bp*2 + 0];
    int et = hts[bp*2 + 1];
    const float* ah = g_ent_att + (long)(b*EE + eh)*HH*CC;
    const float* at = g_ent_att + (long)(b*EE + et)*HH*CC;

    float v[4];
    float lsum = 0.f;
    #pragma unroll
    for (int q = 0; q < 4; q++) {
        int c = q*256 + threadIdx.x;
        float s = 0.f;
        #pragma unroll
        for (int hd = 0; hd < HH; hd++)
            s += ah[hd*CC + c] * at[hd*CC + c];
        s *= (1.0f / HH);
        v[q] = s;
        lsum += s;
    }
    __shared__ float red[256];
    red[threadIdx.x] = lsum;
    __syncthreads();
    for (int st = 128; st > 0; st >>= 1) {
        if (threadIdx.x < st) red[threadIdx.x] += red[threadIdx.x + st];
        __syncthreads();
    }
    float inv = 1.0f / (red[0] + 1e-30f);
    #pragma unroll
    for (int q = 0; q < 4; q++) {
        int c = q*256 + threadIdx.x;
        g_ht_att[(long)bp*CC + c] = v[q] * inv;
    }
}

// ============================================================================
// K4: rs[b,p,:] = sum_c ht_att[b,p,c] * seq[b,c,:]    (per-doc GEMM 256x768x1024)
// grid: (DD/64, PP/64, NN) = (12,4,4), 256 threads, 4x4 microtile, f32x2 FMA
// ============================================================================
__global__ void __launch_bounds__(256, 2) k_rs(const float* __restrict__ seq) {
    int b  = blockIdx.z;
    int p0 = blockIdx.y * 64;
    int d0 = blockIdx.x * 64;
    const float* A = g_ht_att + (long)b*PP*CC;   // [256,1024]
    const float* B = seq      + (long)b*CC*DD;   // [1024,768]

    __shared__ float As[16][68];   // [k][p] transposed, padded
    __shared__ float Bs[16][64];   // [k][d]

    int tid = threadIdx.x;
    int tx  = tid % 16;            // d-group (4 wide)
    int ty  = tid / 16;            // p-group (4 wide)

    unsigned long long acc[4][2];
    #pragma unroll
    for (int i = 0; i < 4; i++) { acc[i][0] = 0ull; acc[i][1] = 0ull; }

    for (int kc = 0; kc < CC; kc += 16) {
        #pragma unroll
        for (int l = 0; l < 4; l++) {
            int idx = l*256 + tid;
            int cA = idx % 16, pA = idx / 16;
            As[cA][pA] = A[(p0 + pA)*CC + kc + cA];
        }
        #pragma unroll
        for (int l = 0; l < 4; l++) {
            int idx = l*256 + tid;
            int xB = idx % 64, kB = idx / 64;
            Bs[kB][xB] = B[(long)(kc + kB)*DD + d0 + xB];
        }
        __syncthreads();
        #pragma unroll
        for (int kk = 0; kk < 16; kk++) {
            float4 a4 = *(const float4*)&As[kk][ty*4];
            const unsigned long long* bw = (const unsigned long long*)&Bs[kk][0];
            unsigned long long b0 = bw[tx*2 + 0];
            unsigned long long b1 = bw[tx*2 + 1];
            const float* af = (const float*)&a4;
            #pragma unroll
            for (int ri = 0; ri < 4; ri++) {
                unsigned long long ad = dup_f32x2(af[ri]);
                acc[ri][0] = fma_f32x2(ad, b0, acc[ri][0]);
                acc[ri][1] = fma_f32x2(ad, b1, acc[ri][1]);
            }
        }
        __syncthreads();
    }
    #pragma unroll
    for (int ri = 0; ri < 4; ri++) {
        long row = (long)(b*PP + p0 + ty*4 + ri);
        float* op = g_rs + row*DD + d0 + tx*4;
        float2 u = unpack_f32x2(acc[ri][0]);
        float2 v = unpack_f32x2(acc[ri][1]);
        op[0] = u.x; op[1] = u.y; op[2] = v.x; op[3] = v.y;
    }
}

// ============================================================================
// K5: hs2/ts2 = tanh(concat(ent_emb[ent], rs) @ W + b)   (1024x768x1536 GEMM)
// grid: (DD/64, RR/64) = (12,16), 256 threads; launched twice (head/tail)
// ============================================================================
__global__ void __launch_bounds__(256, 2) k_ht_gemm(const float* __restrict__ W,
                                                    const float* __restrict__ bias,
                                                    int col,
                                                    const int* __restrict__ hts) {
    int d0 = blockIdx.x * 64;
    int r0 = blockIdx.y * 64;
    float* out = col ? g_ts2 : g_hs2;

    __shared__ float As[16][68];
    __shared__ float Bs[16][64];
    __shared__ int   aOff[64];

    int tid = threadIdx.x;
    if (tid < 64) {
        int r = r0 + tid;
        int b = r >> 8;            // /PP
        int p = r & 255;
        int ent = hts[(b*PP + p)*2 + col];
        aOff[tid] = (b*EE + ent)*DD;
    }
    __syncthreads();

    int tx = tid % 16, ty = tid / 16;
    unsigned long long acc[4][2];
    #pragma unroll
    for (int i = 0; i < 4; i++) { acc[i][0] = 0ull; acc[i][1] = 0ull; }

    for (int kc = 0; kc < 2*DD; kc += 16) {
        #pragma unroll
        for (int l = 0; l < 4; l++) {
            int idx = l*256 + tid;
            int cA = idx % 16, pA = idx / 16;
            int cg = kc + cA;
            float v = (cg < DD) ? g_ent_emb[aOff[pA] + cg]
                                : g_rs[(long)(r0 + pA)*DD + cg - DD];
            As[cA][pA] = v;
        }
        #pragma unroll
        for (int l = 0; l < 4; l++) {
            int idx = l*256 + tid;
            int xB = idx % 64, kB = idx / 64;
            Bs[kB][xB] = W[(long)(kc + kB)*DD + d0 + xB];
        }
        __syncthreads();
        #pragma unroll
        for (int kk = 0; kk < 16; kk++) {
            float4 a4 = *(const float4*)&As[kk][ty*4];
            const unsigned long long* bw = (const unsigned long long*)&Bs[kk][0];
            unsigned long long b0 = bw[tx*2 + 0];
            unsigned long long b1 = bw[tx*2 + 1];
            const float* af = (const float*)&a4;
            #pragma unroll
            for (int ri = 0; ri < 4; ri++) {
                unsigned long long ad = dup_f32x2(af[ri]);
                acc[ri][0] = fma_f32x2(ad, b0, acc[ri][0]);
                acc[ri][1] = fma_f32x2(ad, b1, acc[ri][1]);
            }
        }
        __syncthreads();
    }
    #pragma unroll
    for (int ri = 0; ri < 4; ri++) {
        long row = (long)(r0 + ty*4 + ri);
        float* op = out + row*DD + d0 + tx*4;
        float2 u = unpack_f32x2(acc[ri][0]);
        float2 v = unpack_f32x2(acc[ri][1]);
        op[0] = tanhf(u.x + bias[d0 + tx*4 + 0]);
        op[1] = tanhf(u.y + bias[d0 + tx*4 + 1]);
        op[2] = tanhf(v.x + bias[d0 + tx*4 + 2]);
        op[3] = tanhf(v.y + bias[d0 + tx*4 + 3]);
    }
}

// ============================================================================
// K6: init output with bias (d_out is poisoned before timing)
// ============================================================================
__global__ void k_init_out(const float* __restrict__ b_bil, float* __restrict__ out) {
    int i = blockIdx.x*256 + threadIdx.x;
    if (i < RR*NOUT) out[i] = b_bil[i % NOUT];
}

// ============================================================================
// K7: bilinear logits. out[r,o] += sum_{i,j} hs2[r,k64+i]*ts2[r,k64+j]*W[(k,i,j),o]
// grid: (KBL=12, RR/64=16) = 192 CTAs, 256 threads.
// BL generated on the fly; W streamed through smem; f32x2 FMA; atomic epilogue.
// ============================================================================
__global__ void __launch_bounds__(256, 2) k_bilinear(const float* __restrict__ Wb,
                                                     float* __restrict__ out) {
    int k  = blockIdx.x;
    int r0 = blockIdx.y * 64;

    __shared__ float tsT[64*64];     // [col][r]
    __shared__ float Ws [32*128];    // [kk][o] (o padded to 128, zeros past 97)

    int tid = threadIdx.x;
    int tr  = tid % 16;              // r-group (4 wide)
    int to  = tid / 16;              // o-group (8 wide)

    // stage ts2 tile transposed: tsT[col][r]
    #pragma unroll
    for (int l = 0; l < 16; l++) {
        int idx = l*256 + tid;
        int cx = idx % 64, ry = idx / 64;
        tsT[cx*64 + ry] = g_ts2[(long)(r0 + ry)*DD + k*64 + cx];
    }
    __syncthreads();

    unsigned long long acc[4][4];
    #pragma unroll
    for (int a = 0; a < 4; a++)
        #pragma unroll
        for (int c = 0; c < 4; c++) acc[a][c] = 0ull;

    const float* hsBase = g_hs2 + (long)r0*DD + k*64;

    for (int kc = 0; kc < 128; kc++) {
        int i  = kc >> 1;
        int j0 = (kc & 1) * 32;
        long wrow0 = (long)k*4096 + kc*32;

        // stage W chunk [32 kij rows][128 o]
        #pragma unroll
        for (int l = 0; l < 16; l++) {
            int idx = l*256 + tid;
            int o = idx % 128, kk = idx / 128;
            Ws[kk*128 + o] = (o < NOUT) ? Wb[(wrow0 + kk)*NOUT + o] : 0.0f;
        }
        // per-thread hs values for this i (L1/L2 resident)
        float ha[4];
        #pragma unroll
        for (int ri = 0; ri < 4; ri++)
            ha[ri] = hsBase[(tr*4 + ri)*DD + i];
        __syncthreads();

        #pragma unroll
        for (int kk = 0; kk < 32; kk++) {
            float4 tv = *(const float4*)&tsT[(j0 + kk)*64 + tr*4];
            const unsigned long long* wr = (const unsigned long long*)&Ws[kk*128];
            unsigned long long w0 = wr[to*4 + 0];
            unsigned long long w1 = wr[to*4 + 1];
            unsigned long long w2 = wr[to*4 + 2];
            unsigned long long w3 = wr[to*4 + 3];
            const float* tf = (const float*)&tv;
            #pragma unroll
            for (int ri = 0; ri < 4; ri++) {
                float bl = ha[ri] * tf[ri];
                unsigned long long bd = dup_f32x2(bl);
                acc[ri][0] = fma_f32x2(bd, w0, acc[ri][0]);
                acc[ri][1] = fma_f32x2(bd, w1, acc[ri][1]);
                acc[ri][2] = fma_f32x2(bd, w2, acc[ri][2]);
                acc[ri][3] = fma_f32x2(bd, w3, acc[ri][3]);
            }
        }
        __syncthreads();
    }

    // epilogue: atomic accumulate (12 k-blocks contribute per output)
    #pragma unroll
    for (int ri = 0; ri < 4; ri++) {
        int r = r0 + tr*4 + ri;
        #pragma unroll
        for (int pj = 0; pj < 4; pj++) {
            float2 u = unpack_f32x2(acc[ri][pj]);
            int o = to*8 + pj*2;
            if (o     < NOUT) atomicAdd(&out[r*NOUT + o    ], u.x);
            if (o + 1 < NOUT) atomicAdd(&out[r*NOUT + o + 1], u.y);
        }
    }
}

// ============================================================================
// launch
// ============================================================================
extern "C" void kernel_launch(void* const* d_in, const int* in_sizes, int n_in,
                              void* d_out, int out_size) {
    const float* seq    = (const float*)d_in[0];
    const float* att    = (const float*)d_in[1];
    const int*   mpos   = (const int*  )d_in[2];
    const int*   hts    = (const int*  )d_in[3];
    const float* W_head = (const float*)d_in[4];
    const float* b_head = (const float*)d_in[5];
    const float* W_tail = (const float*)d_in[6];
    const float* b_tail = (const float*)d_in[7];
    const float* W_bil  = (const float*)d_in[8];
    const float* b_bil  = (const float*)d_in[9];
    float* out = (float*)d_out;

    k_ent_emb<<<NN*EE, 256>>>(seq, mpos);
    k_ent_att<<<NN*EE*HH, 256>>>(att, mpos);
    k_ht_att<<<NN*PP, 256>>>(hts);
    k_rs<<<dim3(DD/64, PP/64, NN), 256>>>(seq);
    k_ht_gemm<<<dim3(DD/64, RR/64), 256>>>(W_head, b_head, 0, hts);
    k_ht_gemm<<<dim3(DD/64, RR/64), 256>>>(W_tail, b_tail, 1, hts);
    k_init_out<<<(RR*NOUT + 255)/256, 256>>>(b_bil, out);
    k_bilinear<<<dim3(KBL, RR/64), 256>>>(W_bil, out);
}

// round 2
// speedup vs baseline: 1.3584x; 1.3584x over previous
#include <cuda_runtime.h>
#include <math.h>

// ---------------- fixed problem shapes ----------------
#define NN   4
#define CC   1024
#define DD   768
#define HH   12
#define EE   32
#define MM   4
#define PP   256
#define RR   (NN*PP)     // 1024
#define KBL  12          // EMB/BLOCK
#define NOUT 97

// ---------------- scratch ----------------
__device__ float g_ent_emb[NN*EE*DD];        // [n,E,d]
__device__ float g_ent_att[NN*EE*HH*CC];     // [n,E,h,c]
__device__ float g_ht_att [NN*PP*CC];        // [R,c]
__device__ float g_rs     [RR*DD];           // [R,d]
__device__ float g_hs2    [RR*DD];
__device__ float g_ts2    [RR*DD];

// ---------------- packed fp32x2 helpers ----------------
__device__ __forceinline__ unsigned long long dup_f32x2(float x) {
    unsigned long long r;
    asm("mov.b64 %0, {%1, %1};" : "=l"(r) : "f"(x));
    return r;
}
__device__ __forceinline__ unsigned long long fma_f32x2(unsigned long long a,
                                                        unsigned long long b,
                                                        unsigned long long c) {
    unsigned long long d;
    asm("fma.rn.f32x2 %0, %1, %2, %3;" : "=l"(d) : "l"(a), "l"(b), "l"(c));
    return d;
}
__device__ __forceinline__ float2 unpack_f32x2(unsigned long long v) {
    float lo, hi;
    asm("mov.b64 {%0, %1}, %2;" : "=f"(lo), "=f"(hi) : "l"(v));
    return make_float2(lo, hi);
}

// ============================================================================
// K1: entity embeddings = logsumexp over M mentions
// ============================================================================
__global__ void k_ent_emb(const float* __restrict__ seq,
                          const int*   __restrict__ mpos) {
    int be = blockIdx.x;
    int b  = be / EE;
    const int* mp = mpos + be*MM;
    int p0 = mp[0], p1 = mp[1], p2 = mp[2], p3 = mp[3];
    const float* sb = seq + (long)b*CC*DD;
    for (int dd = threadIdx.x; dd < DD; dd += blockDim.x) {
        float v0 = sb[p0*DD+dd], v1 = sb[p1*DD+dd];
        float v2 = sb[p2*DD+dd], v3 = sb[p3*DD+dd];
        float mx = fmaxf(fmaxf(v0, v1), fmaxf(v2, v3));
        float s  = expf(v0-mx) + expf(v1-mx) + expf(v2-mx) + expf(v3-mx);
        g_ent_emb[be*DD + dd] = mx + logf(s);
    }
}

// ============================================================================
// K2: entity attention = mean over M mention attention rows
// ============================================================================
__global__ void k_ent_att(const float* __restrict__ att,
                          const int*   __restrict__ mpos) {
    int id = blockIdx.x;            // (b*EE+e)*HH + hd
    int hd = id % HH;
    int be = id / HH;
    int b  = be / EE;
    const int* mp = mpos + be*MM;
    const float* ab = att + (long)(b*HH + hd)*CC*CC;
    float* ob = g_ent_att + (long)id*CC;
    int q0 = mp[0]*CC, q1 = mp[1]*CC, q2 = mp[2]*CC, q3 = mp[3]*CC;
    for (int c = threadIdx.x; c < CC; c += blockDim.x) {
        float s = ab[q0+c] + ab[q1+c] + ab[q2+c] + ab[q3+c];
        ob[c] = s * 0.25f;
    }
}

// ============================================================================
// K3: ht_att = mean_h(h_att * t_att), row-normalized
// ============================================================================
__global__ void k_ht_att(const int* __restrict__ hts) {
    int bp = blockIdx.x;
    int b  = bp / PP;
    int eh = hts[bp*2 + 0];
    int et = hts[bp*2 + 1];
    const float* ah = g_ent_att + (long)(b*EE + eh)*HH*CC;
    const float* at = g_ent_att + (long)(b*EE + et)*HH*CC;

    float v[4];
    float lsum = 0.f;
    #pragma unroll
    for (int q = 0; q < 4; q++) {
        int c = q*256 + threadIdx.x;
        float s = 0.f;
        #pragma unroll
        for (int hd = 0; hd < HH; hd++)
            s += ah[hd*CC + c] * at[hd*CC + c];
        s *= (1.0f / HH);
        v[q] = s;
        lsum += s;
    }
    __shared__ float red[256];
    red[threadIdx.x] = lsum;
    __syncthreads();
    for (int st = 128; st > 0; st >>= 1) {
        if (threadIdx.x < st) red[threadIdx.x] += red[threadIdx.x + st];
        __syncthreads();
    }
    float inv = 1.0f / (red[0] + 1e-30f);
    #pragma unroll
    for (int q = 0; q < 4; q++) {
        int c = q*256 + threadIdx.x;
        g_ht_att[(long)bp*CC + c] = v[q] * inv;
    }
}

// ============================================================================
// K4: rs = ht_att @ seq  (double-buffered 64x64 tiles, f32x2 FMA)
// grid: (12, 16)
// ============================================================================
__global__ void __launch_bounds__(256, 3) k_rs(const float* __restrict__ seq) {
    int r0 = blockIdx.y * 64;
    int d0 = blockIdx.x * 64;
    int b  = r0 >> 8;
    const float* Bm = seq + (long)b*CC*DD;

    __shared__ float As[2][16][68];
    __shared__ float Bs[2][16][64];

    int tid = threadIdx.x;
    int cA = tid % 16, pA = tid / 16;   // A stage: col cA, rows pA + 16*l
    int xB = tid % 64, kB = tid / 64;   // B stage: col xB, rows kB + 4*l
    int tx = tid % 16, ty = tid / 16;   // compute micro

    float ra[4], rb[4];
    unsigned long long acc[4][2];
    #pragma unroll
    for (int i = 0; i < 4; i++) { acc[i][0] = 0ull; acc[i][1] = 0ull; }

    // prologue: stage tile 0
    #pragma unroll
    for (int l = 0; l < 4; l++) ra[l] = g_ht_att[(long)(r0 + pA + 16*l)*CC + cA];
    #pragma unroll
    for (int l = 0; l < 4; l++) rb[l] = Bm[(long)(kB + 4*l)*DD + d0 + xB];
    #pragma unroll
    for (int l = 0; l < 4; l++) As[0][cA][pA + 16*l] = ra[l];
    #pragma unroll
    for (int l = 0; l < 4; l++) Bs[0][kB + 4*l][xB] = rb[l];
    __syncthreads();

    const int NK = CC/16;
    for (int t = 0; t < NK; t++) {
        int buf = t & 1;
        if (t + 1 < NK) {
            int kc = (t + 1)*16;
            #pragma unroll
            for (int l = 0; l < 4; l++) ra[l] = g_ht_att[(long)(r0 + pA + 16*l)*CC + kc + cA];
            #pragma unroll
            for (int l = 0; l < 4; l++) rb[l] = Bm[(long)(kc + kB + 4*l)*DD + d0 + xB];
        }
        #pragma unroll
        for (int kk = 0; kk < 16; kk++) {
            float4 a4 = *(const float4*)&As[buf][kk][ty*4];
            const unsigned long long* bw = (const unsigned long long*)&Bs[buf][kk][0];
            unsigned long long b0 = bw[tx*2 + 0];
            unsigned long long b1 = bw[tx*2 + 1];
            const float* af = (const float*)&a4;
            #pragma unroll
            for (int ri = 0; ri < 4; ri++) {
                unsigned long long ad = dup_f32x2(af[ri]);
                acc[ri][0] = fma_f32x2(ad, b0, acc[ri][0]);
                acc[ri][1] = fma_f32x2(ad, b1, acc[ri][1]);
            }
        }
        if (t + 1 < NK) {
            #pragma unroll
            for (int l = 0; l < 4; l++) As[buf^1][cA][pA + 16*l] = ra[l];
            #pragma unroll
            for (int l = 0; l < 4; l++) Bs[buf^1][kB + 4*l][xB] = rb[l];
        }
        __syncthreads();
    }
    #pragma unroll
    for (int ri = 0; ri < 4; ri++) {
        long row = (long)(r0 + ty*4 + ri);
        float* op = g_rs + row*DD + d0 + tx*4;
        float2 u = unpack_f32x2(acc[ri][0]);
        float2 v = unpack_f32x2(acc[ri][1]);
        op[0] = u.x; op[1] = u.y; op[2] = v.x; op[3] = v.y;
    }
}

// ============================================================================
// K5: hs2/ts2 = tanh(concat(ent_emb[ent], rs) @ W + b)  — merged head+tail
// grid: (12, 16, 2)
// ============================================================================
__global__ void __launch_bounds__(256, 3) k_ht_gemm(const float* __restrict__ Wh,
                                                    const float* __restrict__ bh,
                                                    const float* __restrict__ Wt,
                                                    const float* __restrict__ bt,
                                                    const int* __restrict__ hts) {
    int d0  = blockIdx.x * 64;
    int r0  = blockIdx.y * 64;
    int col = blockIdx.z;
    const float* W    = col ? Wt : Wh;
    const float* bias = col ? bt : bh;
    float* out        = col ? g_ts2 : g_hs2;

    __shared__ float As[2][16][68];
    __shared__ float Bs[2][16][64];
    __shared__ int   aOff[64];

    int tid = threadIdx.x;
    if (tid < 64) {
        int r = r0 + tid;
        int ent = hts[r*2 + col];
        aOff[tid] = ((r >> 8)*EE + ent)*DD;
    }
    __syncthreads();

    int cA = tid % 16, pA = tid / 16;
    int xB = tid % 64, kB = tid / 64;
    int tx = tid % 16, ty = tid / 16;

    float ra[4], rb[4];
    unsigned long long acc[4][2];
    #pragma unroll
    for (int i = 0; i < 4; i++) { acc[i][0] = 0ull; acc[i][1] = 0ull; }

    // prologue (kc=0 always in ent_emb half)
    #pragma unroll
    for (int l = 0; l < 4; l++) ra[l] = g_ent_emb[aOff[pA + 16*l] + cA];
    #pragma unroll
    for (int l = 0; l < 4; l++) rb[l] = W[(long)(kB + 4*l)*DD + d0 + xB];
    #pragma unroll
    for (int l = 0; l < 4; l++) As[0][cA][pA + 16*l] = ra[l];
    #pragma unroll
    for (int l = 0; l < 4; l++) Bs[0][kB + 4*l][xB] = rb[l];
    __syncthreads();

    const int NK = (2*DD)/16;   // 96
    for (int t = 0; t < NK; t++) {
        int buf = t & 1;
        if (t + 1 < NK) {
            int kc = (t + 1)*16;
            if (kc < DD) {
                #pragma unroll
                for (int l = 0; l < 4; l++) ra[l] = g_ent_emb[aOff[pA + 16*l] + kc + cA];
            } else {
                #pragma unroll
                for (int l = 0; l < 4; l++) ra[l] = g_rs[(long)(r0 + pA + 16*l)*DD + kc - DD + cA];
            }
            #pragma unroll
            for (int l = 0; l < 4; l++) rb[l] = W[(long)(kc + kB + 4*l)*DD + d0 + xB];
        }
        #pragma unroll
        for (int kk = 0; kk < 16; kk++) {
            float4 a4 = *(const float4*)&As[buf][kk][ty*4];
            const unsigned long long* bw = (const unsigned long long*)&Bs[buf][kk][0];
            unsigned long long b0 = bw[tx*2 + 0];
            unsigned long long b1 = bw[tx*2 + 1];
            const float* af = (const float*)&a4;
            #pragma unroll
            for (int ri = 0; ri < 4; ri++) {
                unsigned long long ad = dup_f32x2(af[ri]);
                acc[ri][0] = fma_f32x2(ad, b0, acc[ri][0]);
                acc[ri][1] = fma_f32x2(ad, b1, acc[ri][1]);
            }
        }
        if (t + 1 < NK) {
            #pragma unroll
            for (int l = 0; l < 4; l++) As[buf^1][cA][pA + 16*l] = ra[l];
            #pragma unroll
            for (int l = 0; l < 4; l++) Bs[buf^1][kB + 4*l][xB] = rb[l];
        }
        __syncthreads();
    }
    #pragma unroll
    for (int ri = 0; ri < 4; ri++) {
        long row = (long)(r0 + ty*4 + ri);
        float* op = out + row*DD + d0 + tx*4;
        float2 u = unpack_f32x2(acc[ri][0]);
        float2 v = unpack_f32x2(acc[ri][1]);
        op[0] = tanhf(u.x + bias[d0 + tx*4 + 0]);
        op[1] = tanhf(u.y + bias[d0 + tx*4 + 1]);
        op[2] = tanhf(v.x + bias[d0 + tx*4 + 2]);
        op[3] = tanhf(v.y + bias[d0 + tx*4 + 3]);
    }
}

// ============================================================================
// K6: init output with bias
// ============================================================================
__global__ void k_init_out(const float* __restrict__ b_bil, float* __restrict__ out) {
    int i = blockIdx.x*256 + threadIdx.x;
    if (i < RR*NOUT) out[i] = b_bil[i % NOUT];
}

// ============================================================================
// K7: bilinear logits, r-tile 32, W double-buffered. grid (12, 32), 256 thr.
// out[r,o] += sum_{i,j} hs2[r,k64+i]*ts2[r,k64+j]*W[(k,i,j),o]
// ============================================================================
__global__ void __launch_bounds__(256, 3) k_bilinear(const float* __restrict__ Wb,
                                                     float* __restrict__ out) {
    int k  = blockIdx.x;
    int r0 = blockIdx.y * 32;

    __shared__ float tsT[64*32];        // [col][row]   8KB
    __shared__ float hsS[32*64];        // [row][col]   8KB
    __shared__ float Ws[2][32*128];     // [kij][o]    32KB  (total 48KB exactly)

    int tid = threadIdx.x;
    int tr  = tid % 16;                 // rows tr*2, tr*2+1
    int to  = tid / 16;                 // u64 cols to*4..to*4+3 (outputs to*8..to*8+7)

    // stage ts2 (transposed) and hs2 tiles once
    #pragma unroll
    for (int l = 0; l < 8; l++) {
        int idx = l*256 + tid;
        int cx = idx % 64, ry = idx / 64;
        tsT[cx*32 + ry] = g_ts2[(long)(r0 + ry)*DD + k*64 + cx];
        hsS[ry*64 + cx] = g_hs2[(long)(r0 + ry)*DD + k*64 + cx];
    }

    // stage W chunk 0
    const float* Wbase = Wb + (long)k*4096*NOUT;
    float wreg[16];
    #pragma unroll
    for (int l = 0; l < 16; l++) {
        int idx = l*256 + tid;
        int o = idx & 127, row = idx >> 7;
        wreg[l] = (o < NOUT) ? Wbase[(long)row*NOUT + o] : 0.0f;
    }
    #pragma unroll
    for (int l = 0; l < 16; l++) {
        int idx = l*256 + tid;
        Ws[0][idx] = wreg[l];
    }
    __syncthreads();

    unsigned long long acc[2][4];
    #pragma unroll
    for (int a = 0; a < 2; a++)
        #pragma unroll
        for (int c = 0; c < 4; c++) acc[a][c] = 0ull;

    for (int kc = 0; kc < 128; kc++) {
        int buf = kc & 1;
        int i   = kc >> 1;
        int j0  = (kc & 1) * 32;

        if (kc + 1 < 128) {
            long rbase = (long)(kc + 1)*32;
            #pragma unroll
            for (int l = 0; l < 16; l++) {
                int idx = l*256 + tid;
                int o = idx & 127, row = idx >> 7;
                wreg[l] = (o < NOUT) ? Wbase[(rbase + row)*NOUT + o] : 0.0f;
            }
        }

        float ha0 = hsS[(tr*2 + 0)*64 + i];
        float ha1 = hsS[(tr*2 + 1)*64 + i];

        #pragma unroll
        for (int kk = 0; kk < 32; kk++) {
            float2 tv = *(const float2*)&tsT[(j0 + kk)*32 + tr*2];
            const unsigned long long* wr = (const unsigned long long*)&Ws[buf][kk*128];
            unsigned long long w0 = wr[to*4 + 0];
            unsigned long long w1 = wr[to*4 + 1];
            unsigned long long w2 = wr[to*4 + 2];
            unsigned long long w3 = wr[to*4 + 3];
            float bl0 = ha0 * tv.x;
            float bl1 = ha1 * tv.y;
            unsigned long long bd0 = dup_f32x2(bl0);
            unsigned long long bd1 = dup_f32x2(bl1);
            acc[0][0] = fma_f32x2(bd0, w0, acc[0][0]);
            acc[0][1] = fma_f32x2(bd0, w1, acc[0][1]);
            acc[0][2] = fma_f32x2(bd0, w2, acc[0][2]);
            acc[0][3] = fma_f32x2(bd0, w3, acc[0][3]);
            acc[1][0] = fma_f32x2(bd1, w0, acc[1][0]);
            acc[1][1] = fma_f32x2(bd1, w1, acc[1][1]);
            acc[1][2] = fma_f32x2(bd1, w2, acc[1][2]);
            acc[1][3] = fma_f32x2(bd1, w3, acc[1][3]);
        }

        if (kc + 1 < 128) {
            #pragma unroll
            for (int l = 0; l < 16; l++) {
                int idx = l*256 + tid;
                Ws[buf^1][idx] = wreg[l];
            }
        }
        __syncthreads();
    }

    // epilogue: atomic accumulate (12 k-blocks per output)
    #pragma unroll
    for (int ri = 0; ri < 2; ri++) {
        int r = r0 + tr*2 + ri;
        #pragma unroll
        for (int pj = 0; pj < 4; pj++) {
            float2 u = unpack_f32x2(acc[ri][pj]);
            int o = to*8 + pj*2;
            if (o     < NOUT) atomicAdd(&out[r*NOUT + o    ], u.x);
            if (o + 1 < NOUT) atomicAdd(&out[r*NOUT + o + 1], u.y);
        }
    }
}

// ============================================================================
// launch
// ============================================================================
extern "C" void kernel_launch(void* const* d_in, const int* in_sizes, int n_in,
                              void* d_out, int out_size) {
    const float* seq    = (const float*)d_in[0];
    const float* att    = (const float*)d_in[1];
    const int*   mpos   = (const int*  )d_in[2];
    const int*   hts    = (const int*  )d_in[3];
    const float* W_head = (const float*)d_in[4];
    const float* b_head = (const float*)d_in[5];
    const float* W_tail = (const float*)d_in[6];
    const float* b_tail = (const float*)d_in[7];
    const float* W_bil  = (const float*)d_in[8];
    const float* b_bil  = (const float*)d_in[9];
    float* out = (float*)d_out;

    k_ent_emb<<<NN*EE, 256>>>(seq, mpos);
    k_ent_att<<<NN*EE*HH, 256>>>(att, mpos);
    k_ht_att<<<NN*PP, 256>>>(hts);
    k_rs<<<dim3(DD/64, RR/64), 256>>>(seq);
    k_ht_gemm<<<dim3(DD/64, RR/64, 2), 256>>>(W_head, b_head, W_tail, b_tail, hts);
    k_init_out<<<(RR*NOUT + 255)/256, 256>>>(b_bil, out);
    k_bilinear<<<dim3(KBL, RR/32), 256>>>(W_bil, out);
}

// round 3
// speedup vs baseline: 1.6795x; 1.2364x over previous
#include <cuda_runtime.h>
#include <math.h>

// ---------------- fixed problem shapes ----------------
#define NN   4
#define CC   1024
#define DD   768
#define HH   12
#define EE   32
#define MM   4
#define PP   256
#define RR   (NN*PP)     // 1024
#define KBL  12
#define NOUT 97

// ---------------- scratch ----------------
__device__ float g_ent_emb[NN*EE*DD];
__device__ float g_ent_att[NN*EE*HH*CC];
__device__ float g_ht_att [NN*PP*CC];
__device__ float g_rs     [RR*DD];
__device__ float g_hs2    [RR*DD];
__device__ float g_ts2    [RR*DD];

// ---------------- packed fp32x2 helpers ----------------
__device__ __forceinline__ unsigned long long dup_f32x2(float x) {
    unsigned long long r;
    asm("mov.b64 %0, {%1, %1};" : "=l"(r) : "f"(x));
    return r;
}
__device__ __forceinline__ unsigned long long fma_f32x2(unsigned long long a,
                                                        unsigned long long b,
                                                        unsigned long long c) {
    unsigned long long d;
    asm("fma.rn.f32x2 %0, %1, %2, %3;" : "=l"(d) : "l"(a), "l"(b), "l"(c));
    return d;
}
__device__ __forceinline__ float2 unpack_f32x2(unsigned long long v) {
    float lo, hi;
    asm("mov.b64 {%0, %1}, %2;" : "=f"(lo), "=f"(hi) : "l"(v));
    return make_float2(lo, hi);
}

// ============================================================================
// K1: entity embeddings = logsumexp over M mentions
// ============================================================================
__global__ void k_ent_emb(const float* __restrict__ seq,
                          const int*   __restrict__ mpos) {
    int be = blockIdx.x;
    int b  = be / EE;
    const int* mp = mpos + be*MM;
    int p0 = mp[0], p1 = mp[1], p2 = mp[2], p3 = mp[3];
    const float* sb = seq + (long)b*CC*DD;
    for (int dd = threadIdx.x; dd < DD; dd += blockDim.x) {
        float v0 = sb[p0*DD+dd], v1 = sb[p1*DD+dd];
        float v2 = sb[p2*DD+dd], v3 = sb[p3*DD+dd];
        float mx = fmaxf(fmaxf(v0, v1), fmaxf(v2, v3));
        float s  = expf(v0-mx) + expf(v1-mx) + expf(v2-mx) + expf(v3-mx);
        g_ent_emb[be*DD + dd] = mx + logf(s);
    }
}

// ============================================================================
// K2: entity attention = mean over M mention attention rows
// ============================================================================
__global__ void k_ent_att(const float* __restrict__ att,
                          const int*   __restrict__ mpos) {
    int id = blockIdx.x;            // (b*EE+e)*HH + hd
    int hd = id % HH;
    int be = id / HH;
    int b  = be / EE;
    const int* mp = mpos + be*MM;
    const float* ab = att + (long)(b*HH + hd)*CC*CC;
    float* ob = g_ent_att + (long)id*CC;
    int q0 = mp[0]*CC, q1 = mp[1]*CC, q2 = mp[2]*CC, q3 = mp[3]*CC;
    for (int c = threadIdx.x; c < CC; c += blockDim.x) {
        float s = ab[q0+c] + ab[q1+c] + ab[q2+c] + ab[q3+c];
        ob[c] = s * 0.25f;
    }
}

// ============================================================================
// K3: ht_att = mean_h(h_att * t_att), row-normalized
// ============================================================================
__global__ void k_ht_att(const int* __restrict__ hts) {
    int bp = blockIdx.x;
    int b  = bp / PP;
    int eh = hts[bp*2 + 0];
    int et = hts[bp*2 + 1];
    const float* ah = g_ent_att + (long)(b*EE + eh)*HH*CC;
    const float* at = g_ent_att + (long)(b*EE + et)*HH*CC;

    float v[4];
    float lsum = 0.f;
    #pragma unroll
    for (int q = 0; q < 4; q++) {
        int c = q*256 + threadIdx.x;
        float s = 0.f;
        #pragma unroll
        for (int hd = 0; hd < HH; hd++)
            s += ah[hd*CC + c] * at[hd*CC + c];
        s *= (1.0f / HH);
        v[q] = s;
        lsum += s;
    }
    __shared__ float red[256];
    red[threadIdx.x] = lsum;
    __syncthreads();
    for (int st = 128; st > 0; st >>= 1) {
        if (threadIdx.x < st) red[threadIdx.x] += red[threadIdx.x + st];
        __syncthreads();
    }
    float inv = 1.0f / (red[0] + 1e-30f);
    #pragma unroll
    for (int q = 0; q < 4; q++) {
        int c = q*256 + threadIdx.x;
        g_ht_att[(long)bp*CC + c] = v[q] * inv;
    }
}

// ============================================================================
// K4: rs = ht_att @ seq.  32x64 tiles, 128 thr, 4x4 per thread, double-buffered
// grid: (12, 32)
// ============================================================================
__global__ void __launch_bounds__(128, 8) k_rs(const float* __restrict__ seq) {
    int d0 = blockIdx.x * 64;
    int r0 = blockIdx.y * 32;
    int b  = r0 >> 8;
    const float* Bm = seq + (long)b*CC*DD;

    __shared__ __align__(16) float As[2][16][36];
    __shared__ __align__(16) float Bs[2][16][64];

    int tid = threadIdx.x;
    int cA = tid & 15, rA = tid >> 4;     // A stage: rows rA+8l
    int xB = tid & 63, kB = tid >> 6;     // B stage: rows kB+2l
    int tx = tid & 15, ty = tid >> 4;     // compute: rows ty*4+ri, cols tx*4

    float ra[4], rb[8];
    unsigned long long acc[4][2];
    #pragma unroll
    for (int i = 0; i < 4; i++) { acc[i][0] = 0ull; acc[i][1] = 0ull; }

    #pragma unroll
    for (int l = 0; l < 4; l++) ra[l] = g_ht_att[(long)(r0 + rA + 8*l)*CC + cA];
    #pragma unroll
    for (int l = 0; l < 8; l++) rb[l] = Bm[(long)(kB + 2*l)*DD + d0 + xB];
    #pragma unroll
    for (int l = 0; l < 4; l++) As[0][cA][rA + 8*l] = ra[l];
    #pragma unroll
    for (int l = 0; l < 8; l++) Bs[0][kB + 2*l][xB] = rb[l];
    __syncthreads();

    const int NK = CC/16;
    for (int t = 0; t < NK; t++) {
        int buf = t & 1;
        if (t + 1 < NK) {
            int kc = (t + 1)*16;
            #pragma unroll
            for (int l = 0; l < 4; l++) ra[l] = g_ht_att[(long)(r0 + rA + 8*l)*CC + kc + cA];
            #pragma unroll
            for (int l = 0; l < 8; l++) rb[l] = Bm[(long)(kc + kB + 2*l)*DD + d0 + xB];
        }
        #pragma unroll
        for (int kk = 0; kk < 16; kk++) {
            float4 a4 = *(const float4*)&As[buf][kk][ty*4];
            ulonglong2 bw = *(const ulonglong2*)&Bs[buf][kk][tx*4];
            const float* af = (const float*)&a4;
            #pragma unroll
            for (int ri = 0; ri < 4; ri++) {
                unsigned long long ad = dup_f32x2(af[ri]);
                acc[ri][0] = fma_f32x2(ad, bw.x, acc[ri][0]);
                acc[ri][1] = fma_f32x2(ad, bw.y, acc[ri][1]);
            }
        }
        if (t + 1 < NK) {
            #pragma unroll
            for (int l = 0; l < 4; l++) As[buf^1][cA][rA + 8*l] = ra[l];
            #pragma unroll
            for (int l = 0; l < 8; l++) Bs[buf^1][kB + 2*l][xB] = rb[l];
        }
        __syncthreads();
    }
    #pragma unroll
    for (int ri = 0; ri < 4; ri++) {
        long row = (long)(r0 + ty*4 + ri);
        float* op = g_rs + row*DD + d0 + tx*4;
        float2 u = unpack_f32x2(acc[ri][0]);
        float2 v = unpack_f32x2(acc[ri][1]);
        op[0] = u.x; op[1] = u.y; op[2] = v.x; op[3] = v.y;
    }
}

// ============================================================================
// K5: hs2/ts2 = tanh(concat(ent_emb[ent], rs) @ W + b). grid (12, 32, 2)
// ============================================================================
__global__ void __launch_bounds__(128, 8) k_ht_gemm(const float* __restrict__ Wh,
                                                    const float* __restrict__ bh,
                                                    const float* __restrict__ Wt,
                                                    const float* __restrict__ bt,
                                                    const int* __restrict__ hts) {
    int d0  = blockIdx.x * 64;
    int r0  = blockIdx.y * 32;
    int col = blockIdx.z;
    const float* W    = col ? Wt : Wh;
    const float* bias = col ? bt : bh;
    float* out        = col ? g_ts2 : g_hs2;

    __shared__ __align__(16) float As[2][16][36];
    __shared__ __align__(16) float Bs[2][16][64];
    __shared__ int aOff[32];

    int tid = threadIdx.x;
    if (tid < 32) {
        int r = r0 + tid;
        aOff[tid] = ((r >> 8)*EE + hts[r*2 + col])*DD;
    }
    __syncthreads();

    int cA = tid & 15, rA = tid >> 4;
    int xB = tid & 63, kB = tid >> 6;
    int tx = tid & 15, ty = tid >> 4;

    float ra[4], rb[8];
    unsigned long long acc[4][2];
    #pragma unroll
    for (int i = 0; i < 4; i++) { acc[i][0] = 0ull; acc[i][1] = 0ull; }

    #pragma unroll
    for (int l = 0; l < 4; l++) ra[l] = g_ent_emb[aOff[rA + 8*l] + cA];
    #pragma unroll
    for (int l = 0; l < 8; l++) rb[l] = W[(long)(kB + 2*l)*DD + d0 + xB];
    #pragma unroll
    for (int l = 0; l < 4; l++) As[0][cA][rA + 8*l] = ra[l];
    #pragma unroll
    for (int l = 0; l < 8; l++) Bs[0][kB + 2*l][xB] = rb[l];
    __syncthreads();

    const int NK = (2*DD)/16;   // 96
    for (int t = 0; t < NK; t++) {
        int buf = t & 1;
        if (t + 1 < NK) {
            int kc = (t + 1)*16;
            if (kc < DD) {
                #pragma unroll
                for (int l = 0; l < 4; l++) ra[l] = g_ent_emb[aOff[rA + 8*l] + kc + cA];
            } else {
                #pragma unroll
                for (int l = 0; l < 4; l++) ra[l] = g_rs[(long)(r0 + rA + 8*l)*DD + kc - DD + cA];
            }
            #pragma unroll
            for (int l = 0; l < 8; l++) rb[l] = W[(long)(kc + kB + 2*l)*DD + d0 + xB];
        }
        #pragma unroll
        for (int kk = 0; kk < 16; kk++) {
            float4 a4 = *(const float4*)&As[buf][kk][ty*4];
            ulonglong2 bw = *(const ulonglong2*)&Bs[buf][kk][tx*4];
            const float* af = (const float*)&a4;
            #pragma unroll
            for (int ri = 0; ri < 4; ri++) {
                unsigned long long ad = dup_f32x2(af[ri]);
                acc[ri][0] = fma_f32x2(ad, bw.x, acc[ri][0]);
                acc[ri][1] = fma_f32x2(ad, bw.y, acc[ri][1]);
            }
        }
        if (t + 1 < NK) {
            #pragma unroll
            for (int l = 0; l < 4; l++) As[buf^1][cA][rA + 8*l] = ra[l];
            #pragma unroll
            for (int l = 0; l < 8; l++) Bs[buf^1][kB + 2*l][xB] = rb[l];
        }
        __syncthreads();
    }
    #pragma unroll
    for (int ri = 0; ri < 4; ri++) {
        long row = (long)(r0 + ty*4 + ri);
        float* op = out + row*DD + d0 + tx*4;
        float2 u = unpack_f32x2(acc[ri][0]);
        float2 v = unpack_f32x2(acc[ri][1]);
        op[0] = tanhf(u.x + bias[d0 + tx*4 + 0]);
        op[1] = tanhf(u.y + bias[d0 + tx*4 + 1]);
        op[2] = tanhf(v.x + bias[d0 + tx*4 + 2]);
        op[3] = tanhf(v.y + bias[d0 + tx*4 + 3]);
    }
}

// ============================================================================
// K6: init output with bias
// ============================================================================
__global__ void k_init_out(const float* __restrict__ b_bil, float* __restrict__ out) {
    int i = blockIdx.x*256 + threadIdx.x;
    if (i < RR*NOUT) out[i] = b_bil[i % NOUT];
}

// ============================================================================
// K7: bilinear logits via G-factored accumulation:
//   out[r,o] += sum_i hs[r,ki] * ( sum_j ts[r,kj] * W[(k,i,j),o] )
// grid (24,16): x = k*2+half (2048 kij rows each), y = r-tile of 64.
// 256 threads: tr=tid&31 (2 rows), to=tid>>5 (12 o-cols; to==0 also does o=96).
// ============================================================================
__global__ void __launch_bounds__(256, 2) k_bilinear(const float* __restrict__ Wb,
                                                     float* __restrict__ out) {
    int k    = blockIdx.x >> 1;
    int half = blockIdx.x & 1;
    int r0   = blockIdx.y * 64;

    __shared__ __align__(16) float tsT[64][68];      // [j][r]
    __shared__ __align__(16) float hsT[32][68];      // [i_local][r]
    __shared__ __align__(16) float Ws[2][16*104];    // [kk][o], 104-padded

    int tid = threadIdx.x;
    int tr  = tid & 31;
    int to  = tid >> 5;

    // stage ts (transposed) and hs (transposed, this half's 32 i values)
    #pragma unroll
    for (int l = 0; l < 16; l++) {
        int idx = l*256 + tid;
        int cx = idx & 63, ry = idx >> 6;
        tsT[cx][ry] = g_ts2[(long)(r0 + ry)*DD + k*64 + cx];
    }
    #pragma unroll
    for (int l = 0; l < 8; l++) {
        int idx = l*256 + tid;
        int cx = idx & 31, ry = idx >> 5;
        hsT[cx][ry] = g_hs2[(long)(r0 + ry)*DD + k*64 + half*32 + cx];
    }

    const float* Wp = Wb + ((long)k*4096 + half*2048)*NOUT;

    // stage W rows [0,16)
    float wreg[7];
    #pragma unroll
    for (int l = 0; l < 7; l++) {
        int idx = l*256 + tid;
        if (idx < 16*104) {
            int row = idx / 104, o = idx - row*104;
            wreg[l] = (o < NOUT) ? Wp[(long)row*NOUT + o] : 0.0f;
        }
    }
    #pragma unroll
    for (int l = 0; l < 7; l++) {
        int idx = l*256 + tid;
        if (idx < 16*104) Ws[0][idx] = wreg[l];
    }
    __syncthreads();

    unsigned long long acc[2][6], G[2][6];
    float a96[2] = {0.f, 0.f}, g96[2] = {0.f, 0.f};
    #pragma unroll
    for (int a = 0; a < 2; a++)
        #pragma unroll
        for (int c = 0; c < 6; c++) { acc[a][c] = 0ull; G[a][c] = 0ull; }

    for (int s = 0; s < 128; s++) {
        int buf = s & 1;
        int j0  = (s & 3) * 16;

        if (s + 1 < 128) {
            long rbase = (long)(s + 1)*16;
            #pragma unroll
            for (int l = 0; l < 7; l++) {
                int idx = l*256 + tid;
                if (idx < 16*104) {
                    int row = idx / 104, o = idx - row*104;
                    wreg[l] = (o < NOUT) ? Wp[(rbase + row)*NOUT + o] : 0.0f;
                }
            }
        }

        #pragma unroll
        for (int kk = 0; kk < 16; kk++) {
            float2 tv = *(const float2*)&tsT[j0 + kk][tr*2];
            const ulonglong2* wp2 = (const ulonglong2*)&Ws[buf][kk*104 + to*12];
            ulonglong2 w0 = wp2[0];
            ulonglong2 w1 = wp2[1];
            ulonglong2 w2 = wp2[2];
            unsigned long long t0 = dup_f32x2(tv.x);
            unsigned long long t1 = dup_f32x2(tv.y);
            G[0][0] = fma_f32x2(t0, w0.x, G[0][0]);
            G[0][1] = fma_f32x2(t0, w0.y, G[0][1]);
            G[0][2] = fma_f32x2(t0, w1.x, G[0][2]);
            G[0][3] = fma_f32x2(t0, w1.y, G[0][3]);
            G[0][4] = fma_f32x2(t0, w2.x, G[0][4]);
            G[0][5] = fma_f32x2(t0, w2.y, G[0][5]);
            G[1][0] = fma_f32x2(t1, w0.x, G[1][0]);
            G[1][1] = fma_f32x2(t1, w0.y, G[1][1]);
            G[1][2] = fma_f32x2(t1, w1.x, G[1][2]);
            G[1][3] = fma_f32x2(t1, w1.y, G[1][3]);
            G[1][4] = fma_f32x2(t1, w2.x, G[1][4]);
            G[1][5] = fma_f32x2(t1, w2.y, G[1][5]);
            if (to == 0) {                       // warp-uniform branch
                float w96 = Ws[buf][kk*104 + 96];
                g96[0] = fmaf(tv.x, w96, g96[0]);
                g96[1] = fmaf(tv.y, w96, g96[1]);
            }
        }

        if ((s & 3) == 3) {                      // fold G into acc with hs_i
            int i_loc = s >> 2;
            float2 ha = *(const float2*)&hsT[i_loc][tr*2];
            unsigned long long h0 = dup_f32x2(ha.x);
            unsigned long long h1 = dup_f32x2(ha.y);
            #pragma unroll
            for (int c = 0; c < 6; c++) {
                acc[0][c] = fma_f32x2(h0, G[0][c], acc[0][c]);
                acc[1][c] = fma_f32x2(h1, G[1][c], acc[1][c]);
                G[0][c] = 0ull; G[1][c] = 0ull;
            }
            if (to == 0) {
                a96[0] = fmaf(ha.x, g96[0], a96[0]);
                a96[1] = fmaf(ha.y, g96[1], a96[1]);
                g96[0] = 0.f; g96[1] = 0.f;
            }
        }

        if (s + 1 < 128) {
            #pragma unroll
            for (int l = 0; l < 7; l++) {
                int idx = l*256 + tid;
                if (idx < 16*104) Ws[buf^1][idx] = wreg[l];
            }
        }
        __syncthreads();
    }

    // epilogue: atomic accumulate (24 kij-slices contribute per output)
    #pragma unroll
    for (int ri = 0; ri < 2; ri++) {
        int r = r0 + tr*2 + ri;
        float* orow = out + r*NOUT;
        #pragma unroll
        for (int c = 0; c < 6; c++) {
            float2 u = unpack_f32x2(acc[ri][c]);
            int o = to*12 + c*2;
            atomicAdd(&orow[o    ], u.x);
            atomicAdd(&orow[o + 1], u.y);
        }
    }
    if (to == 0) {
        atomicAdd(&out[(r0 + tr*2 + 0)*NOUT + 96], a96[0]);
        atomicAdd(&out[(r0 + tr*2 + 1)*NOUT + 96], a96[1]);
    }
}

// ============================================================================
// launch
// ============================================================================
extern "C" void kernel_launch(void* const* d_in, const int* in_sizes, int n_in,
                              void* d_out, int out_size) {
    const float* seq    = (const float*)d_in[0];
    const float* att    = (const float*)d_in[1];
    const int*   mpos   = (const int*  )d_in[2];
    const int*   hts    = (const int*  )d_in[3];
    const float* W_head = (const float*)d_in[4];
    const float* b_head = (const float*)d_in[5];
    const float* W_tail = (const float*)d_in[6];
    const float* b_tail = (const float*)d_in[7];
    const float* W_bil  = (const float*)d_in[8];
    const float* b_bil  = (const float*)d_in[9];
    float* out = (float*)d_out;

    k_ent_emb<<<NN*EE, 256>>>(seq, mpos);
    k_ent_att<<<NN*EE*HH, 256>>>(att, mpos);
    k_ht_att<<<NN*PP, 256>>>(hts);
    k_rs<<<dim3(DD/64, RR/32), 128>>>(seq);
    k_ht_gemm<<<dim3(DD/64, RR/32, 2), 128>>>(W_head, b_head, W_tail, b_tail, hts);
    k_init_out<<<(RR*NOUT + 255)/256, 256>>>(b_bil, out);
    k_bilinear<<<dim3(KBL*2, RR/64), 256>>>(W_bil, out);
}

// round 5
// speedup vs baseline: 2.2547x; 1.3425x over previous
#include <cuda_runtime.h>
#include <math.h>

// ---------------- fixed problem shapes ----------------
#define NN   4
#define CC   1024
#define DD   768
#define HH   12
#define EE   32
#define MM   4
#define PP   256
#define RR   (NN*PP)     // 1024
#define KBL  12
#define NOUT 97

// ---------------- scratch ----------------
__device__ float g_ent_emb[NN*EE*DD];
__device__ float g_ent_att[NN*EE*HH*CC];
__device__ float g_ht_att [NN*PP*CC];
__device__ float g_rs     [RR*DD];
__device__ float g_hs2    [RR*DD];
__device__ float g_ts2    [RR*DD];

// W_bil pre-packed for mma.sync fragments:
// 3072 chunks (16 kij rows each) x 13 n8-tiles x 32 lanes x uint4{hi0,hi1,lo0,lo1}
__device__ __align__(16) unsigned char g_Wp[3072UL*13*32*16];

// ---------------- packed fp32x2 helpers ----------------
__device__ __forceinline__ unsigned long long dup_f32x2(float x) {
    unsigned long long r;
    asm("mov.b64 %0, {%1, %1};" : "=l"(r) : "f"(x));
    return r;
}
__device__ __forceinline__ unsigned long long fma_f32x2(unsigned long long a,
                                                        unsigned long long b,
                                                        unsigned long long c) {
    unsigned long long d;
    asm("fma.rn.f32x2 %0, %1, %2, %3;" : "=l"(d) : "l"(a), "l"(b), "l"(c));
    return d;
}
__device__ __forceinline__ float2 unpack_f32x2(unsigned long long v) {
    float lo, hi;
    asm("mov.b64 {%0, %1}, %2;" : "=f"(lo), "=f"(hi) : "l"(v));
    return make_float2(lo, hi);
}

// ---------------- bf16 helpers ----------------
// result: lower16 = bf16(lo_f), upper16 = bf16(hi_f)
__device__ __forceinline__ unsigned pack_bf16x2(float hi_f, float lo_f) {
    unsigned r;
    asm("cvt.rn.bf16x2.f32 %0, %1, %2;" : "=r"(r) : "f"(hi_f), "f"(lo_f));
    return r;
}
// split (p0 lower, p1 upper) into bf16x2 hi + bf16x2 lo (residual)
__device__ __forceinline__ void split2(float p0, float p1, unsigned& hi, unsigned& lo) {
    hi = pack_bf16x2(p1, p0);
    float f0 = __uint_as_float(hi << 16);
    float f1 = __uint_as_float(hi & 0xffff0000u);
    lo = pack_bf16x2(p1 - f1, p0 - f0);
}

// warp mma: D += A(bf16) * B(bf16), m16n8k16, row.col, fp32 accum
__device__ __forceinline__ void mma_bf16(float* d, const unsigned* a,
                                         unsigned b0, unsigned b1) {
    asm volatile(
        "mma.sync.aligned.m16n8k16.row.col.f32.bf16.bf16.f32 "
        "{%0,%1,%2,%3}, {%4,%5,%6,%7}, {%8,%9}, {%0,%1,%2,%3};"
        : "+f"(d[0]), "+f"(d[1]), "+f"(d[2]), "+f"(d[3])
        : "r"(a[0]), "r"(a[1]), "r"(a[2]), "r"(a[3]), "r"(b0), "r"(b1));
}

// ============================================================================
// K0: pack W_bil into fragment layout (split bf16 hi/lo).  grid 3072, 128 thr
// chunk = 16 consecutive kij rows; per n8-tile, lane holds B-fragment regs.
// ============================================================================
__global__ void k_wt(const float* __restrict__ Wb) {
    __shared__ float Wsm[16*104];
    int chunk = blockIdx.x;
    int tid = threadIdx.x;
    int row0 = chunk * 16;

    for (int idx = tid; idx < 16*104; idx += 128) {
        int r = idx / 104, n = idx - r*104;
        Wsm[idx] = (n < NOUT) ? Wb[(size_t)(row0 + r)*NOUT + n] : 0.0f;
    }
    __syncthreads();

    for (int e = tid; e < 13*32; e += 128) {
        int nt = e >> 5, lane = e & 31;
        int g = lane >> 2, t = lane & 3;
        int n = nt*8 + g, k0 = 2*t;
        float w00 = Wsm[(k0    )*104 + n], w01 = Wsm[(k0 + 1)*104 + n];
        float w08 = Wsm[(k0 + 8)*104 + n], w09 = Wsm[(k0 + 9)*104 + n];
        unsigned hi0, lo0, hi1, lo1;
        split2(w00, w01, hi0, lo0);
        split2(w08, w09, hi1, lo1);
        *(uint4*)(g_Wp + ((size_t)(chunk*13 + nt)*32 + lane)*16) =
            make_uint4(hi0, hi1, lo0, lo1);
    }
}

// ============================================================================
// K1: entity embeddings = logsumexp over M mentions
// ============================================================================
__global__ void k_ent_emb(const float* __restrict__ seq,
                          const int*   __restrict__ mpos) {
    int be = blockIdx.x;
    int b  = be / EE;
    const int* mp = mpos + be*MM;
    int p0 = mp[0], p1 = mp[1], p2 = mp[2], p3 = mp[3];
    const float* sb = seq + (long)b*CC*DD;
    for (int dd = threadIdx.x; dd < DD; dd += blockDim.x) {
        float v0 = sb[p0*DD+dd], v1 = sb[p1*DD+dd];
        float v2 = sb[p2*DD+dd], v3 = sb[p3*DD+dd];
        float mx = fmaxf(fmaxf(v0, v1), fmaxf(v2, v3));
        float s  = expf(v0-mx) + expf(v1-mx) + expf(v2-mx) + expf(v3-mx);
        g_ent_emb[be*DD + dd] = mx + logf(s);
    }
}

// ============================================================================
// K2: entity attention = mean over M mention attention rows
// ============================================================================
__global__ void k_ent_att(const float* __restrict__ att,
                          const int*   __restrict__ mpos) {
    int id = blockIdx.x;
    int hd = id % HH;
    int be = id / HH;
    int b  = be / EE;
    const int* mp = mpos + be*MM;
    const float* ab = att + (long)(b*HH + hd)*CC*CC;
    float* ob = g_ent_att + (long)id*CC;
    int q0 = mp[0]*CC, q1 = mp[1]*CC, q2 = mp[2]*CC, q3 = mp[3]*CC;
    for (int c = threadIdx.x; c < CC; c += blockDim.x) {
        float s = ab[q0+c] + ab[q1+c] + ab[q2+c] + ab[q3+c];
        ob[c] = s * 0.25f;
    }
}

// ============================================================================
// K3: ht_att = mean_h(h_att * t_att), row-normalized
// ============================================================================
__global__ void k_ht_att(const int* __restrict__ hts) {
    int bp = blockIdx.x;
    int b  = bp / PP;
    int eh = hts[bp*2 + 0];
    int et = hts[bp*2 + 1];
    const float* ah = g_ent_att + (long)(b*EE + eh)*HH*CC;
    const float* at = g_ent_att + (long)(b*EE + et)*HH*CC;

    float v[4];
    float lsum = 0.f;
    #pragma unroll
    for (int q = 0; q < 4; q++) {
        int c = q*256 + threadIdx.x;
        float s = 0.f;
        #pragma unroll
        for (int hd = 0; hd < HH; hd++)
            s += ah[hd*CC + c] * at[hd*CC + c];
        s *= (1.0f / HH);
        v[q] = s;
        lsum += s;
    }
    __shared__ float red[256];
    red[threadIdx.x] = lsum;
    __syncthreads();
    for (int st = 128; st > 0; st >>= 1) {
        if (threadIdx.x < st) red[threadIdx.x] += red[threadIdx.x + st];
        __syncthreads();
    }
    float inv = 1.0f / (red[0] + 1e-30f);
    #pragma unroll
    for (int q = 0; q < 4; q++) {
        int c = q*256 + threadIdx.x;
        g_ht_att[(long)bp*CC + c] = v[q] * inv;
    }
}

// ============================================================================
// K4: rs = ht_att @ seq (unchanged scalar FFMA2 version)
// ============================================================================
__global__ void __launch_bounds__(128, 8) k_rs(const float* __restrict__ seq) {
    int d0 = blockIdx.x * 64;
    int r0 = blockIdx.y * 32;
    int b  = r0 >> 8;
    const float* Bm = seq + (long)b*CC*DD;

    __shared__ __align__(16) float As[2][16][36];
    __shared__ __align__(16) float Bs[2][16][64];

    int tid = threadIdx.x;
    int cA = tid & 15, rA = tid >> 4;
    int xB = tid & 63, kB = tid >> 6;
    int tx = tid & 15, ty = tid >> 4;

    float ra[4], rb[8];
    unsigned long long acc[4][2];
    #pragma unroll
    for (int i = 0; i < 4; i++) { acc[i][0] = 0ull; acc[i][1] = 0ull; }

    #pragma unroll
    for (int l = 0; l < 4; l++) ra[l] = g_ht_att[(long)(r0 + rA + 8*l)*CC + cA];
    #pragma unroll
    for (int l = 0; l < 8; l++) rb[l] = Bm[(long)(kB + 2*l)*DD + d0 + xB];
    #pragma unroll
    for (int l = 0; l < 4; l++) As[0][cA][rA + 8*l] = ra[l];
    #pragma unroll
    for (int l = 0; l < 8; l++) Bs[0][kB + 2*l][xB] = rb[l];
    __syncthreads();

    const int NK = CC/16;
    for (int t = 0; t < NK; t++) {
        int buf = t & 1;
        if (t + 1 < NK) {
            int kc = (t + 1)*16;
            #pragma unroll
            for (int l = 0; l < 4; l++) ra[l] = g_ht_att[(long)(r0 + rA + 8*l)*CC + kc + cA];
            #pragma unroll
            for (int l = 0; l < 8; l++) rb[l] = Bm[(long)(kc + kB + 2*l)*DD + d0 + xB];
        }
        #pragma unroll
        for (int kk = 0; kk < 16; kk++) {
            float4 a4 = *(const float4*)&As[buf][kk][ty*4];
            ulonglong2 bw = *(const ulonglong2*)&Bs[buf][kk][tx*4];
            const float* af = (const float*)&a4;
            #pragma unroll
            for (int ri = 0; ri < 4; ri++) {
                unsigned long long ad = dup_f32x2(af[ri]);
                acc[ri][0] = fma_f32x2(ad, bw.x, acc[ri][0]);
                acc[ri][1] = fma_f32x2(ad, bw.y, acc[ri][1]);
            }
        }
        if (t + 1 < NK) {
            #pragma unroll
            for (int l = 0; l < 4; l++) As[buf^1][cA][rA + 8*l] = ra[l];
            #pragma unroll
            for (int l = 0; l < 8; l++) Bs[buf^1][kB + 2*l][xB] = rb[l];
        }
        __syncthreads();
    }
    #pragma unroll
    for (int ri = 0; ri < 4; ri++) {
        long row = (long)(r0 + ty*4 + ri);
        float* op = g_rs + row*DD + d0 + tx*4;
        float2 u = unpack_f32x2(acc[ri][0]);
        float2 v = unpack_f32x2(acc[ri][1]);
        op[0] = u.x; op[1] = u.y; op[2] = v.x; op[3] = v.y;
    }
}

// ============================================================================
// K5: hs2/ts2 = tanh(concat(ent_emb[ent], rs) @ W + b) (unchanged)
// ============================================================================
__global__ void __launch_bounds__(128, 8) k_ht_gemm(const float* __restrict__ Wh,
                                                    const float* __restrict__ bh,
                                                    const float* __restrict__ Wt,
                                                    const float* __restrict__ bt,
                                                    const int* __restrict__ hts) {
    int d0  = blockIdx.x * 64;
    int r0  = blockIdx.y * 32;
    int col = blockIdx.z;
    const float* W    = col ? Wt : Wh;
    const float* bias = col ? bt : bh;
    float* out        = col ? g_ts2 : g_hs2;

    __shared__ __align__(16) float As[2][16][36];
    __shared__ __align__(16) float Bs[2][16][64];
    __shared__ int aOff[32];

    int tid = threadIdx.x;
    if (tid < 32) {
        int r = r0 + tid;
        aOff[tid] = ((r >> 8)*EE + hts[r*2 + col])*DD;
    }
    __syncthreads();

    int cA = tid & 15, rA = tid >> 4;
    int xB = tid & 63, kB = tid >> 6;
    int tx = tid & 15, ty = tid >> 4;

    float ra[4], rb[8];
    unsigned long long acc[4][2];
    #pragma unroll
    for (int i = 0; i < 4; i++) { acc[i][0] = 0ull; acc[i][1] = 0ull; }

    #pragma unroll
    for (int l = 0; l < 4; l++) ra[l] = g_ent_emb[aOff[rA + 8*l] + cA];
    #pragma unroll
    for (int l = 0; l < 8; l++) rb[l] = W[(long)(kB + 2*l)*DD + d0 + xB];
    #pragma unroll
    for (int l = 0; l < 4; l++) As[0][cA][rA + 8*l] = ra[l];
    #pragma unroll
    for (int l = 0; l < 8; l++) Bs[0][kB + 2*l][xB] = rb[l];
    __syncthreads();

    const int NK = (2*DD)/16;
    for (int t = 0; t < NK; t++) {
        int buf = t & 1;
        if (t + 1 < NK) {
            int kc = (t + 1)*16;
            if (kc < DD) {
                #pragma unroll
                for (int l = 0; l < 4; l++) ra[l] = g_ent_emb[aOff[rA + 8*l] + kc + cA];
            } else {
                #pragma unroll
                for (int l = 0; l < 4; l++) ra[l] = g_rs[(long)(r0 + rA + 8*l)*DD + kc - DD + cA];
            }
            #pragma unroll
            for (int l = 0; l < 8; l++) rb[l] = W[(long)(kc + kB + 2*l)*DD + d0 + xB];
        }
        #pragma unroll
        for (int kk = 0; kk < 16; kk++) {
            float4 a4 = *(const float4*)&As[buf][kk][ty*4];
            ulonglong2 bw = *(const ulonglong2*)&Bs[buf][kk][tx*4];
            const float* af = (const float*)&a4;
            #pragma unroll
            for (int ri = 0; ri < 4; ri++) {
                unsigned long long ad = dup_f32x2(af[ri]);
                acc[ri][0] = fma_f32x2(ad, bw.x, acc[ri][0]);
                acc[ri][1] = fma_f32x2(ad, bw.y, acc[ri][1]);
            }
        }
        if (t + 1 < NK) {
            #pragma unroll
            for (int l = 0; l < 4; l++) As[buf^1][cA][rA + 8*l] = ra[l];
            #pragma unroll
            for (int l = 0; l < 8; l++) Bs[buf^1][kB + 2*l][xB] = rb[l];
        }
        __syncthreads();
    }
    #pragma unroll
    for (int ri = 0; ri < 4; ri++) {
        long row = (long)(r0 + ty*4 + ri);
        float* op = out + row*DD + d0 + tx*4;
        float2 u = unpack_f32x2(acc[ri][0]);
        float2 v = unpack_f32x2(acc[ri][1]);
        op[0] = tanhf(u.x + bias[d0 + tx*4 + 0]);
        op[1] = tanhf(u.y + bias[d0 + tx*4 + 1]);
        op[2] = tanhf(v.x + bias[d0 + tx*4 + 2]);
        op[3] = tanhf(v.y + bias[d0 + tx*4 + 3]);
    }
}

// ============================================================================
// K6: init output with bias
// ============================================================================
__global__ void k_init_out(const float* __restrict__ b_bil, float* __restrict__ out) {
    int i = blockIdx.x*256 + threadIdx.x;
    if (i < RR*NOUT) out[i] = b_bil[i % NOUT];
}

// ============================================================================
// K7: bilinear via warp mma.sync (split-bf16, 3-term).
// grid (48, 8): x = kb*4 + quarter (1024 kij rows = 64 chunks each), y = 128-row
// tile. 128 threads = 4 warps; each warp owns 32 rows (2 m16 A-fragments),
// generates A = hs*ts on the fly into fragment regs, W streamed via smem.
// ============================================================================
// dyn smem layout: tsS f32[128][66] @0 (33792B), hsS f32[128][17] @33792 (8704B),
//                  Wbuf 2 x 6656B @42496  -> total 55808B
#define TS_OFF  0
#define HS_OFF  33792
#define WB_OFF  42496
#define BIL_SMEM 55808
#define CHUNK_BYTES 6656   // 13 ntiles * 32 lanes * 16B

__global__ void __launch_bounds__(128) k_bil_mma(float* __restrict__ out) {
    extern __shared__ __align__(16) char smem[];
    float* tsS = (float*)(smem + TS_OFF);
    float* hsS = (float*)(smem + HS_OFF);
    char*  Wbuf = smem + WB_OFF;

    const int kb = blockIdx.x >> 2;
    const int qt = blockIdx.x & 3;
    const int r0 = blockIdx.y * 128;
    const int tid  = threadIdx.x;
    const int wid  = tid >> 5;
    const int lane = tid & 31;
    const int g = lane >> 2, t = lane & 3;

    // stage ts [128 r][64 j] and hs [128 r][16 i] (this quarter's i-range)
    for (int idx = tid; idx < 128*64; idx += 128) {
        int r = idx >> 6, j = idx & 63;
        tsS[r*66 + j] = g_ts2[(size_t)(r0 + r)*DD + kb*64 + j];
    }
    for (int idx = tid; idx < 128*16; idx += 128) {
        int r = idx >> 4, ii = idx & 15;
        hsS[r*17 + ii] = g_hs2[(size_t)(r0 + r)*DD + kb*64 + qt*16 + ii];
    }
    // stage W chunk 0
    const size_t chunk0 = (size_t)(kb*256 + qt*64);
    {
        const char* src = (const char*)g_Wp + chunk0*CHUNK_BYTES;
        for (int e = tid; e < 416; e += 128)
            *(uint4*)(Wbuf + e*16) = *(const uint4*)(src + e*16);
    }
    __syncthreads();

    float acc[2][13][4];
    #pragma unroll
    for (int a = 0; a < 2; a++)
        #pragma unroll
        for (int n = 0; n < 13; n++)
            #pragma unroll
            for (int c = 0; c < 4; c++) acc[a][n][c] = 0.0f;

    for (int cc = 0; cc < 64; cc++) {
        int s = cc & 1;
        // prefetch next W chunk into regs
        uint4 pw0, pw1, pw2, pw3;
        if (cc + 1 < 64) {
            const char* src = (const char*)g_Wp + (chunk0 + cc + 1)*CHUNK_BYTES;
            pw0 = *(const uint4*)(src + (tid      )*16);
            pw1 = *(const uint4*)(src + (tid + 128)*16);
            pw2 = *(const uint4*)(src + (tid + 256)*16);
            if (tid < 32) pw3 = *(const uint4*)(src + (tid + 384)*16);
        }

        // generate A fragments for this chunk: i_loc = cc>>2, j0 = (cc&3)*16
        int i_loc = cc >> 2;
        int j0    = (cc & 3) * 16;
        unsigned ahi[2][4], alo[2][4];
        #pragma unroll
        for (int af = 0; af < 2; af++) {
            int ra = wid*32 + af*16 + g;
            int rb = ra + 8;
            float hA = hsS[ra*17 + i_loc];
            float hB = hsS[rb*17 + i_loc];
            float2 tA0 = *(const float2*)&tsS[ra*66 + j0 + 2*t];
            float2 tA1 = *(const float2*)&tsS[ra*66 + j0 + 2*t + 8];
            float2 tB0 = *(const float2*)&tsS[rb*66 + j0 + 2*t];
            float2 tB1 = *(const float2*)&tsS[rb*66 + j0 + 2*t + 8];
            split2(hA*tA0.x, hA*tA0.y, ahi[af][0], alo[af][0]);
            split2(hB*tB0.x, hB*tB0.y, ahi[af][1], alo[af][1]);
            split2(hA*tA1.x, hA*tA1.y, ahi[af][2], alo[af][2]);
            split2(hB*tB1.x, hB*tB1.y, ahi[af][3], alo[af][3]);
        }

        // MMAs against staged W
        #pragma unroll
        for (int nt = 0; nt < 13; nt++) {
            uint4 w = *(const uint4*)(Wbuf + s*CHUNK_BYTES + (nt*32 + lane)*16);
            #pragma unroll
            for (int af = 0; af < 2; af++) {
                mma_bf16(acc[af][nt], ahi[af], w.x, w.y);   // Ahi * Whi
                mma_bf16(acc[af][nt], ahi[af], w.z, w.w);   // Ahi * Wlo
                mma_bf16(acc[af][nt], alo[af], w.x, w.y);   // Alo * Whi
            }
        }

        __syncthreads();
        if (cc + 1 < 64) {
            char* dst = Wbuf + (s^1)*CHUNK_BYTES;
            *(uint4*)(dst + (tid      )*16) = pw0;
            *(uint4*)(dst + (tid + 128)*16) = pw1;
            *(uint4*)(dst + (tid + 256)*16) = pw2;
            if (tid < 32) *(uint4*)(dst + (tid + 384)*16) = pw3;
        }
        __syncthreads();
    }

    // epilogue: atomics (48 slices fold per output element)
    #pragma unroll
    for (int af = 0; af < 2; af++) {
        int r1 = r0 + wid*32 + af*16 + g;
        #pragma unroll
        for (int nt = 0; nt < 13; nt++) {
            int n0 = nt*8 + 2*t;
            const float* a = acc[af][nt];
            if (n0 < NOUT) {
                atomicAdd(&out[(size_t)r1*NOUT + n0],       a[0]);
                atomicAdd(&out[(size_t)(r1+8)*NOUT + n0],   a[2]);
            }
            if (n0 + 1 < NOUT) {
                atomicAdd(&out[(size_t)r1*NOUT + n0 + 1],     a[1]);
                atomicAdd(&out[(size_t)(r1+8)*NOUT + n0 + 1], a[3]);
            }
        }
    }
}

// ============================================================================
// launch
// ============================================================================
extern "C" void kernel_launch(void* const* d_in, const int* in_sizes, int n_in,
                              void* d_out, int out_size) {
    const float* seq    = (const float*)d_in[0];
    const float* att    = (const float*)d_in[1];
    const int*   mpos   = (const int*  )d_in[2];
    const int*   hts    = (const int*  )d_in[3];
    const float* W_head = (const float*)d_in[4];
    const float* b_head = (const float*)d_in[5];
    const float* W_tail = (const float*)d_in[6];
    const float* b_tail = (const float*)d_in[7];
    const float* W_bil  = (const float*)d_in[8];
    const float* b_bil  = (const float*)d_in[9];
    float* out = (float*)d_out;

    cudaFuncSetAttribute(k_bil_mma, cudaFuncAttributeMaxDynamicSharedMemorySize, BIL_SMEM);

    k_wt<<<3072, 128>>>(W_bil);
    k_ent_emb<<<NN*EE, 256>>>(seq, mpos);
    k_ent_att<<<NN*EE*HH, 256>>>(att, mpos);
    k_ht_att<<<NN*PP, 256>>>(hts);
    k_rs<<<dim3(DD/64, RR/32), 128>>>(seq);
    k_ht_gemm<<<dim3(DD/64, RR/32, 2), 128>>>(W_head, b_head, W_tail, b_tail, hts);
    k_init_out<<<(RR*NOUT + 255)/256, 256>>>(b_bil, out);
    k_bil_mma<<<dim3(KBL*4, RR/128), 128, BIL_SMEM>>>(out);
}

// round 6
// speedup vs baseline: 2.6292x; 1.1661x over previous
#include <cuda_runtime.h>
#include <math.h>

// ---------------- fixed problem shapes ----------------
#define NN   4
#define CC   1024
#define DD   768
#define HH   12
#define EE   32
#define MM   4
#define PP   256
#define RR   (NN*PP)     // 1024
#define KBL  12
#define NOUT 97

// ---------------- scratch ----------------
__device__ float g_ent_emb[NN*EE*DD];
__device__ float g_ent_att[NN*EE*HH*CC];
__device__ float g_ht_att [NN*PP*CC];
__device__ float g_rs     [RR*DD];
__device__ float g_hs2    [RR*DD];
__device__ float g_ts2    [RR*DD];

// W_bil fragments: 3072 chunks x 13 nt x 32 lanes x uint4{hi0,hi1,lo0,lo1}
__device__ __align__(16) unsigned char g_Wp[3072UL*13*32*16];
// W_head/W_tail fragments: [2][96 kc][96 nt][32] uint4   (9.4 MB)
__device__ __align__(16) unsigned char g_Whtp[2UL*96*96*32*16];
// seq fragments: [4][64 kc][96 nt][32] uint4              (12.6 MB)
__device__ __align__(16) unsigned char g_seqf[4UL*64*96*32*16];

// ---------------- bf16 helpers ----------------
__device__ __forceinline__ unsigned pack_bf16x2(float hi_f, float lo_f) {
    unsigned r;
    asm("cvt.rn.bf16x2.f32 %0, %1, %2;" : "=r"(r) : "f"(hi_f), "f"(lo_f));
    return r;
}
// split (p0 lower, p1 upper) into bf16x2 hi + bf16x2 lo residual
__device__ __forceinline__ void split2(float p0, float p1, unsigned& hi, unsigned& lo) {
    hi = pack_bf16x2(p1, p0);
    float f0 = __uint_as_float(hi << 16);
    float f1 = __uint_as_float(hi & 0xffff0000u);
    lo = pack_bf16x2(p1 - f1, p0 - f0);
}
// warp mma: D += A(bf16) * B(bf16), m16n8k16, row.col, fp32 accum
__device__ __forceinline__ void mma_bf16(float* d, const unsigned* a,
                                         unsigned b0, unsigned b1) {
    asm volatile(
        "mma.sync.aligned.m16n8k16.row.col.f32.bf16.bf16.f32 "
        "{%0,%1,%2,%3}, {%4,%5,%6,%7}, {%8,%9}, {%0,%1,%2,%3};"
        : "+f"(d[0]), "+f"(d[1]), "+f"(d[2]), "+f"(d[3])
        : "r"(a[0]), "r"(a[1]), "r"(a[2]), "r"(a[3]), "r"(b0), "r"(b1));
}

// ============================================================================
// P0: pack W_bil into fragment layout. grid 3072, 128 thr
// ============================================================================
__global__ void k_wt(const float* __restrict__ Wb) {
    __shared__ float Wsm[16*104];
    int chunk = blockIdx.x;
    int tid = threadIdx.x;
    int row0 = chunk * 16;

    for (int idx = tid; idx < 16*104; idx += 128) {
        int r = idx / 104, n = idx - r*104;
        Wsm[idx] = (n < NOUT) ? Wb[(size_t)(row0 + r)*NOUT + n] : 0.0f;
    }
    __syncthreads();

    for (int e = tid; e < 13*32; e += 128) {
        int nt = e >> 5, lane = e & 31;
        int g = lane >> 2, t = lane & 3;
        int n = nt*8 + g, k0 = 2*t;
        unsigned hi0, lo0, hi1, lo1;
        split2(Wsm[(k0    )*104 + n], Wsm[(k0 + 1)*104 + n], hi0, lo0);
        split2(Wsm[(k0 + 8)*104 + n], Wsm[(k0 + 9)*104 + n], hi1, lo1);
        *(uint4*)(g_Wp + ((size_t)(chunk*13 + nt)*32 + lane)*16) =
            make_uint4(hi0, hi1, lo0, lo1);
    }
}

// ============================================================================
// P1: pack W_head / W_tail [1536][768] into fragments. grid (96, 2), 256 thr
// ============================================================================
__global__ void k_wht(const float* __restrict__ Wh, const float* __restrict__ Wt) {
    __shared__ float S[16*768];
    int kc = blockIdx.x;
    int w  = blockIdx.y;
    const float* W = w ? Wt : Wh;
    int tid = threadIdx.x;

    for (int idx = tid; idx < 16*768; idx += 256)
        S[idx] = W[(size_t)kc*16*768 + idx];
    __syncthreads();

    for (int e = tid; e < 96*32; e += 256) {
        int nt = e >> 5, lane = e & 31;
        int g = lane >> 2, t = lane & 3;
        int n = nt*8 + g, k0 = 2*t;
        unsigned hi0, lo0, hi1, lo1;
        split2(S[(k0    )*768 + n], S[(k0 + 1)*768 + n], hi0, lo0);
        split2(S[(k0 + 8)*768 + n], S[(k0 + 9)*768 + n], hi1, lo1);
        *(uint4*)(g_Whtp + ((((size_t)w*96 + kc)*96 + nt)*32 + lane)*16) =
            make_uint4(hi0, hi1, lo0, lo1);
    }
}

// ============================================================================
// P2: pack seq [4][1024][768] into fragments (k=c, n=d). grid (64, 4), 256 thr
// ============================================================================
__global__ void k_seqf(const float* __restrict__ seq) {
    __shared__ float S[16*768];
    int kc = blockIdx.x;
    int b  = blockIdx.y;
    int tid = threadIdx.x;

    for (int idx = tid; idx < 16*768; idx += 256)
        S[idx] = seq[((size_t)b*CC + kc*16)*768 + idx];
    __syncthreads();

    for (int e = tid; e < 96*32; e += 256) {
        int nt = e >> 5, lane = e & 31;
        int g = lane >> 2, t = lane & 3;
        int n = nt*8 + g, k0 = 2*t;
        unsigned hi0, lo0, hi1, lo1;
        split2(S[(k0    )*768 + n], S[(k0 + 1)*768 + n], hi0, lo0);
        split2(S[(k0 + 8)*768 + n], S[(k0 + 9)*768 + n], hi1, lo1);
        *(uint4*)(g_seqf + ((((size_t)b*64 + kc)*96 + nt)*32 + lane)*16) =
            make_uint4(hi0, hi1, lo0, lo1);
    }
}

// ============================================================================
// K1: entity embeddings = logsumexp over M mentions
// ============================================================================
__global__ void k_ent_emb(const float* __restrict__ seq,
                          const int*   __restrict__ mpos) {
    int be = blockIdx.x;
    int b  = be / EE;
    const int* mp = mpos + be*MM;
    int p0 = mp[0], p1 = mp[1], p2 = mp[2], p3 = mp[3];
    const float* sb = seq + (long)b*CC*DD;
    for (int dd = threadIdx.x; dd < DD; dd += blockDim.x) {
        float v0 = sb[p0*DD+dd], v1 = sb[p1*DD+dd];
        float v2 = sb[p2*DD+dd], v3 = sb[p3*DD+dd];
        float mx = fmaxf(fmaxf(v0, v1), fmaxf(v2, v3));
        float s  = expf(v0-mx) + expf(v1-mx) + expf(v2-mx) + expf(v3-mx);
        g_ent_emb[be*DD + dd] = mx + logf(s);
    }
}

// ============================================================================
// K2: entity attention = mean over M mention attention rows
// ============================================================================
__global__ void k_ent_att(const float* __restrict__ att,
                          const int*   __restrict__ mpos) {
    int id = blockIdx.x;
    int hd = id % HH;
    int be = id / HH;
    int b  = be / EE;
    const int* mp = mpos + be*MM;
    const float* ab = att + (long)(b*HH + hd)*CC*CC;
    float* ob = g_ent_att + (long)id*CC;
    int q0 = mp[0]*CC, q1 = mp[1]*CC, q2 = mp[2]*CC, q3 = mp[3]*CC;
    for (int c = threadIdx.x; c < CC; c += blockDim.x) {
        float s = ab[q0+c] + ab[q1+c] + ab[q2+c] + ab[q3+c];
        ob[c] = s * 0.25f;
    }
}

// ============================================================================
// K3: ht_att = mean_h(h_att * t_att), row-normalized
// ============================================================================
__global__ void k_ht_att(const int* __restrict__ hts) {
    int bp = blockIdx.x;
    int b  = bp / PP;
    int eh = hts[bp*2 + 0];
    int et = hts[bp*2 + 1];
    const float* ah = g_ent_att + (long)(b*EE + eh)*HH*CC;
    const float* at = g_ent_att + (long)(b*EE + et)*HH*CC;

    float v[4];
    float lsum = 0.f;
    #pragma unroll
    for (int q = 0; q < 4; q++) {
        int c = q*256 + threadIdx.x;
        float s = 0.f;
        #pragma unroll
        for (int hd = 0; hd < HH; hd++)
            s += ah[hd*CC + c] * at[hd*CC + c];
        s *= (1.0f / HH);
        v[q] = s;
        lsum += s;
    }
    __shared__ float red[256];
    red[threadIdx.x] = lsum;
    __syncthreads();
    for (int st = 128; st > 0; st >>= 1) {
        if (threadIdx.x < st) red[threadIdx.x] += red[threadIdx.x + st];
        __syncthreads();
    }
    float inv = 1.0f / (red[0] + 1e-30f);
    #pragma unroll
    for (int q = 0; q < 4; q++) {
        int c = q*256 + threadIdx.x;
        g_ht_att[(long)bp*CC + c] = v[q] * inv;
    }
}

// ============================================================================
// K4: rs = ht_att @ seq via mma.sync split-bf16. grid (12, 8), 128 thr.
// CTA: 128 rows x 64 cols, K=1024 (64 ksteps of 16).
// ============================================================================
#define APITCH 20
__global__ void __launch_bounds__(128) k_rs_mma() {
    __shared__ __align__(16) float As[2][128*APITCH];
    __shared__ __align__(16) unsigned char Bb[2][4096];

    int nt0 = blockIdx.x * 8;
    int r0  = blockIdx.y * 128;
    int b   = r0 >> 8;
    int tid = threadIdx.x, wid = tid >> 5, lane = tid & 31;
    int g = lane >> 2, t = lane & 3;

    const float* Arow = g_ht_att + (size_t)(r0 + tid)*CC;
    const char*  Bbase = (const char*)g_seqf + (((size_t)b*64)*96 + nt0)*32*16;
    const size_t kcs = (size_t)96*32*16;

    float4 pa[4]; uint4 pb0, pb1;
    #pragma unroll
    for (int q = 0; q < 4; q++) pa[q] = *(const float4*)(Arow + q*4);
    pb0 = *(const uint4*)(Bbase + tid*16);
    pb1 = *(const uint4*)(Bbase + (tid + 128)*16);
    #pragma unroll
    for (int q = 0; q < 4; q++) *(float4*)&As[0][tid*APITCH + q*4] = pa[q];
    *(uint4*)&Bb[0][tid*16] = pb0;
    *(uint4*)&Bb[0][(tid + 128)*16] = pb1;
    __syncthreads();

    float acc[2][8][4];
    #pragma unroll
    for (int a = 0; a < 2; a++)
        #pragma unroll
        for (int n = 0; n < 8; n++)
            #pragma unroll
            for (int c = 0; c < 4; c++) acc[a][n][c] = 0.0f;

    for (int ks = 0; ks < 64; ks++) {
        int s = ks & 1;
        if (ks + 1 < 64) {
            #pragma unroll
            for (int q = 0; q < 4; q++) pa[q] = *(const float4*)(Arow + (ks+1)*16 + q*4);
            const char* bsrc = Bbase + (size_t)(ks+1)*kcs;
            pb0 = *(const uint4*)(bsrc + tid*16);
            pb1 = *(const uint4*)(bsrc + (tid + 128)*16);
        }

        unsigned ahi[2][4], alo[2][4];
        #pragma unroll
        for (int af = 0; af < 2; af++) {
            int ra = wid*32 + af*16 + g;
            int rb = ra + 8;
            float2 a0 = *(const float2*)&As[s][ra*APITCH + 2*t];
            float2 a1 = *(const float2*)&As[s][rb*APITCH + 2*t];
            float2 a2 = *(const float2*)&As[s][ra*APITCH + 2*t + 8];
            float2 a3 = *(const float2*)&As[s][rb*APITCH + 2*t + 8];
            split2(a0.x, a0.y, ahi[af][0], alo[af][0]);
            split2(a1.x, a1.y, ahi[af][1], alo[af][1]);
            split2(a2.x, a2.y, ahi[af][2], alo[af][2]);
            split2(a3.x, a3.y, ahi[af][3], alo[af][3]);
        }

        #pragma unroll
        for (int nt = 0; nt < 8; nt++) {
            uint4 w = *(const uint4*)&Bb[s][(nt*32 + lane)*16];
            #pragma unroll
            for (int af = 0; af < 2; af++) {
                mma_bf16(acc[af][nt], ahi[af], w.x, w.y);
                mma_bf16(acc[af][nt], ahi[af], w.z, w.w);
                mma_bf16(acc[af][nt], alo[af], w.x, w.y);
            }
        }

        __syncthreads();
        if (ks + 1 < 64) {
            #pragma unroll
            for (int q = 0; q < 4; q++) *(float4*)&As[s^1][tid*APITCH + q*4] = pa[q];
            *(uint4*)&Bb[s^1][tid*16] = pb0;
            *(uint4*)&Bb[s^1][(tid + 128)*16] = pb1;
        }
        __syncthreads();
    }

    #pragma unroll
    for (int af = 0; af < 2; af++) {
        int ra = r0 + wid*32 + af*16 + g;
        #pragma unroll
        for (int nt = 0; nt < 8; nt++) {
            int n0 = (nt0 + nt)*8 + 2*t;
            *(float2*)(g_rs + (size_t)ra*DD + n0)     = make_float2(acc[af][nt][0], acc[af][nt][1]);
            *(float2*)(g_rs + (size_t)(ra+8)*DD + n0) = make_float2(acc[af][nt][2], acc[af][nt][3]);
        }
    }
}

// ============================================================================
// K5: hs2/ts2 = tanh(concat(ent_emb[ent], rs) @ W + b) via mma.sync.
// grid (12, 8, 2), 128 thr. K=1536 (96 ksteps).
// ============================================================================
__global__ void __launch_bounds__(128) k_ht_mma(const float* __restrict__ bh,
                                                const float* __restrict__ bt,
                                                const int* __restrict__ hts) {
    __shared__ __align__(16) float As[2][128*APITCH];
    __shared__ __align__(16) unsigned char Bb[2][4096];

    int nt0 = blockIdx.x * 8;
    int r0  = blockIdx.y * 128;
    int col = blockIdx.z;
    const float* bias = col ? bt : bh;
    float* outm = col ? g_ts2 : g_hs2;

    int tid = threadIdx.x, wid = tid >> 5, lane = tid & 31;
    int g = lane >> 2, t = lane & 3;

    int r = r0 + tid;
    const float* eRow = g_ent_emb + ((size_t)(r >> 8)*EE + hts[r*2 + col])*DD;
    const float* rRow = g_rs + (size_t)r*DD;
    const char*  Bbase = (const char*)g_Whtp + (((size_t)col*96)*96 + nt0)*32*16;
    const size_t kcs = (size_t)96*32*16;

    float4 pa[4]; uint4 pb0, pb1;
    #pragma unroll
    for (int q = 0; q < 4; q++) pa[q] = *(const float4*)(eRow + q*4);
    pb0 = *(const uint4*)(Bbase + tid*16);
    pb1 = *(const uint4*)(Bbase + (tid + 128)*16);
    #pragma unroll
    for (int q = 0; q < 4; q++) *(float4*)&As[0][tid*APITCH + q*4] = pa[q];
    *(uint4*)&Bb[0][tid*16] = pb0;
    *(uint4*)&Bb[0][(tid + 128)*16] = pb1;
    __syncthreads();

    float acc[2][8][4];
    #pragma unroll
    for (int a = 0; a < 2; a++)
        #pragma unroll
        for (int n = 0; n < 8; n++)
            #pragma unroll
            for (int c = 0; c < 4; c++) acc[a][n][c] = 0.0f;

    const int NK = 96;
    for (int ks = 0; ks < NK; ks++) {
        int s = ks & 1;
        if (ks + 1 < NK) {
            int kc = (ks + 1)*16;
            const float* src = (kc < DD) ? (eRow + kc) : (rRow + kc - DD);
            #pragma unroll
            for (int q = 0; q < 4; q++) pa[q] = *(const float4*)(src + q*4);
            const char* bsrc = Bbase + (size_t)(ks+1)*kcs;
            pb0 = *(const uint4*)(bsrc + tid*16);
            pb1 = *(const uint4*)(bsrc + (tid + 128)*16);
        }

        unsigned ahi[2][4], alo[2][4];
        #pragma unroll
        for (int af = 0; af < 2; af++) {
            int ra = wid*32 + af*16 + g;
            int rb = ra + 8;
            float2 a0 = *(const float2*)&As[s][ra*APITCH + 2*t];
            float2 a1 = *(const float2*)&As[s][rb*APITCH + 2*t];
            float2 a2 = *(const float2*)&As[s][ra*APITCH + 2*t + 8];
            float2 a3 = *(const float2*)&As[s][rb*APITCH + 2*t + 8];
            split2(a0.x, a0.y, ahi[af][0], alo[af][0]);
            split2(a1.x, a1.y, ahi[af][1], alo[af][1]);
            split2(a2.x, a2.y, ahi[af][2], alo[af][2]);
            split2(a3.x, a3.y, ahi[af][3], alo[af][3]);
        }

        #pragma unroll
        for (int nt = 0; nt < 8; nt++) {
            uint4 w = *(const uint4*)&Bb[s][(nt*32 + lane)*16];
            #pragma unroll
            for (int af = 0; af < 2; af++) {
                mma_bf16(acc[af][nt], ahi[af], w.x, w.y);
                mma_bf16(acc[af][nt], ahi[af], w.z, w.w);
                mma_bf16(acc[af][nt], alo[af], w.x, w.y);
            }
        }

        __syncthreads();
        if (ks + 1 < NK) {
            #pragma unroll
            for (int q = 0; q < 4; q++) *(float4*)&As[s^1][tid*APITCH + q*4] = pa[q];
            *(uint4*)&Bb[s^1][tid*16] = pb0;
            *(uint4*)&Bb[s^1][(tid + 128)*16] = pb1;
        }
        __syncthreads();
    }

    #pragma unroll
    for (int af = 0; af < 2; af++) {
        int ra = r0 + wid*32 + af*16 + g;
        #pragma unroll
        for (int nt = 0; nt < 8; nt++) {
            int n0 = (nt0 + nt)*8 + 2*t;
            float b0v = bias[n0], b1v = bias[n0 + 1];
            *(float2*)(outm + (size_t)ra*DD + n0) =
                make_float2(tanhf(acc[af][nt][0] + b0v), tanhf(acc[af][nt][1] + b1v));
            *(float2*)(outm + (size_t)(ra+8)*DD + n0) =
                make_float2(tanhf(acc[af][nt][2] + b0v), tanhf(acc[af][nt][3] + b1v));
        }
    }
}

// ============================================================================
// K6: init output with bias
// ============================================================================
__global__ void k_init_out(const float* __restrict__ b_bil, float* __restrict__ out) {
    int i = blockIdx.x*256 + threadIdx.x;
    if (i < RR*NOUT) out[i] = b_bil[i % NOUT];
}

// ============================================================================
// K7: bilinear via warp mma.sync (unchanged from R5 pass)
// ============================================================================
#define TS_OFF  0
#define HS_OFF  33792
#define WB_OFF  42496
#define BIL_SMEM 55808
#define CHUNK_BYTES 6656   // 13 ntiles * 32 lanes * 16B

__global__ void __launch_bounds__(128) k_bil_mma(float* __restrict__ out) {
    extern __shared__ __align__(16) char smem[];
    float* tsS = (float*)(smem + TS_OFF);
    float* hsS = (float*)(smem + HS_OFF);
    char*  Wbuf = smem + WB_OFF;

    const int kb = blockIdx.x >> 2;
    const int qt = blockIdx.x & 3;
    const int r0 = blockIdx.y * 128;
    const int tid  = threadIdx.x;
    const int wid  = tid >> 5;
    const int lane = tid & 31;
    const int g = lane >> 2, t = lane & 3;

    for (int idx = tid; idx < 128*64; idx += 128) {
        int rr = idx >> 6, j = idx & 63;
        tsS[rr*66 + j] = g_ts2[(size_t)(r0 + rr)*DD + kb*64 + j];
    }
    for (int idx = tid; idx < 128*16; idx += 128) {
        int rr = idx >> 4, ii = idx & 15;
        hsS[rr*17 + ii] = g_hs2[(size_t)(r0 + rr)*DD + kb*64 + qt*16 + ii];
    }
    const size_t chunk0 = (size_t)(kb*256 + qt*64);
    {
        const char* src = (const char*)g_Wp + chunk0*CHUNK_BYTES;
        for (int e = tid; e < 416; e += 128)
            *(uint4*)(Wbuf + e*16) = *(const uint4*)(src + e*16);
    }
    __syncthreads();

    float acc[2][13][4];
    #pragma unroll
    for (int a = 0; a < 2; a++)
        #pragma unroll
        for (int n = 0; n < 13; n++)
            #pragma unroll
            for (int c = 0; c < 4; c++) acc[a][n][c] = 0.0f;

    for (int cc = 0; cc < 64; cc++) {
        int s = cc & 1;
        uint4 pw0, pw1, pw2, pw3;
        if (cc + 1 < 64) {
            const char* src = (const char*)g_Wp + (chunk0 + cc + 1)*CHUNK_BYTES;
            pw0 = *(const uint4*)(src + (tid      )*16);
            pw1 = *(const uint4*)(src + (tid + 128)*16);
            pw2 = *(const uint4*)(src + (tid + 256)*16);
            if (tid < 32) pw3 = *(const uint4*)(src + (tid + 384)*16);
        }

        int i_loc = cc >> 2;
        int j0    = (cc & 3) * 16;
        unsigned ahi[2][4], alo[2][4];
        #pragma unroll
        for (int af = 0; af < 2; af++) {
            int ra = wid*32 + af*16 + g;
            int rb = ra + 8;
            float hA = hsS[ra*17 + i_loc];
            float hB = hsS[rb*17 + i_loc];
            float2 tA0 = *(const float2*)&tsS[ra*66 + j0 + 2*t];
            float2 tA1 = *(const float2*)&tsS[ra*66 + j0 + 2*t + 8];
            float2 tB0 = *(const float2*)&tsS[rb*66 + j0 + 2*t];
            float2 tB1 = *(const float2*)&tsS[rb*66 + j0 + 2*t + 8];
            split2(hA*tA0.x, hA*tA0.y, ahi[af][0], alo[af][0]);
            split2(hB*tB0.x, hB*tB0.y, ahi[af][1], alo[af][1]);
            split2(hA*tA1.x, hA*tA1.y, ahi[af][2], alo[af][2]);
            split2(hB*tB1.x, hB*tB1.y, ahi[af][3], alo[af][3]);
        }

        #pragma unroll
        for (int nt = 0; nt < 13; nt++) {
            uint4 w = *(const uint4*)(Wbuf + s*CHUNK_BYTES + (nt*32 + lane)*16);
            #pragma unroll
            for (int af = 0; af < 2; af++) {
                mma_bf16(acc[af][nt], ahi[af], w.x, w.y);
                mma_bf16(acc[af][nt], ahi[af], w.z, w.w);
                mma_bf16(acc[af][nt], alo[af], w.x, w.y);
            }
        }

        __syncthreads();
        if (cc + 1 < 64) {
            char* dst = Wbuf + (s^1)*CHUNK_BYTES;
            *(uint4*)(dst + (tid      )*16) = pw0;
            *(uint4*)(dst + (tid + 128)*16) = pw1;
            *(uint4*)(dst + (tid + 256)*16) = pw2;
            if (tid < 32) *(uint4*)(dst + (tid + 384)*16) = pw3;
        }
        __syncthreads();
    }

    #pragma unroll
    for (int af = 0; af < 2; af++) {
        int r1 = r0 + wid*32 + af*16 + g;
        #pragma unroll
        for (int nt = 0; nt < 13; nt++) {
            int n0 = nt*8 + 2*t;
            const float* a = acc[af][nt];
            if (n0 < NOUT) {
                atomicAdd(&out[(size_t)r1*NOUT + n0],       a[0]);
                atomicAdd(&out[(size_t)(r1+8)*NOUT + n0],   a[2]);
            }
            if (n0 + 1 < NOUT) {
                atomicAdd(&out[(size_t)r1*NOUT + n0 + 1],     a[1]);
                atomicAdd(&out[(size_t)(r1+8)*NOUT + n0 + 1], a[3]);
            }
        }
    }
}

// ============================================================================
// launch
// ============================================================================
extern "C" void kernel_launch(void* const* d_in, const int* in_sizes, int n_in,
                              void* d_out, int out_size) {
    const float* seq    = (const float*)d_in[0];
    const float* att    = (const float*)d_in[1];
    const int*   mpos   = (const int*  )d_in[2];
    const int*   hts    = (const int*  )d_in[3];
    const float* W_head = (const float*)d_in[4];
    const float* b_head = (const float*)d_in[5];
    const float* W_tail = (const float*)d_in[6];
    const float* b_tail = (const float*)d_in[7];
    const float* W_bil  = (const float*)d_in[8];
    const float* b_bil  = (const float*)d_in[9];
    float* out = (float*)d_out;

    cudaFuncSetAttribute(k_bil_mma, cudaFuncAttributeMaxDynamicSharedMemorySize, BIL_SMEM);

    k_wt<<<3072, 128>>>(W_bil);
    k_wht<<<dim3(96, 2), 256>>>(W_head, W_tail);
    k_seqf<<<dim3(64, 4), 256>>>(seq);
    k_ent_emb<<<NN*EE, 256>>>(seq, mpos);
    k_ent_att<<<NN*EE*HH, 256>>>(att, mpos);
    k_ht_att<<<NN*PP, 256>>>(hts);
    k_rs_mma<<<dim3(12, 8), 128>>>();
    k_ht_mma<<<dim3(12, 8, 2), 128>>>(b_head, b_tail, hts);
    k_init_out<<<(RR*NOUT + 255)/256, 256>>>(b_bil, out);
    k_bil_mma<<<dim3(KBL*4, RR/128), 128, BIL_SMEM>>>(out);
}

// round 7
// speedup vs baseline: 2.6638x; 1.0132x over previous
#include <cuda_runtime.h>
#include <math.h>

// ---------------- fixed problem shapes ----------------
#define NN   4
#define CC   1024
#define DD   768
#define HH   12
#define EE   32
#define MM   4
#define PP   256
#define RR   (NN*PP)     // 1024
#define KBL  12
#define NOUT 97

// ---------------- scratch ----------------
__device__ float g_ent_emb[NN*EE*DD];
__device__ float g_ent_att[NN*EE*HH*CC];
__device__ float g_ht_att [NN*PP*CC];
__device__ float g_rs     [RR*DD];
__device__ float g_hs2    [RR*DD];
__device__ float g_ts2    [RR*DD];

// W_bil fragments: 3072 chunks x 13 nt x 32 lanes x uint4{hi0,hi1,lo0,lo1}
__device__ __align__(16) unsigned char g_Wp[3072UL*13*32*16];
// W_head/W_tail fragments: [2][96 kc][96 nt][32] uint4   (9.4 MB)
__device__ __align__(16) unsigned char g_Whtp[2UL*96*96*32*16];
// seq fragments: [4][64 kc][96 nt][32] uint4              (12.6 MB)
__device__ __align__(16) unsigned char g_seqf[4UL*64*96*32*16];

// ---------------- bf16 helpers ----------------
__device__ __forceinline__ unsigned pack_bf16x2(float hi_f, float lo_f) {
    unsigned r;
    asm("cvt.rn.bf16x2.f32 %0, %1, %2;" : "=r"(r) : "f"(hi_f), "f"(lo_f));
    return r;
}
// split (p0 lower, p1 upper) into bf16x2 hi + bf16x2 lo residual
__device__ __forceinline__ void split2(float p0, float p1, unsigned& hi, unsigned& lo) {
    hi = pack_bf16x2(p1, p0);
    float f0 = __uint_as_float(hi << 16);
    float f1 = __uint_as_float(hi & 0xffff0000u);
    lo = pack_bf16x2(p1 - f1, p0 - f0);
}
// warp mma: D += A(bf16) * B(bf16), m16n8k16, row.col, fp32 accum
__device__ __forceinline__ void mma_bf16(float* d, const unsigned* a,
                                         unsigned b0, unsigned b1) {
    asm volatile(
        "mma.sync.aligned.m16n8k16.row.col.f32.bf16.bf16.f32 "
        "{%0,%1,%2,%3}, {%4,%5,%6,%7}, {%8,%9}, {%0,%1,%2,%3};"
        : "+f"(d[0]), "+f"(d[1]), "+f"(d[2]), "+f"(d[3])
        : "r"(a[0]), "r"(a[1]), "r"(a[2]), "r"(a[3]), "r"(b0), "r"(b1));
}

// ============================================================================
// P0: pack W_bil into fragment layout. grid 3072, 128 thr
// ============================================================================
__global__ void k_wt(const float* __restrict__ Wb) {
    __shared__ float Wsm[16*104];
    int chunk = blockIdx.x;
    int tid = threadIdx.x;
    int row0 = chunk * 16;

    for (int idx = tid; idx < 16*104; idx += 128) {
        int r = idx / 104, n = idx - r*104;
        Wsm[idx] = (n < NOUT) ? Wb[(size_t)(row0 + r)*NOUT + n] : 0.0f;
    }
    __syncthreads();

    for (int e = tid; e < 13*32; e += 128) {
        int nt = e >> 5, lane = e & 31;
        int g = lane >> 2, t = lane & 3;
        int n = nt*8 + g, k0 = 2*t;
        unsigned hi0, lo0, hi1, lo1;
        split2(Wsm[(k0    )*104 + n], Wsm[(k0 + 1)*104 + n], hi0, lo0);
        split2(Wsm[(k0 + 8)*104 + n], Wsm[(k0 + 9)*104 + n], hi1, lo1);
        *(uint4*)(g_Wp + ((size_t)(chunk*13 + nt)*32 + lane)*16) =
            make_uint4(hi0, hi1, lo0, lo1);
    }
}

// ============================================================================
// P1: pack W_head / W_tail [1536][768] into fragments. grid (96, 2), 256 thr
// ============================================================================
__global__ void k_wht(const float* __restrict__ Wh, const float* __restrict__ Wt) {
    __shared__ float S[16*768];
    int kc = blockIdx.x;
    int w  = blockIdx.y;
    const float* W = w ? Wt : Wh;
    int tid = threadIdx.x;

    for (int idx = tid; idx < 16*768; idx += 256)
        S[idx] = W[(size_t)kc*16*768 + idx];
    __syncthreads();

    for (int e = tid; e < 96*32; e += 256) {
        int nt = e >> 5, lane = e & 31;
        int g = lane >> 2, t = lane & 3;
        int n = nt*8 + g, k0 = 2*t;
        unsigned hi0, lo0, hi1, lo1;
        split2(S[(k0    )*768 + n], S[(k0 + 1)*768 + n], hi0, lo0);
        split2(S[(k0 + 8)*768 + n], S[(k0 + 9)*768 + n], hi1, lo1);
        *(uint4*)(g_Whtp + ((((size_t)w*96 + kc)*96 + nt)*32 + lane)*16) =
            make_uint4(hi0, hi1, lo0, lo1);
    }
}

// ============================================================================
// P2: pack seq [4][1024][768] into fragments (k=c, n=d). grid (64, 4), 256 thr
// ============================================================================
__global__ void k_seqf(const float* __restrict__ seq) {
    __shared__ float S[16*768];
    int kc = blockIdx.x;
    int b  = blockIdx.y;
    int tid = threadIdx.x;

    for (int idx = tid; idx < 16*768; idx += 256)
        S[idx] = seq[((size_t)b*CC + kc*16)*768 + idx];
    __syncthreads();

    for (int e = tid; e < 96*32; e += 256) {
        int nt = e >> 5, lane = e & 31;
        int g = lane >> 2, t = lane & 3;
        int n = nt*8 + g, k0 = 2*t;
        unsigned hi0, lo0, hi1, lo1;
        split2(S[(k0    )*768 + n], S[(k0 + 1)*768 + n], hi0, lo0);
        split2(S[(k0 + 8)*768 + n], S[(k0 + 9)*768 + n], hi1, lo1);
        *(uint4*)(g_seqf + ((((size_t)b*64 + kc)*96 + nt)*32 + lane)*16) =
            make_uint4(hi0, hi1, lo0, lo1);
    }
}

// ============================================================================
// K1: entity embeddings = logsumexp over M mentions
// ============================================================================
__global__ void k_ent_emb(const float* __restrict__ seq,
                          const int*   __restrict__ mpos) {
    int be = blockIdx.x;
    int b  = be / EE;
    const int* mp = mpos + be*MM;
    int p0 = mp[0], p1 = mp[1], p2 = mp[2], p3 = mp[3];
    const float* sb = seq + (long)b*CC*DD;
    for (int dd = threadIdx.x; dd < DD; dd += blockDim.x) {
        float v0 = sb[p0*DD+dd], v1 = sb[p1*DD+dd];
        float v2 = sb[p2*DD+dd], v3 = sb[p3*DD+dd];
        float mx = fmaxf(fmaxf(v0, v1), fmaxf(v2, v3));
        float s  = expf(v0-mx) + expf(v1-mx) + expf(v2-mx) + expf(v3-mx);
        g_ent_emb[be*DD + dd] = mx + logf(s);
    }
}

// ============================================================================
// K2: entity attention = mean over M mention attention rows
// ============================================================================
__global__ void k_ent_att(const float* __restrict__ att,
                          const int*   __restrict__ mpos) {
    int id = blockIdx.x;
    int hd = id % HH;
    int be = id / HH;
    int b  = be / EE;
    const int* mp = mpos + be*MM;
    const float* ab = att + (long)(b*HH + hd)*CC*CC;
    float* ob = g_ent_att + (long)id*CC;
    int q0 = mp[0]*CC, q1 = mp[1]*CC, q2 = mp[2]*CC, q3 = mp[3]*CC;
    for (int c = threadIdx.x; c < CC; c += blockDim.x) {
        float s = ab[q0+c] + ab[q1+c] + ab[q2+c] + ab[q3+c];
        ob[c] = s * 0.25f;
    }
}

// ============================================================================
// K3: ht_att = mean_h(h_att * t_att), row-normalized
// ============================================================================
__global__ void k_ht_att(const int* __restrict__ hts) {
    int bp = blockIdx.x;
    int b  = bp / PP;
    int eh = hts[bp*2 + 0];
    int et = hts[bp*2 + 1];
    const float* ah = g_ent_att + (long)(b*EE + eh)*HH*CC;
    const float* at = g_ent_att + (long)(b*EE + et)*HH*CC;

    float v[4];
    float lsum = 0.f;
    #pragma unroll
    for (int q = 0; q < 4; q++) {
        int c = q*256 + threadIdx.x;
        float s = 0.f;
        #pragma unroll
        for (int hd = 0; hd < HH; hd++)
            s += ah[hd*CC + c] * at[hd*CC + c];
        s *= (1.0f / HH);
        v[q] = s;
        lsum += s;
    }
    __shared__ float red[256];
    red[threadIdx.x] = lsum;
    __syncthreads();
    for (int st = 128; st > 0; st >>= 1) {
        if (threadIdx.x < st) red[threadIdx.x] += red[threadIdx.x + st];
        __syncthreads();
    }
    float inv = 1.0f / (red[0] + 1e-30f);
    #pragma unroll
    for (int q = 0; q < 4; q++) {
        int c = q*256 + threadIdx.x;
        g_ht_att[(long)bp*CC + c] = v[q] * inv;
    }
}

// ============================================================================
// K4: rs = ht_att @ seq via mma.sync split-bf16. grid (12, 8), 128 thr.
// ============================================================================
#define APITCH 20
__global__ void __launch_bounds__(128) k_rs_mma() {
    __shared__ __align__(16) float As[2][128*APITCH];
    __shared__ __align__(16) unsigned char Bb[2][4096];

    int nt0 = blockIdx.x * 8;
    int r0  = blockIdx.y * 128;
    int b   = r0 >> 8;
    int tid = threadIdx.x, wid = tid >> 5, lane = tid & 31;
    int g = lane >> 2, t = lane & 3;

    const float* Arow = g_ht_att + (size_t)(r0 + tid)*CC;
    const char*  Bbase = (const char*)g_seqf + (((size_t)b*64)*96 + nt0)*32*16;
    const size_t kcs = (size_t)96*32*16;

    float4 pa[4]; uint4 pb0, pb1;
    #pragma unroll
    for (int q = 0; q < 4; q++) pa[q] = *(const float4*)(Arow + q*4);
    pb0 = *(const uint4*)(Bbase + tid*16);
    pb1 = *(const uint4*)(Bbase + (tid + 128)*16);
    #pragma unroll
    for (int q = 0; q < 4; q++) *(float4*)&As[0][tid*APITCH + q*4] = pa[q];
    *(uint4*)&Bb[0][tid*16] = pb0;
    *(uint4*)&Bb[0][(tid + 128)*16] = pb1;
    __syncthreads();

    float acc[2][8][4];
    #pragma unroll
    for (int a = 0; a < 2; a++)
        #pragma unroll
        for (int n = 0; n < 8; n++)
            #pragma unroll
            for (int c = 0; c < 4; c++) acc[a][n][c] = 0.0f;

    for (int ks = 0; ks < 64; ks++) {
        int s = ks & 1;
        if (ks + 1 < 64) {
            #pragma unroll
            for (int q = 0; q < 4; q++) pa[q] = *(const float4*)(Arow + (ks+1)*16 + q*4);
            const char* bsrc = Bbase + (size_t)(ks+1)*kcs;
            pb0 = *(const uint4*)(bsrc + tid*16);
            pb1 = *(const uint4*)(bsrc + (tid + 128)*16);
        }

        unsigned ahi[2][4], alo[2][4];
        #pragma unroll
        for (int af = 0; af < 2; af++) {
            int ra = wid*32 + af*16 + g;
            int rb = ra + 8;
            float2 a0 = *(const float2*)&As[s][ra*APITCH + 2*t];
            float2 a1 = *(const float2*)&As[s][rb*APITCH + 2*t];
            float2 a2 = *(const float2*)&As[s][ra*APITCH + 2*t + 8];
            float2 a3 = *(const float2*)&As[s][rb*APITCH + 2*t + 8];
            split2(a0.x, a0.y, ahi[af][0], alo[af][0]);
            split2(a1.x, a1.y, ahi[af][1], alo[af][1]);
            split2(a2.x, a2.y, ahi[af][2], alo[af][2]);
            split2(a3.x, a3.y, ahi[af][3], alo[af][3]);
        }

        #pragma unroll
        for (int nt = 0; nt < 8; nt++) {
            uint4 w = *(const uint4*)&Bb[s][(nt*32 + lane)*16];
            #pragma unroll
            for (int af = 0; af < 2; af++) {
                mma_bf16(acc[af][nt], ahi[af], w.x, w.y);
                mma_bf16(acc[af][nt], ahi[af], w.z, w.w);
                mma_bf16(acc[af][nt], alo[af], w.x, w.y);
            }
        }

        __syncthreads();
        if (ks + 1 < 64) {
            #pragma unroll
            for (int q = 0; q < 4; q++) *(float4*)&As[s^1][tid*APITCH + q*4] = pa[q];
            *(uint4*)&Bb[s^1][tid*16] = pb0;
            *(uint4*)&Bb[s^1][(tid + 128)*16] = pb1;
        }
        __syncthreads();
    }

    #pragma unroll
    for (int af = 0; af < 2; af++) {
        int ra = r0 + wid*32 + af*16 + g;
        #pragma unroll
        for (int nt = 0; nt < 8; nt++) {
            int n0 = (nt0 + nt)*8 + 2*t;
            *(float2*)(g_rs + (size_t)ra*DD + n0)     = make_float2(acc[af][nt][0], acc[af][nt][1]);
            *(float2*)(g_rs + (size_t)(ra+8)*DD + n0) = make_float2(acc[af][nt][2], acc[af][nt][3]);
        }
    }
}

// ============================================================================
// K5: hs2/ts2 = tanh(concat(ent_emb[ent], rs) @ W + b) via mma.sync.
// ============================================================================
__global__ void __launch_bounds__(128) k_ht_mma(const float* __restrict__ bh,
                                                const float* __restrict__ bt,
                                                const int* __restrict__ hts) {
    __shared__ __align__(16) float As[2][128*APITCH];
    __shared__ __align__(16) unsigned char Bb[2][4096];

    int nt0 = blockIdx.x * 8;
    int r0  = blockIdx.y * 128;
    int col = blockIdx.z;
    const float* bias = col ? bt : bh;
    float* outm = col ? g_ts2 : g_hs2;

    int tid = threadIdx.x, wid = tid >> 5, lane = tid & 31;
    int g = lane >> 2, t = lane & 3;

    int r = r0 + tid;
    const float* eRow = g_ent_emb + ((size_t)(r >> 8)*EE + hts[r*2 + col])*DD;
    const float* rRow = g_rs + (size_t)r*DD;
    const char*  Bbase = (const char*)g_Whtp + (((size_t)col*96)*96 + nt0)*32*16;
    const size_t kcs = (size_t)96*32*16;

    float4 pa[4]; uint4 pb0, pb1;
    #pragma unroll
    for (int q = 0; q < 4; q++) pa[q] = *(const float4*)(eRow + q*4);
    pb0 = *(const uint4*)(Bbase + tid*16);
    pb1 = *(const uint4*)(Bbase + (tid + 128)*16);
    #pragma unroll
    for (int q = 0; q < 4; q++) *(float4*)&As[0][tid*APITCH + q*4] = pa[q];
    *(uint4*)&Bb[0][tid*16] = pb0;
    *(uint4*)&Bb[0][(tid + 128)*16] = pb1;
    __syncthreads();

    float acc[2][8][4];
    #pragma unroll
    for (int a = 0; a < 2; a++)
        #pragma unroll
        for (int n = 0; n < 8; n++)
            #pragma unroll
            for (int c = 0; c < 4; c++) acc[a][n][c] = 0.0f;

    const int NK = 96;
    for (int ks = 0; ks < NK; ks++) {
        int s = ks & 1;
        if (ks + 1 < NK) {
            int kc = (ks + 1)*16;
            const float* src = (kc < DD) ? (eRow + kc) : (rRow + kc - DD);
            #pragma unroll
            for (int q = 0; q < 4; q++) pa[q] = *(const float4*)(src + q*4);
            const char* bsrc = Bbase + (size_t)(ks+1)*kcs;
            pb0 = *(const uint4*)(bsrc + tid*16);
            pb1 = *(const uint4*)(bsrc + (tid + 128)*16);
        }

        unsigned ahi[2][4], alo[2][4];
        #pragma unroll
        for (int af = 0; af < 2; af++) {
            int ra = wid*32 + af*16 + g;
            int rb = ra + 8;
            float2 a0 = *(const float2*)&As[s][ra*APITCH + 2*t];
            float2 a1 = *(const float2*)&As[s][rb*APITCH + 2*t];
            float2 a2 = *(const float2*)&As[s][ra*APITCH + 2*t + 8];
            float2 a3 = *(const float2*)&As[s][rb*APITCH + 2*t + 8];
            split2(a0.x, a0.y, ahi[af][0], alo[af][0]);
            split2(a1.x, a1.y, ahi[af][1], alo[af][1]);
            split2(a2.x, a2.y, ahi[af][2], alo[af][2]);
            split2(a3.x, a3.y, ahi[af][3], alo[af][3]);
        }

        #pragma unroll
        for (int nt = 0; nt < 8; nt++) {
            uint4 w = *(const uint4*)&Bb[s][(nt*32 + lane)*16];
            #pragma unroll
            for (int af = 0; af < 2; af++) {
                mma_bf16(acc[af][nt], ahi[af], w.x, w.y);
                mma_bf16(acc[af][nt], ahi[af], w.z, w.w);
                mma_bf16(acc[af][nt], alo[af], w.x, w.y);
            }
        }

        __syncthreads();
        if (ks + 1 < NK) {
            #pragma unroll
            for (int q = 0; q < 4; q++) *(float4*)&As[s^1][tid*APITCH + q*4] = pa[q];
            *(uint4*)&Bb[s^1][tid*16] = pb0;
            *(uint4*)&Bb[s^1][(tid + 128)*16] = pb1;
        }
        __syncthreads();
    }

    #pragma unroll
    for (int af = 0; af < 2; af++) {
        int ra = r0 + wid*32 + af*16 + g;
        #pragma unroll
        for (int nt = 0; nt < 8; nt++) {
            int n0 = (nt0 + nt)*8 + 2*t;
            float b0v = bias[n0], b1v = bias[n0 + 1];
            *(float2*)(outm + (size_t)ra*DD + n0) =
                make_float2(tanhf(acc[af][nt][0] + b0v), tanhf(acc[af][nt][1] + b1v));
            *(float2*)(outm + (size_t)(ra+8)*DD + n0) =
                make_float2(tanhf(acc[af][nt][2] + b0v), tanhf(acc[af][nt][3] + b1v));
        }
    }
}

// ============================================================================
// K6: init output with bias
// ============================================================================
__global__ void k_init_out(const float* __restrict__ b_bil, float* __restrict__ out) {
    int i = blockIdx.x*256 + threadIdx.x;
    if (i < RR*NOUT) out[i] = b_bil[i % NOUT];
}

// ============================================================================
// K7: bilinear via warp mma.sync (unchanged)
// ============================================================================
#define TS_OFF  0
#define HS_OFF  33792
#define WB_OFF  42496
#define BIL_SMEM 55808
#define CHUNK_BYTES 6656   // 13 ntiles * 32 lanes * 16B

__global__ void __launch_bounds__(128) k_bil_mma(float* __restrict__ out) {
    extern __shared__ __align__(16) char smem[];
    float* tsS = (float*)(smem + TS_OFF);
    float* hsS = (float*)(smem + HS_OFF);
    char*  Wbuf = smem + WB_OFF;

    const int kb = blockIdx.x >> 2;
    const int qt = blockIdx.x & 3;
    const int r0 = blockIdx.y * 128;
    const int tid  = threadIdx.x;
    const int wid  = tid >> 5;
    const int lane = tid & 31;
    const int g = lane >> 2, t = lane & 3;

    for (int idx = tid; idx < 128*64; idx += 128) {
        int rr = idx >> 6, j = idx & 63;
        tsS[rr*66 + j] = g_ts2[(size_t)(r0 + rr)*DD + kb*64 + j];
    }
    for (int idx = tid; idx < 128*16; idx += 128) {
        int rr = idx >> 4, ii = idx & 15;
        hsS[rr*17 + ii] = g_hs2[(size_t)(r0 + rr)*DD + kb*64 + qt*16 + ii];
    }
    const size_t chunk0 = (size_t)(kb*256 + qt*64);
    {
        const char* src = (const char*)g_Wp + chunk0*CHUNK_BYTES;
        for (int e = tid; e < 416; e += 128)
            *(uint4*)(Wbuf + e*16) = *(const uint4*)(src + e*16);
    }
    __syncthreads();

    float acc[2][13][4];
    #pragma unroll
    for (int a = 0; a < 2; a++)
        #pragma unroll
        for (int n = 0; n < 13; n++)
            #pragma unroll
            for (int c = 0; c < 4; c++) acc[a][n][c] = 0.0f;

    for (int cc = 0; cc < 64; cc++) {
        int s = cc & 1;
        uint4 pw0, pw1, pw2, pw3;
        if (cc + 1 < 64) {
            const char* src = (const char*)g_Wp + (chunk0 + cc + 1)*CHUNK_BYTES;
            pw0 = *(const uint4*)(src + (tid      )*16);
            pw1 = *(const uint4*)(src + (tid + 128)*16);
            pw2 = *(const uint4*)(src + (tid + 256)*16);
            if (tid < 32) pw3 = *(const uint4*)(src + (tid + 384)*16);
        }

        int i_loc = cc >> 2;
        int j0    = (cc & 3) * 16;
        unsigned ahi[2][4], alo[2][4];
        #pragma unroll
        for (int af = 0; af < 2; af++) {
            int ra = wid*32 + af*16 + g;
            int rb = ra + 8;
            float hA = hsS[ra*17 + i_loc];
            float hB = hsS[rb*17 + i_loc];
            float2 tA0 = *(const float2*)&tsS[ra*66 + j0 + 2*t];
            float2 tA1 = *(const float2*)&tsS[ra*66 + j0 + 2*t + 8];
            float2 tB0 = *(const float2*)&tsS[rb*66 + j0 + 2*t];
            float2 tB1 = *(const float2*)&tsS[rb*66 + j0 + 2*t + 8];
            split2(hA*tA0.x, hA*tA0.y, ahi[af][0], alo[af][0]);
            split2(hB*tB0.x, hB*tB0.y, ahi[af][1], alo[af][1]);
            split2(hA*tA1.x, hA*tA1.y, ahi[af][2], alo[af][2]);
            split2(hB*tB1.x, hB*tB1.y, ahi[af][3], alo[af][3]);
        }

        #pragma unroll
        for (int nt = 0; nt < 13; nt++) {
            uint4 w = *(const uint4*)(Wbuf + s*CHUNK_BYTES + (nt*32 + lane)*16);
            #pragma unroll
            for (int af = 0; af < 2; af++) {
                mma_bf16(acc[af][nt], ahi[af], w.x, w.y);
                mma_bf16(acc[af][nt], ahi[af], w.z, w.w);
                mma_bf16(acc[af][nt], alo[af], w.x, w.y);
            }
        }

        __syncthreads();
        if (cc + 1 < 64) {
            char* dst = Wbuf + (s^1)*CHUNK_BYTES;
            *(uint4*)(dst + (tid      )*16) = pw0;
            *(uint4*)(dst + (tid + 128)*16) = pw1;
            *(uint4*)(dst + (tid + 256)*16) = pw2;
            if (tid < 32) *(uint4*)(dst + (tid + 384)*16) = pw3;
        }
        __syncthreads();
    }

    #pragma unroll
    for (int af = 0; af < 2; af++) {
        int r1 = r0 + wid*32 + af*16 + g;
        #pragma unroll
        for (int nt = 0; nt < 13; nt++) {
            int n0 = nt*8 + 2*t;
            const float* a = acc[af][nt];
            if (n0 < NOUT) {
                atomicAdd(&out[(size_t)r1*NOUT + n0],       a[0]);
                atomicAdd(&out[(size_t)(r1+8)*NOUT + n0],   a[2]);
            }
            if (n0 + 1 < NOUT) {
                atomicAdd(&out[(size_t)r1*NOUT + n0 + 1],     a[1]);
                atomicAdd(&out[(size_t)(r1+8)*NOUT + n0 + 1], a[3]);
            }
        }
    }
}

// ============================================================================
// launch: fork-join multi-stream DAG (graph-capturable)
// ============================================================================
extern "C" void kernel_launch(void* const* d_in, const int* in_sizes, int n_in,
                              void* d_out, int out_size) {
    const float* seq    = (const float*)d_in[0];
    const float* att    = (const float*)d_in[1];
    const int*   mpos   = (const int*  )d_in[2];
    const int*   hts    = (const int*  )d_in[3];
    const float* W_head = (const float*)d_in[4];
    const float* b_head = (const float*)d_in[5];
    const float* W_tail = (const float*)d_in[6];
    const float* b_tail = (const float*)d_in[7];
    const float* W_bil  = (const float*)d_in[8];
    const float* b_bil  = (const float*)d_in[9];
    float* out = (float*)d_out;

    // one-time host-side infra (identical GPU work enqueued on every call)
    static cudaStream_t s1, s2, s3;
    static cudaEvent_t evRoot, evA, evB, evC, evD, evF;
    static int inited = 0;
    if (!inited) {
        cudaStreamCreateWithFlags(&s1, cudaStreamNonBlocking);
        cudaStreamCreateWithFlags(&s2, cudaStreamNonBlocking);
        cudaStreamCreateWithFlags(&s3, cudaStreamNonBlocking);
        cudaEventCreateWithFlags(&evRoot, cudaEventDisableTiming);
        cudaEventCreateWithFlags(&evA, cudaEventDisableTiming);
        cudaEventCreateWithFlags(&evB, cudaEventDisableTiming);
        cudaEventCreateWithFlags(&evC, cudaEventDisableTiming);
        cudaEventCreateWithFlags(&evD, cudaEventDisableTiming);
        cudaEventCreateWithFlags(&evF, cudaEventDisableTiming);
        cudaFuncSetAttribute(k_bil_mma, cudaFuncAttributeMaxDynamicSharedMemorySize, BIL_SMEM);
        inited = 1;
    }

    // fork
    cudaEventRecord(evRoot, 0);
    cudaStreamWaitEvent(s1, evRoot, 0);
    cudaStreamWaitEvent(s2, evRoot, 0);
    cudaStreamWaitEvent(s3, evRoot, 0);

    // s1: bilinear weight pack (needed only by k_bil_mma)
    k_wt<<<3072, 128, 0, s1>>>(W_bil);
    cudaEventRecord(evA, s1);

    // s2: seq fragments (needed by k_rs_mma), then head/tail weight pack
    k_seqf<<<dim3(64, 4), 256, 0, s2>>>(seq);
    cudaEventRecord(evC, s2);
    k_wht<<<dim3(96, 2), 256, 0, s2>>>(W_head, W_tail);
    cudaEventRecord(evB, s2);

    // s3: entity embeddings (needed by k_ht_mma), output bias init (k_bil_mma)
    k_ent_emb<<<NN*EE, 256, 0, s3>>>(seq, mpos);
    cudaEventRecord(evD, s3);
    k_init_out<<<(RR*NOUT + 255)/256, 256, 0, s3>>>(b_bil, out);
    cudaEventRecord(evF, s3);

    // main (capture) stream: critical chain
    k_ent_att<<<NN*EE*HH, 256>>>(att, mpos);
    k_ht_att<<<NN*PP, 256>>>(hts);
    cudaStreamWaitEvent(0, evC, 0);
    k_rs_mma<<<dim3(12, 8), 128>>>();
    cudaStreamWaitEvent(0, evB, 0);
    cudaStreamWaitEvent(0, evD, 0);
    k_ht_mma<<<dim3(12, 8, 2), 128>>>(b_head, b_tail, hts);
    cudaStreamWaitEvent(0, evA, 0);
    cudaStreamWaitEvent(0, evF, 0);
    k_bil_mma<<<dim3(KBL*4, RR/128), 128, BIL_SMEM>>>(out);
}

// round 8
// speedup vs baseline: 3.2363x; 1.2149x over previous
#include <cuda_runtime.h>
#include <math.h>

// ---------------- fixed problem shapes ----------------
#define NN   4
#define CC   1024
#define DD   768
#define HH   12
#define EE   32
#define MM   4
#define PP   256
#define RR   (NN*PP)     // 1024
#define KBL  12
#define NOUT 97

// ---------------- scratch ----------------
__device__ float g_ent_emb[NN*EE*DD];
__device__ float g_ent_att[NN*EE*HH*CC];
__device__ float g_ht_att [NN*PP*CC];
__device__ float g_rs     [RR*DD];
__device__ float g_hs2    [RR*DD];
__device__ float g_ts2    [RR*DD];

// W_bil fragments: 3072 chunks x 13 nt x 32 lanes x uint4{hi0,hi1,lo0,lo1}
__device__ __align__(16) unsigned char g_Wp[3072UL*13*32*16];
// W_head/W_tail fragments: [2][96 kc][96 nt][32] uint4   (9.4 MB)
__device__ __align__(16) unsigned char g_Whtp[2UL*96*96*32*16];
// seq fragments: [4][64 kc][96 nt][32] uint4              (12.6 MB)
__device__ __align__(16) unsigned char g_seqf[4UL*64*96*32*16];

// ---------------- bf16 helpers ----------------
__device__ __forceinline__ unsigned pack_bf16x2(float hi_f, float lo_f) {
    unsigned r;
    asm("cvt.rn.bf16x2.f32 %0, %1, %2;" : "=r"(r) : "f"(hi_f), "f"(lo_f));
    return r;
}
// split (p0 lower, p1 upper) into bf16x2 hi + bf16x2 lo residual
__device__ __forceinline__ void split2(float p0, float p1, unsigned& hi, unsigned& lo) {
    hi = pack_bf16x2(p1, p0);
    float f0 = __uint_as_float(hi << 16);
    float f1 = __uint_as_float(hi & 0xffff0000u);
    lo = pack_bf16x2(p1 - f1, p0 - f0);
}
// warp mma: D += A(bf16) * B(bf16), m16n8k16, row.col, fp32 accum
__device__ __forceinline__ void mma_bf16(float* d, const unsigned* a,
                                         unsigned b0, unsigned b1) {
    asm volatile(
        "mma.sync.aligned.m16n8k16.row.col.f32.bf16.bf16.f32 "
        "{%0,%1,%2,%3}, {%4,%5,%6,%7}, {%8,%9}, {%0,%1,%2,%3};"
        : "+f"(d[0]), "+f"(d[1]), "+f"(d[2]), "+f"(d[3])
        : "r"(a[0]), "r"(a[1]), "r"(a[2]), "r"(a[3]), "r"(b0), "r"(b1));
}

// ============================================================================
// P0: pack W_bil into fragment layout. grid 3072, 128 thr
// ============================================================================
__global__ void k_wt(const float* __restrict__ Wb) {
    __shared__ float Wsm[16*104];
    int chunk = blockIdx.x;
    int tid = threadIdx.x;
    int row0 = chunk * 16;

    for (int idx = tid; idx < 16*104; idx += 128) {
        int r = idx / 104, n = idx - r*104;
        Wsm[idx] = (n < NOUT) ? Wb[(size_t)(row0 + r)*NOUT + n] : 0.0f;
    }
    __syncthreads();

    for (int e = tid; e < 13*32; e += 128) {
        int nt = e >> 5, lane = e & 31;
        int g = lane >> 2, t = lane & 3;
        int n = nt*8 + g, k0 = 2*t;
        unsigned hi0, lo0, hi1, lo1;
        split2(Wsm[(k0    )*104 + n], Wsm[(k0 + 1)*104 + n], hi0, lo0);
        split2(Wsm[(k0 + 8)*104 + n], Wsm[(k0 + 9)*104 + n], hi1, lo1);
        *(uint4*)(g_Wp + ((size_t)(chunk*13 + nt)*32 + lane)*16) =
            make_uint4(hi0, hi1, lo0, lo1);
    }
}

// ============================================================================
// P1: pack W_head / W_tail [1536][768] into fragments. grid (96, 2), 256 thr
// ============================================================================
__global__ void k_wht(const float* __restrict__ Wh, const float* __restrict__ Wt) {
    __shared__ float S[16*768];
    int kc = blockIdx.x;
    int w  = blockIdx.y;
    const float* W = w ? Wt : Wh;
    int tid = threadIdx.x;

    for (int idx = tid; idx < 16*768; idx += 256)
        S[idx] = W[(size_t)kc*16*768 + idx];
    __syncthreads();

    for (int e = tid; e < 96*32; e += 256) {
        int nt = e >> 5, lane = e & 31;
        int g = lane >> 2, t = lane & 3;
        int n = nt*8 + g, k0 = 2*t;
        unsigned hi0, lo0, hi1, lo1;
        split2(S[(k0    )*768 + n], S[(k0 + 1)*768 + n], hi0, lo0);
        split2(S[(k0 + 8)*768 + n], S[(k0 + 9)*768 + n], hi1, lo1);
        *(uint4*)(g_Whtp + ((((size_t)w*96 + kc)*96 + nt)*32 + lane)*16) =
            make_uint4(hi0, hi1, lo0, lo1);
    }
}

// ============================================================================
// P2: pack seq [4][1024][768] into fragments (k=c, n=d). grid (64, 4), 256 thr
// ============================================================================
__global__ void k_seqf(const float* __restrict__ seq) {
    __shared__ float S[16*768];
    int kc = blockIdx.x;
    int b  = blockIdx.y;
    int tid = threadIdx.x;

    for (int idx = tid; idx < 16*768; idx += 256)
        S[idx] = seq[((size_t)b*CC + kc*16)*768 + idx];
    __syncthreads();

    for (int e = tid; e < 96*32; e += 256) {
        int nt = e >> 5, lane = e & 31;
        int g = lane >> 2, t = lane & 3;
        int n = nt*8 + g, k0 = 2*t;
        unsigned hi0, lo0, hi1, lo1;
        split2(S[(k0    )*768 + n], S[(k0 + 1)*768 + n], hi0, lo0);
        split2(S[(k0 + 8)*768 + n], S[(k0 + 9)*768 + n], hi1, lo1);
        *(uint4*)(g_seqf + ((((size_t)b*64 + kc)*96 + nt)*32 + lane)*16) =
            make_uint4(hi0, hi1, lo0, lo1);
    }
}

// ============================================================================
// K1: entity embeddings = logsumexp over M mentions
// ============================================================================
__global__ void k_ent_emb(const float* __restrict__ seq,
                          const int*   __restrict__ mpos) {
    int be = blockIdx.x;
    int b  = be / EE;
    const int* mp = mpos + be*MM;
    int p0 = mp[0], p1 = mp[1], p2 = mp[2], p3 = mp[3];
    const float* sb = seq + (long)b*CC*DD;
    for (int dd = threadIdx.x; dd < DD; dd += blockDim.x) {
        float v0 = sb[p0*DD+dd], v1 = sb[p1*DD+dd];
        float v2 = sb[p2*DD+dd], v3 = sb[p3*DD+dd];
        float mx = fmaxf(fmaxf(v0, v1), fmaxf(v2, v3));
        float s  = expf(v0-mx) + expf(v1-mx) + expf(v2-mx) + expf(v3-mx);
        g_ent_emb[be*DD + dd] = mx + logf(s);
    }
}

// ============================================================================
// K2: entity attention = mean over M mention attention rows
// ============================================================================
__global__ void k_ent_att(const float* __restrict__ att,
                          const int*   __restrict__ mpos) {
    int id = blockIdx.x;
    int hd = id % HH;
    int be = id / HH;
    int b  = be / EE;
    const int* mp = mpos + be*MM;
    const float* ab = att + (long)(b*HH + hd)*CC*CC;
    float* ob = g_ent_att + (long)id*CC;
    int q0 = mp[0]*CC, q1 = mp[1]*CC, q2 = mp[2]*CC, q3 = mp[3]*CC;
    for (int c = threadIdx.x; c < CC; c += blockDim.x) {
        float s = ab[q0+c] + ab[q1+c] + ab[q2+c] + ab[q3+c];
        ob[c] = s * 0.25f;
    }
}

// ============================================================================
// K3: ht_att = mean_h(h_att * t_att), row-normalized
// ============================================================================
__global__ void k_ht_att(const int* __restrict__ hts) {
    int bp = blockIdx.x;
    int b  = bp / PP;
    int eh = hts[bp*2 + 0];
    int et = hts[bp*2 + 1];
    const float* ah = g_ent_att + (long)(b*EE + eh)*HH*CC;
    const float* at = g_ent_att + (long)(b*EE + et)*HH*CC;

    float v[4];
    float lsum = 0.f;
    #pragma unroll
    for (int q = 0; q < 4; q++) {
        int c = q*256 + threadIdx.x;
        float s = 0.f;
        #pragma unroll
        for (int hd = 0; hd < HH; hd++)
            s += ah[hd*CC + c] * at[hd*CC + c];
        s *= (1.0f / HH);
        v[q] = s;
        lsum += s;
    }
    __shared__ float red[256];
    red[threadIdx.x] = lsum;
    __syncthreads();
    for (int st = 128; st > 0; st >>= 1) {
        if (threadIdx.x < st) red[threadIdx.x] += red[threadIdx.x + st];
        __syncthreads();
    }
    float inv = 1.0f / (red[0] + 1e-30f);
    #pragma unroll
    for (int q = 0; q < 4; q++) {
        int c = q*256 + threadIdx.x;
        g_ht_att[(long)bp*CC + c] = v[q] * inv;
    }
}

// ============================================================================
// K4: rs = ht_att @ seq via mma.sync. grid (12, 32) = 384 CTAs, 128 thr.
// CTA: 32 rows x 64 cols. Warp w owns nt pair {w*2, w*2+1}; B frags in regs;
// A tile 32x16 f32 double-buffered in smem, ONE sync per k-step.
// ============================================================================
__global__ void __launch_bounds__(128) k_rs_mma() {
    __shared__ __align__(16) float As[2][32*20];

    int ntg0 = blockIdx.x * 8;
    int r0   = blockIdx.y * 32;
    int b    = r0 >> 8;
    int tid = threadIdx.x, wid = tid >> 5, lane = tid & 31;
    int g = lane >> 2, t = lane & 3;

    int arow = tid >> 2;             // 0..31
    int acol = (tid & 3) * 4;        // 0,4,8,12
    const float* Arow = g_ht_att + (size_t)(r0 + arow)*CC + acol;

    // warp's two B streams
    const char* Bp0 = (const char*)g_seqf + (((size_t)b*64*96) + ntg0 + wid*2    )*512 + lane*16;
    const char* Bp1 = (const char*)g_seqf + (((size_t)b*64*96) + ntg0 + wid*2 + 1)*512 + lane*16;
    const size_t KSTR = (size_t)96*512;

    // prologue: A tile 0 + B frags 0
    float4 pa = *(const float4*)(Arow);
    uint4 bc0 = *(const uint4*)(Bp0);
    uint4 bc1 = *(const uint4*)(Bp1);
    *(float4*)&As[0][arow*20 + acol] = pa;
    __syncthreads();

    float acc[2][2][4];
    #pragma unroll
    for (int a = 0; a < 2; a++)
        #pragma unroll
        for (int n = 0; n < 2; n++)
            #pragma unroll
            for (int c = 0; c < 4; c++) acc[a][n][c] = 0.0f;

    uint4 pb0, pb1;
    for (int ks = 0; ks < 64; ks++) {
        int s = ks & 1;
        if (ks + 1 < 64) {
            pa  = *(const float4*)(Arow + (ks + 1)*16);
            pb0 = *(const uint4*)(Bp0 + (size_t)(ks + 1)*KSTR);
            pb1 = *(const uint4*)(Bp1 + (size_t)(ks + 1)*KSTR);
        }

        unsigned ahi[2][4], alo[2][4];
        #pragma unroll
        for (int af = 0; af < 2; af++) {
            int ra = af*16 + g, rb = ra + 8;
            float2 a0 = *(const float2*)&As[s][ra*20 + 2*t];
            float2 a1 = *(const float2*)&As[s][rb*20 + 2*t];
            float2 a2 = *(const float2*)&As[s][ra*20 + 2*t + 8];
            float2 a3 = *(const float2*)&As[s][rb*20 + 2*t + 8];
            split2(a0.x, a0.y, ahi[af][0], alo[af][0]);
            split2(a1.x, a1.y, ahi[af][1], alo[af][1]);
            split2(a2.x, a2.y, ahi[af][2], alo[af][2]);
            split2(a3.x, a3.y, ahi[af][3], alo[af][3]);
        }

        #pragma unroll
        for (int af = 0; af < 2; af++) {
            mma_bf16(acc[af][0], ahi[af], bc0.x, bc0.y);
            mma_bf16(acc[af][0], ahi[af], bc0.z, bc0.w);
            mma_bf16(acc[af][0], alo[af], bc0.x, bc0.y);
            mma_bf16(acc[af][1], ahi[af], bc1.x, bc1.y);
            mma_bf16(acc[af][1], ahi[af], bc1.z, bc1.w);
            mma_bf16(acc[af][1], alo[af], bc1.x, bc1.y);
        }

        if (ks + 1 < 64) {
            *(float4*)&As[s^1][arow*20 + acol] = pa;
            bc0 = pb0; bc1 = pb1;
        }
        __syncthreads();
    }

    #pragma unroll
    for (int af = 0; af < 2; af++) {
        int ra = r0 + af*16 + g;
        #pragma unroll
        for (int nt = 0; nt < 2; nt++) {
            int n0 = (ntg0 + wid*2 + nt)*8 + 2*t;
            *(float2*)(g_rs + (size_t)ra*DD + n0)     = make_float2(acc[af][nt][0], acc[af][nt][1]);
            *(float2*)(g_rs + (size_t)(ra+8)*DD + n0) = make_float2(acc[af][nt][2], acc[af][nt][3]);
        }
    }
}

// ============================================================================
// K5: hs2/ts2 = tanh(concat(ent_emb[ent], rs) @ W + b) via mma.sync.
// grid (12, 32, 2) = 768 CTAs, 128 thr. Same shape as k_rs_mma, K=1536.
// ============================================================================
__global__ void __launch_bounds__(128) k_ht_mma(const float* __restrict__ bh,
                                                const float* __restrict__ bt,
                                                const int* __restrict__ hts) {
    __shared__ __align__(16) float As[2][32*20];
    __shared__ int eOff[32];

    int ntg0 = blockIdx.x * 8;
    int r0   = blockIdx.y * 32;
    int col  = blockIdx.z;
    const float* bias = col ? bt : bh;
    float* outm = col ? g_ts2 : g_hs2;

    int tid = threadIdx.x, wid = tid >> 5, lane = tid & 31;
    int g = lane >> 2, t = lane & 3;

    if (tid < 32) {
        int r = r0 + tid;
        eOff[tid] = ((r >> 8)*EE + hts[r*2 + col])*DD;
    }
    __syncthreads();

    int arow = tid >> 2;
    int acol = (tid & 3) * 4;
    const float* rRow = g_rs + (size_t)(r0 + arow)*DD + acol;
    int eBase = eOff[arow] + acol;

    const char* Bp0 = (const char*)g_Whtp + (((size_t)col*96*96) + ntg0 + wid*2    )*512 + lane*16;
    const char* Bp1 = (const char*)g_Whtp + (((size_t)col*96*96) + ntg0 + wid*2 + 1)*512 + lane*16;
    const size_t KSTR = (size_t)96*512;

    float4 pa = *(const float4*)(g_ent_emb + eBase);
    uint4 bc0 = *(const uint4*)(Bp0);
    uint4 bc1 = *(const uint4*)(Bp1);
    *(float4*)&As[0][arow*20 + acol] = pa;
    __syncthreads();

    float acc[2][2][4];
    #pragma unroll
    for (int a = 0; a < 2; a++)
        #pragma unroll
        for (int n = 0; n < 2; n++)
            #pragma unroll
            for (int c = 0; c < 4; c++) acc[a][n][c] = 0.0f;

    uint4 pb0, pb1;
    const int NK = 96;
    for (int ks = 0; ks < NK; ks++) {
        int s = ks & 1;
        if (ks + 1 < NK) {
            int kc = (ks + 1)*16;
            pa = (kc < DD) ? *(const float4*)(g_ent_emb + eBase + kc)
                           : *(const float4*)(rRow + kc - DD);
            pb0 = *(const uint4*)(Bp0 + (size_t)(ks + 1)*KSTR);
            pb1 = *(const uint4*)(Bp1 + (size_t)(ks + 1)*KSTR);
        }

        unsigned ahi[2][4], alo[2][4];
        #pragma unroll
        for (int af = 0; af < 2; af++) {
            int ra = af*16 + g, rb = ra + 8;
            float2 a0 = *(const float2*)&As[s][ra*20 + 2*t];
            float2 a1 = *(const float2*)&As[s][rb*20 + 2*t];
            float2 a2 = *(const float2*)&As[s][ra*20 + 2*t + 8];
            float2 a3 = *(const float2*)&As[s][rb*20 + 2*t + 8];
            split2(a0.x, a0.y, ahi[af][0], alo[af][0]);
            split2(a1.x, a1.y, ahi[af][1], alo[af][1]);
            split2(a2.x, a2.y, ahi[af][2], alo[af][2]);
            split2(a3.x, a3.y, ahi[af][3], alo[af][3]);
        }

        #pragma unroll
        for (int af = 0; af < 2; af++) {
            mma_bf16(acc[af][0], ahi[af], bc0.x, bc0.y);
            mma_bf16(acc[af][0], ahi[af], bc0.z, bc0.w);
            mma_bf16(acc[af][0], alo[af], bc0.x, bc0.y);
            mma_bf16(acc[af][1], ahi[af], bc1.x, bc1.y);
            mma_bf16(acc[af][1], ahi[af], bc1.z, bc1.w);
            mma_bf16(acc[af][1], alo[af], bc1.x, bc1.y);
        }

        if (ks + 1 < NK) {
            *(float4*)&As[s^1][arow*20 + acol] = pa;
            bc0 = pb0; bc1 = pb1;
        }
        __syncthreads();
    }

    #pragma unroll
    for (int af = 0; af < 2; af++) {
        int ra = r0 + af*16 + g;
        #pragma unroll
        for (int nt = 0; nt < 2; nt++) {
            int n0 = (ntg0 + wid*2 + nt)*8 + 2*t;
            float b0v = bias[n0], b1v = bias[n0 + 1];
            *(float2*)(outm + (size_t)ra*DD + n0) =
                make_float2(tanhf(acc[af][nt][0] + b0v), tanhf(acc[af][nt][1] + b1v));
            *(float2*)(outm + (size_t)(ra+8)*DD + n0) =
                make_float2(tanhf(acc[af][nt][2] + b0v), tanhf(acc[af][nt][3] + b1v));
        }
    }
}

// ============================================================================
// K6: init output with bias
// ============================================================================
__global__ void k_init_out(const float* __restrict__ b_bil, float* __restrict__ out) {
    int i = blockIdx.x*256 + threadIdx.x;
    if (i < RR*NOUT) out[i] = b_bil[i % NOUT];
}

// ============================================================================
// K7: bilinear via warp mma.sync (unchanged)
// ============================================================================
#define TS_OFF  0
#define HS_OFF  33792
#define WB_OFF  42496
#define BIL_SMEM 55808
#define CHUNK_BYTES 6656   // 13 ntiles * 32 lanes * 16B

__global__ void __launch_bounds__(128) k_bil_mma(float* __restrict__ out) {
    extern __shared__ __align__(16) char smem[];
    float* tsS = (float*)(smem + TS_OFF);
    float* hsS = (float*)(smem + HS_OFF);
    char*  Wbuf = smem + WB_OFF;

    const int kb = blockIdx.x >> 2;
    const int qt = blockIdx.x & 3;
    const int r0 = blockIdx.y * 128;
    const int tid  = threadIdx.x;
    const int wid  = tid >> 5;
    const int lane = tid & 31;
    const int g = lane >> 2, t = lane & 3;

    for (int idx = tid; idx < 128*64; idx += 128) {
        int rr = idx >> 6, j = idx & 63;
        tsS[rr*66 + j] = g_ts2[(size_t)(r0 + rr)*DD + kb*64 + j];
    }
    for (int idx = tid; idx < 128*16; idx += 128) {
        int rr = idx >> 4, ii = idx & 15;
        hsS[rr*17 + ii] = g_hs2[(size_t)(r0 + rr)*DD + kb*64 + qt*16 + ii];
    }
    const size_t chunk0 = (size_t)(kb*256 + qt*64);
    {
        const char* src = (const char*)g_Wp + chunk0*CHUNK_BYTES;
        for (int e = tid; e < 416; e += 128)
            *(uint4*)(Wbuf + e*16) = *(const uint4*)(src + e*16);
    }
    __syncthreads();

    float acc[2][13][4];
    #pragma unroll
    for (int a = 0; a < 2; a++)
        #pragma unroll
        for (int n = 0; n < 13; n++)
            #pragma unroll
            for (int c = 0; c < 4; c++) acc[a][n][c] = 0.0f;

    for (int cc = 0; cc < 64; cc++) {
        int s = cc & 1;
        uint4 pw0, pw1, pw2, pw3;
        if (cc + 1 < 64) {
            const char* src = (const char*)g_Wp + (chunk0 + cc + 1)*CHUNK_BYTES;
            pw0 = *(const uint4*)(src + (tid      )*16);
            pw1 = *(const uint4*)(src + (tid + 128)*16);
            pw2 = *(const uint4*)(src + (tid + 256)*16);
            if (tid < 32) pw3 = *(const uint4*)(src + (tid + 384)*16);
        }

        int i_loc = cc >> 2;
        int j0    = (cc & 3) * 16;
        unsigned ahi[2][4], alo[2][4];
        #pragma unroll
        for (int af = 0; af < 2; af++) {
            int ra = wid*32 + af*16 + g;
            int rb = ra + 8;
            float hA = hsS[ra*17 + i_loc];
            float hB = hsS[rb*17 + i_loc];
            float2 tA0 = *(const float2*)&tsS[ra*66 + j0 + 2*t];
            float2 tA1 = *(const float2*)&tsS[ra*66 + j0 + 2*t + 8];
            float2 tB0 = *(const float2*)&tsS[rb*66 + j0 + 2*t];
            float2 tB1 = *(const float2*)&tsS[rb*66 + j0 + 2*t + 8];
            split2(hA*tA0.x, hA*tA0.y, ahi[af][0], alo[af][0]);
            split2(hB*tB0.x, hB*tB0.y, ahi[af][1], alo[af][1]);
            split2(hA*tA1.x, hA*tA1.y, ahi[af][2], alo[af][2]);
            split2(hB*tB1.x, hB*tB1.y, ahi[af][3], alo[af][3]);
        }

        #pragma unroll
        for (int nt = 0; nt < 13; nt++) {
            uint4 w = *(const uint4*)(Wbuf + s*CHUNK_BYTES + (nt*32 + lane)*16);
            #pragma unroll
            for (int af = 0; af < 2; af++) {
                mma_bf16(acc[af][nt], ahi[af], w.x, w.y);
                mma_bf16(acc[af][nt], ahi[af], w.z, w.w);
                mma_bf16(acc[af][nt], alo[af], w.x, w.y);
            }
        }

        __syncthreads();
        if (cc + 1 < 64) {
            char* dst = Wbuf + (s^1)*CHUNK_BYTES;
            *(uint4*)(dst + (tid      )*16) = pw0;
            *(uint4*)(dst + (tid + 128)*16) = pw1;
            *(uint4*)(dst + (tid + 256)*16) = pw2;
            if (tid < 32) *(uint4*)(dst + (tid + 384)*16) = pw3;
        }
        __syncthreads();
    }

    #pragma unroll
    for (int af = 0; af < 2; af++) {
        int r1 = r0 + wid*32 + af*16 + g;
        #pragma unroll
        for (int nt = 0; nt < 13; nt++) {
            int n0 = nt*8 + 2*t;
            const float* a = acc[af][nt];
            if (n0 < NOUT) {
                atomicAdd(&out[(size_t)r1*NOUT + n0],       a[0]);
                atomicAdd(&out[(size_t)(r1+8)*NOUT + n0],   a[2]);
            }
            if (n0 + 1 < NOUT) {
                atomicAdd(&out[(size_t)r1*NOUT + n0 + 1],     a[1]);
                atomicAdd(&out[(size_t)(r1+8)*NOUT + n0 + 1], a[3]);
            }
        }
    }
}

// ============================================================================
// launch: fork-join multi-stream DAG (graph-capturable)
// ============================================================================
extern "C" void kernel_launch(void* const* d_in, const int* in_sizes, int n_in,
                              void* d_out, int out_size) {
    const float* seq    = (const float*)d_in[0];
    const float* att    = (const float*)d_in[1];
    const int*   mpos   = (const int*  )d_in[2];
    const int*   hts    = (const int*  )d_in[3];
    const float* W_head = (const float*)d_in[4];
    const float* b_head = (const float*)d_in[5];
    const float* W_tail = (const float*)d_in[6];
    const float* b_tail = (const float*)d_in[7];
    const float* W_bil  = (const float*)d_in[8];
    const float* b_bil  = (const float*)d_in[9];
    float* out = (float*)d_out;

    static cudaStream_t s1, s2, s3;
    static cudaEvent_t evRoot, evA, evB, evC, evD, evF;
    static int inited = 0;
    if (!inited) {
        cudaStreamCreateWithFlags(&s1, cudaStreamNonBlocking);
        cudaStreamCreateWithFlags(&s2, cudaStreamNonBlocking);
        cudaStreamCreateWithFlags(&s3, cudaStreamNonBlocking);
        cudaEventCreateWithFlags(&evRoot, cudaEventDisableTiming);
        cudaEventCreateWithFlags(&evA, cudaEventDisableTiming);
        cudaEventCreateWithFlags(&evB, cudaEventDisableTiming);
        cudaEventCreateWithFlags(&evC, cudaEventDisableTiming);
        cudaEventCreateWithFlags(&evD, cudaEventDisableTiming);
        cudaEventCreateWithFlags(&evF, cudaEventDisableTiming);
        cudaFuncSetAttribute(k_bil_mma, cudaFuncAttributeMaxDynamicSharedMemorySize, BIL_SMEM);
        inited = 1;
    }

    cudaEventRecord(evRoot, 0);
    cudaStreamWaitEvent(s1, evRoot, 0);
    cudaStreamWaitEvent(s2, evRoot, 0);
    cudaStreamWaitEvent(s3, evRoot, 0);

    // s1: bilinear weight pack
    k_wt<<<3072, 128, 0, s1>>>(W_bil);
    cudaEventRecord(evA, s1);

    // s2: seq fragments, then head/tail weight pack
    k_seqf<<<dim3(64, 4), 256, 0, s2>>>(seq);
    cudaEventRecord(evC, s2);
    k_wht<<<dim3(96, 2), 256, 0, s2>>>(W_head, W_tail);
    cudaEventRecord(evB, s2);

    // s3: entity embeddings, output bias init
    k_ent_emb<<<NN*EE, 256, 0, s3>>>(seq, mpos);
    cudaEventRecord(evD, s3);
    k_init_out<<<(RR*NOUT + 255)/256, 256, 0, s3>>>(b_bil, out);
    cudaEventRecord(evF, s3);

    // main stream: critical chain
    k_ent_att<<<NN*EE*HH, 256>>>(att, mpos);
    k_ht_att<<<NN*PP, 256>>>(hts);
    cudaStreamWaitEvent(0, evC, 0);
    k_rs_mma<<<dim3(12, 32), 128>>>();
    cudaStreamWaitEvent(0, evB, 0);
    cudaStreamWaitEvent(0, evD, 0);
    k_ht_mma<<<dim3(12, 32, 2), 128>>>(b_head, b_tail, hts);
    cudaStreamWaitEvent(0, evA, 0);
    cudaStreamWaitEvent(0, evF, 0);
    k_bil_mma<<<dim3(KBL*4, RR/128), 128, BIL_SMEM>>>(out);
}

// round 9
// speedup vs baseline: 3.9772x; 1.2289x over previous
#include <cuda_runtime.h>
#include <math.h>

// ---------------- fixed problem shapes ----------------
#define NN   4
#define CC   1024
#define DD   768
#define HH   12
#define EE   32
#define MM   4
#define PP   256
#define RR   (NN*PP)     // 1024
#define KBL  12
#define NOUT 97

#define WSCALE     1024.0f
#define WSCALE_INV (1.0f/1024.0f)

// ---------------- scratch ----------------
__device__ float g_ent_emb[NN*EE*DD];
__device__ float g_ent_att[NN*EE*HH*CC];
__device__ float g_ht_att [NN*PP*CC];
__device__ float g_rs     [RR*DD];
__device__ float g_hs2    [RR*DD];
__device__ float g_ts2    [RR*DD];

// W_bil fragments (fp16, x1024): 3072 chunks x 13 nt x 32 lanes x uint2
__device__ __align__(16) unsigned char g_Wp[3072UL*13*32*8];
// W_head/W_tail fragments (fp16, x1024): [2][96 kc][96 nt][32] uint2
__device__ __align__(16) unsigned char g_Whtp[2UL*96*96*32*8];
// seq fragments (fp16, unscaled): [4][64 kc][96 nt][32] uint2
__device__ __align__(16) unsigned char g_seqf[4UL*64*96*32*8];

// ---------------- fp16 helpers ----------------
// result: lower16 = f16(lo_f), upper16 = f16(hi_f)
__device__ __forceinline__ unsigned pack_f16x2(float hi_f, float lo_f) {
    unsigned r;
    asm("cvt.rn.f16x2.f32 %0, %1, %2;" : "=r"(r) : "f"(hi_f), "f"(lo_f));
    return r;
}
// split (p0 lower, p1 upper) into f16x2 hi + f16x2 lo residual (~22-bit total)
__device__ __forceinline__ void split2h(float p0, float p1, unsigned& hi, unsigned& lo) {
    hi = pack_f16x2(p1, p0);
    float f0, f1;
    asm("{\n\t.reg .b16 h0, h1;\n\t"
        "mov.b32 {h0, h1}, %2;\n\t"
        "cvt.f32.f16 %0, h0;\n\t"
        "cvt.f32.f16 %1, h1;\n\t}"
        : "=f"(f0), "=f"(f1) : "r"(hi));
    lo = pack_f16x2(p1 - f1, p0 - f0);
}
// warp mma: D += A(f16) * B(f16), m16n8k16, row.col, fp32 accum
__device__ __forceinline__ void mma_f16(float* d, const unsigned* a,
                                        unsigned b0, unsigned b1) {
    asm volatile(
        "mma.sync.aligned.m16n8k16.row.col.f32.f16.f16.f32 "
        "{%0,%1,%2,%3}, {%4,%5,%6,%7}, {%8,%9}, {%0,%1,%2,%3};"
        : "+f"(d[0]), "+f"(d[1]), "+f"(d[2]), "+f"(d[3])
        : "r"(a[0]), "r"(a[1]), "r"(a[2]), "r"(a[3]), "r"(b0), "r"(b1));
}

// ============================================================================
// P0: pack W_bil (x1024, fp16) into B-fragment layout. grid 3072, 128 thr
// ============================================================================
__global__ void k_wt(const float* __restrict__ Wb) {
    __shared__ float Wsm[16*104];
    int chunk = blockIdx.x;
    int tid = threadIdx.x;
    int row0 = chunk * 16;

    for (int idx = tid; idx < 16*104; idx += 128) {
        int r = idx / 104, n = idx - r*104;
        Wsm[idx] = (n < NOUT) ? Wb[(size_t)(row0 + r)*NOUT + n] * WSCALE : 0.0f;
    }
    __syncthreads();

    for (int e = tid; e < 13*32; e += 128) {
        int nt = e >> 5, lane = e & 31;
        int g = lane >> 2, t = lane & 3;
        int n = nt*8 + g, k0 = 2*t;
        unsigned b0 = pack_f16x2(Wsm[(k0 + 1)*104 + n], Wsm[(k0    )*104 + n]);
        unsigned b1 = pack_f16x2(Wsm[(k0 + 9)*104 + n], Wsm[(k0 + 8)*104 + n]);
        *(uint2*)(g_Wp + ((size_t)(chunk*13 + nt)*32 + lane)*8) = make_uint2(b0, b1);
    }
}

// ============================================================================
// P1: pack W_head / W_tail (x1024, fp16). grid (96, 2), 256 thr
// ============================================================================
__global__ void k_wht(const float* __restrict__ Wh, const float* __restrict__ Wt) {
    __shared__ float S[16*768];
    int kc = blockIdx.x;
    int w  = blockIdx.y;
    const float* W = w ? Wt : Wh;
    int tid = threadIdx.x;

    for (int idx = tid; idx < 16*768; idx += 256)
        S[idx] = W[(size_t)kc*16*768 + idx] * WSCALE;
    __syncthreads();

    for (int e = tid; e < 96*32; e += 256) {
        int nt = e >> 5, lane = e & 31;
        int g = lane >> 2, t = lane & 3;
        int n = nt*8 + g, k0 = 2*t;
        unsigned b0 = pack_f16x2(S[(k0 + 1)*768 + n], S[(k0    )*768 + n]);
        unsigned b1 = pack_f16x2(S[(k0 + 9)*768 + n], S[(k0 + 8)*768 + n]);
        *(uint2*)(g_Whtp + ((((size_t)w*96 + kc)*96 + nt)*32 + lane)*8) = make_uint2(b0, b1);
    }
}

// ============================================================================
// P2: pack seq (fp16, unscaled). grid (64, 4), 256 thr
// ============================================================================
__global__ void k_seqf(const float* __restrict__ seq) {
    __shared__ float S[16*768];
    int kc = blockIdx.x;
    int b  = blockIdx.y;
    int tid = threadIdx.x;

    for (int idx = tid; idx < 16*768; idx += 256)
        S[idx] = seq[((size_t)b*CC + kc*16)*768 + idx];
    __syncthreads();

    for (int e = tid; e < 96*32; e += 256) {
        int nt = e >> 5, lane = e & 31;
        int g = lane >> 2, t = lane & 3;
        int n = nt*8 + g, k0 = 2*t;
        unsigned b0 = pack_f16x2(S[(k0 + 1)*768 + n], S[(k0    )*768 + n]);
        unsigned b1 = pack_f16x2(S[(k0 + 9)*768 + n], S[(k0 + 8)*768 + n]);
        *(uint2*)(g_seqf + ((((size_t)b*64 + kc)*96 + nt)*32 + lane)*8) = make_uint2(b0, b1);
    }
}

// ============================================================================
// K1: entity embeddings = logsumexp over M mentions
// ============================================================================
__global__ void k_ent_emb(const float* __restrict__ seq,
                          const int*   __restrict__ mpos) {
    int be = blockIdx.x;
    int b  = be / EE;
    const int* mp = mpos + be*MM;
    int p0 = mp[0], p1 = mp[1], p2 = mp[2], p3 = mp[3];
    const float* sb = seq + (long)b*CC*DD;
    for (int dd = threadIdx.x; dd < DD; dd += blockDim.x) {
        float v0 = sb[p0*DD+dd], v1 = sb[p1*DD+dd];
        float v2 = sb[p2*DD+dd], v3 = sb[p3*DD+dd];
        float mx = fmaxf(fmaxf(v0, v1), fmaxf(v2, v3));
        float s  = expf(v0-mx) + expf(v1-mx) + expf(v2-mx) + expf(v3-mx);
        g_ent_emb[be*DD + dd] = mx + logf(s);
    }
}

// ============================================================================
// K2: entity attention = mean over M mention attention rows
// ============================================================================
__global__ void k_ent_att(const float* __restrict__ att,
                          const int*   __restrict__ mpos) {
    int id = blockIdx.x;
    int hd = id % HH;
    int be = id / HH;
    int b  = be / EE;
    const int* mp = mpos + be*MM;
    const float* ab = att + (long)(b*HH + hd)*CC*CC;
    float* ob = g_ent_att + (long)id*CC;
    int q0 = mp[0]*CC, q1 = mp[1]*CC, q2 = mp[2]*CC, q3 = mp[3]*CC;
    for (int c = threadIdx.x; c < CC; c += blockDim.x) {
        float s = ab[q0+c] + ab[q1+c] + ab[q2+c] + ab[q3+c];
        ob[c] = s * 0.25f;
    }
}

// ============================================================================
// K3: ht_att = mean_h(h_att * t_att), row-normalized
// ============================================================================
__global__ void k_ht_att(const int* __restrict__ hts) {
    int bp = blockIdx.x;
    int b  = bp / PP;
    int eh = hts[bp*2 + 0];
    int et = hts[bp*2 + 1];
    const float* ah = g_ent_att + (long)(b*EE + eh)*HH*CC;
    const float* at = g_ent_att + (long)(b*EE + et)*HH*CC;

    float v[4];
    float lsum = 0.f;
    #pragma unroll
    for (int q = 0; q < 4; q++) {
        int c = q*256 + threadIdx.x;
        float s = 0.f;
        #pragma unroll
        for (int hd = 0; hd < HH; hd++)
            s += ah[hd*CC + c] * at[hd*CC + c];
        s *= (1.0f / HH);
        v[q] = s;
        lsum += s;
    }
    __shared__ float red[256];
    red[threadIdx.x] = lsum;
    __syncthreads();
    for (int st = 128; st > 0; st >>= 1) {
        if (threadIdx.x < st) red[threadIdx.x] += red[threadIdx.x + st];
        __syncthreads();
    }
    float inv = 1.0f / (red[0] + 1e-30f);
    #pragma unroll
    for (int q = 0; q < 4; q++) {
        int c = q*256 + threadIdx.x;
        g_ht_att[(long)bp*CC + c] = v[q] * inv;
    }
}

// ============================================================================
// K4: rs = ht_att @ seq via fp16 2-term mma. grid (12, 32) = 384 CTAs, 128 thr.
// A = ht_att x1024 (2-term split), B = seq fp16 (1-term). Epilogue /1024.
// ============================================================================
__global__ void __launch_bounds__(128) k_rs_mma() {
    __shared__ __align__(16) float As[2][32*20];

    int ntg0 = blockIdx.x * 8;
    int r0   = blockIdx.y * 32;
    int b    = r0 >> 8;
    int tid = threadIdx.x, wid = tid >> 5, lane = tid & 31;
    int g = lane >> 2, t = lane & 3;

    int arow = tid >> 2;
    int acol = (tid & 3) * 4;
    const float* Arow = g_ht_att + (size_t)(r0 + arow)*CC + acol;

    const char* Bp0 = (const char*)g_seqf + (((size_t)b*64*96) + ntg0 + wid*2    )*256 + lane*8;
    const char* Bp1 = (const char*)g_seqf + (((size_t)b*64*96) + ntg0 + wid*2 + 1)*256 + lane*8;
    const size_t KSTR = (size_t)96*256;

    float4 pa = *(const float4*)(Arow);
    pa.x *= WSCALE; pa.y *= WSCALE; pa.z *= WSCALE; pa.w *= WSCALE;
    uint2 bc0 = *(const uint2*)(Bp0);
    uint2 bc1 = *(const uint2*)(Bp1);
    *(float4*)&As[0][arow*20 + acol] = pa;
    __syncthreads();

    float acc[2][2][4];
    #pragma unroll
    for (int a = 0; a < 2; a++)
        #pragma unroll
        for (int n = 0; n < 2; n++)
            #pragma unroll
            for (int c = 0; c < 4; c++) acc[a][n][c] = 0.0f;

    uint2 pb0, pb1;
    for (int ks = 0; ks < 64; ks++) {
        int s = ks & 1;
        if (ks + 1 < 64) {
            pa  = *(const float4*)(Arow + (ks + 1)*16);
            pa.x *= WSCALE; pa.y *= WSCALE; pa.z *= WSCALE; pa.w *= WSCALE;
            pb0 = *(const uint2*)(Bp0 + (size_t)(ks + 1)*KSTR);
            pb1 = *(const uint2*)(Bp1 + (size_t)(ks + 1)*KSTR);
        }

        unsigned ahi[2][4], alo[2][4];
        #pragma unroll
        for (int af = 0; af < 2; af++) {
            int ra = af*16 + g, rb = ra + 8;
            float2 a0 = *(const float2*)&As[s][ra*20 + 2*t];
            float2 a1 = *(const float2*)&As[s][rb*20 + 2*t];
            float2 a2 = *(const float2*)&As[s][ra*20 + 2*t + 8];
            float2 a3 = *(const float2*)&As[s][rb*20 + 2*t + 8];
            split2h(a0.x, a0.y, ahi[af][0], alo[af][0]);
            split2h(a1.x, a1.y, ahi[af][1], alo[af][1]);
            split2h(a2.x, a2.y, ahi[af][2], alo[af][2]);
            split2h(a3.x, a3.y, ahi[af][3], alo[af][3]);
        }

        #pragma unroll
        for (int af = 0; af < 2; af++) {
            mma_f16(acc[af][0], ahi[af], bc0.x, bc0.y);
            mma_f16(acc[af][0], alo[af], bc0.x, bc0.y);
            mma_f16(acc[af][1], ahi[af], bc1.x, bc1.y);
            mma_f16(acc[af][1], alo[af], bc1.x, bc1.y);
        }

        if (ks + 1 < 64) {
            *(float4*)&As[s^1][arow*20 + acol] = pa;
            bc0 = pb0; bc1 = pb1;
        }
        __syncthreads();
    }

    #pragma unroll
    for (int af = 0; af < 2; af++) {
        int ra = r0 + af*16 + g;
        #pragma unroll
        for (int nt = 0; nt < 2; nt++) {
            int n0 = (ntg0 + wid*2 + nt)*8 + 2*t;
            *(float2*)(g_rs + (size_t)ra*DD + n0) =
                make_float2(acc[af][nt][0]*WSCALE_INV, acc[af][nt][1]*WSCALE_INV);
            *(float2*)(g_rs + (size_t)(ra+8)*DD + n0) =
                make_float2(acc[af][nt][2]*WSCALE_INV, acc[af][nt][3]*WSCALE_INV);
        }
    }
}

// ============================================================================
// K5: hs2/ts2 = tanh(concat(ent_emb[ent], rs) @ W + b) via fp16 2-term mma.
// grid (12, 32, 2). A unscaled 2-term; W x1024 1-term. Epilogue /1024 + bias.
// ============================================================================
__global__ void __launch_bounds__(128) k_ht_mma(const float* __restrict__ bh,
                                                const float* __restrict__ bt,
                                                const int* __restrict__ hts) {
    __shared__ __align__(16) float As[2][32*20];
    __shared__ int eOff[32];

    int ntg0 = blockIdx.x * 8;
    int r0   = blockIdx.y * 32;
    int col  = blockIdx.z;
    const float* bias = col ? bt : bh;
    float* outm = col ? g_ts2 : g_hs2;

    int tid = threadIdx.x, wid = tid >> 5, lane = tid & 31;
    int g = lane >> 2, t = lane & 3;

    if (tid < 32) {
        int r = r0 + tid;
        eOff[tid] = ((r >> 8)*EE + hts[r*2 + col])*DD;
    }
    __syncthreads();

    int arow = tid >> 2;
    int acol = (tid & 3) * 4;
    const float* rRow = g_rs + (size_t)(r0 + arow)*DD + acol;
    int eBase = eOff[arow] + acol;

    const char* Bp0 = (const char*)g_Whtp + (((size_t)col*96*96) + ntg0 + wid*2    )*256 + lane*8;
    const char* Bp1 = (const char*)g_Whtp + (((size_t)col*96*96) + ntg0 + wid*2 + 1)*256 + lane*8;
    const size_t KSTR = (size_t)96*256;

    float4 pa = *(const float4*)(g_ent_emb + eBase);
    uint2 bc0 = *(const uint2*)(Bp0);
    uint2 bc1 = *(const uint2*)(Bp1);
    *(float4*)&As[0][arow*20 + acol] = pa;
    __syncthreads();

    float acc[2][2][4];
    #pragma unroll
    for (int a = 0; a < 2; a++)
        #pragma unroll
        for (int n = 0; n < 2; n++)
            #pragma unroll
            for (int c = 0; c < 4; c++) acc[a][n][c] = 0.0f;

    uint2 pb0, pb1;
    const int NK = 96;
    for (int ks = 0; ks < NK; ks++) {
        int s = ks & 1;
        if (ks + 1 < NK) {
            int kc = (ks + 1)*16;
            pa = (kc < DD) ? *(const float4*)(g_ent_emb + eBase + kc)
                           : *(const float4*)(rRow + kc - DD);
            pb0 = *(const uint2*)(Bp0 + (size_t)(ks + 1)*KSTR);
            pb1 = *(const uint2*)(Bp1 + (size_t)(ks + 1)*KSTR);
        }

        unsigned ahi[2][4], alo[2][4];
        #pragma unroll
        for (int af = 0; af < 2; af++) {
            int ra = af*16 + g, rb = ra + 8;
            float2 a0 = *(const float2*)&As[s][ra*20 + 2*t];
            float2 a1 = *(const float2*)&As[s][rb*20 + 2*t];
            float2 a2 = *(const float2*)&As[s][ra*20 + 2*t + 8];
            float2 a3 = *(const float2*)&As[s][rb*20 + 2*t + 8];
            split2h(a0.x, a0.y, ahi[af][0], alo[af][0]);
            split2h(a1.x, a1.y, ahi[af][1], alo[af][1]);
            split2h(a2.x, a2.y, ahi[af][2], alo[af][2]);
            split2h(a3.x, a3.y, ahi[af][3], alo[af][3]);
        }

        #pragma unroll
        for (int af = 0; af < 2; af++) {
            mma_f16(acc[af][0], ahi[af], bc0.x, bc0.y);
            mma_f16(acc[af][0], alo[af], bc0.x, bc0.y);
            mma_f16(acc[af][1], ahi[af], bc1.x, bc1.y);
            mma_f16(acc[af][1], alo[af], bc1.x, bc1.y);
        }

        if (ks + 1 < NK) {
            *(float4*)&As[s^1][arow*20 + acol] = pa;
            bc0 = pb0; bc1 = pb1;
        }
        __syncthreads();
    }

    #pragma unroll
    for (int af = 0; af < 2; af++) {
        int ra = r0 + af*16 + g;
        #pragma unroll
        for (int nt = 0; nt < 2; nt++) {
            int n0 = (ntg0 + wid*2 + nt)*8 + 2*t;
            float b0v = bias[n0], b1v = bias[n0 + 1];
            *(float2*)(outm + (size_t)ra*DD + n0) =
                make_float2(tanhf(acc[af][nt][0]*WSCALE_INV + b0v),
                            tanhf(acc[af][nt][1]*WSCALE_INV + b1v));
            *(float2*)(outm + (size_t)(ra+8)*DD + n0) =
                make_float2(tanhf(acc[af][nt][2]*WSCALE_INV + b0v),
                            tanhf(acc[af][nt][3]*WSCALE_INV + b1v));
        }
    }
}

// ============================================================================
// K6: init output with bias
// ============================================================================
__global__ void k_init_out(const float* __restrict__ b_bil, float* __restrict__ out) {
    int i = blockIdx.x*256 + threadIdx.x;
    if (i < RR*NOUT) out[i] = b_bil[i % NOUT];
}

// ============================================================================
// K7: bilinear via fp16 2-term mma. A = hs*ts (2-term split); W x1024 1-term.
// grid (48, 8), 128 thr. Epilogue /1024 + atomicAdd.
// ============================================================================
#define TS_OFF  0
#define HS_OFF  33792
#define WB_OFF  42496
#define CHUNK_BYTES 3328   // 13 ntiles * 32 lanes * 8B
#define BIL_SMEM (WB_OFF + 2*CHUNK_BYTES)   // 49152

__global__ void __launch_bounds__(128) k_bil_mma(float* __restrict__ out) {
    extern __shared__ __align__(16) char smem[];
    float* tsS = (float*)(smem + TS_OFF);
    float* hsS = (float*)(smem + HS_OFF);
    char*  Wbuf = smem + WB_OFF;

    const int kb = blockIdx.x >> 2;
    const int qt = blockIdx.x & 3;
    const int r0 = blockIdx.y * 128;
    const int tid  = threadIdx.x;
    const int wid  = tid >> 5;
    const int lane = tid & 31;
    const int g = lane >> 2, t = lane & 3;

    for (int idx = tid; idx < 128*64; idx += 128) {
        int rr = idx >> 6, j = idx & 63;
        tsS[rr*66 + j] = g_ts2[(size_t)(r0 + rr)*DD + kb*64 + j];
    }
    for (int idx = tid; idx < 128*16; idx += 128) {
        int rr = idx >> 4, ii = idx & 15;
        hsS[rr*17 + ii] = g_hs2[(size_t)(r0 + rr)*DD + kb*64 + qt*16 + ii];
    }
    const size_t chunk0 = (size_t)(kb*256 + qt*64);
    {
        const char* src = (const char*)g_Wp + chunk0*CHUNK_BYTES;
        for (int e = tid; e < 416; e += 128)
            *(uint2*)(Wbuf + e*8) = *(const uint2*)(src + e*8);
    }
    __syncthreads();

    float acc[2][13][4];
    #pragma unroll
    for (int a = 0; a < 2; a++)
        #pragma unroll
        for (int n = 0; n < 13; n++)
            #pragma unroll
            for (int c = 0; c < 4; c++) acc[a][n][c] = 0.0f;

    for (int cc = 0; cc < 64; cc++) {
        int s = cc & 1;
        uint2 pw0, pw1, pw2, pw3;
        if (cc + 1 < 64) {
            const char* src = (const char*)g_Wp + (chunk0 + cc + 1)*CHUNK_BYTES;
            pw0 = *(const uint2*)(src + (tid      )*8);
            pw1 = *(const uint2*)(src + (tid + 128)*8);
            pw2 = *(const uint2*)(src + (tid + 256)*8);
            if (tid < 32) pw3 = *(const uint2*)(src + (tid + 384)*8);
        }

        int i_loc = cc >> 2;
        int j0    = (cc & 3) * 16;
        unsigned ahi[2][4], alo[2][4];
        #pragma unroll
        for (int af = 0; af < 2; af++) {
            int ra = wid*32 + af*16 + g;
            int rb = ra + 8;
            float hA = hsS[ra*17 + i_loc];
            float hB = hsS[rb*17 + i_loc];
            float2 tA0 = *(const float2*)&tsS[ra*66 + j0 + 2*t];
            float2 tA1 = *(const float2*)&tsS[ra*66 + j0 + 2*t + 8];
            float2 tB0 = *(const float2*)&tsS[rb*66 + j0 + 2*t];
            float2 tB1 = *(const float2*)&tsS[rb*66 + j0 + 2*t + 8];
            split2h(hA*tA0.x, hA*tA0.y, ahi[af][0], alo[af][0]);
            split2h(hB*tB0.x, hB*tB0.y, ahi[af][1], alo[af][1]);
            split2h(hA*tA1.x, hA*tA1.y, ahi[af][2], alo[af][2]);
            split2h(hB*tB1.x, hB*tB1.y, ahi[af][3], alo[af][3]);
        }

        #pragma unroll
        for (int nt = 0; nt < 13; nt++) {
            uint2 w = *(const uint2*)(Wbuf + s*CHUNK_BYTES + (nt*32 + lane)*8);
            #pragma unroll
            for (int af = 0; af < 2; af++) {
                mma_f16(acc[af][nt], ahi[af], w.x, w.y);
                mma_f16(acc[af][nt], alo[af], w.x, w.y);
            }
        }

        __syncthreads();
        if (cc + 1 < 64) {
            char* dst = Wbuf + (s^1)*CHUNK_BYTES;
            *(uint2*)(dst + (tid      )*8) = pw0;
            *(uint2*)(dst + (tid + 128)*8) = pw1;
            *(uint2*)(dst + (tid + 256)*8) = pw2;
            if (tid < 32) *(uint2*)(dst + (tid + 384)*8) = pw3;
        }
        __syncthreads();
    }

    #pragma unroll
    for (int af = 0; af < 2; af++) {
        int r1 = r0 + wid*32 + af*16 + g;
        #pragma unroll
        for (int nt = 0; nt < 13; nt++) {
            int n0 = nt*8 + 2*t;
            const float* a = acc[af][nt];
            if (n0 < NOUT) {
                atomicAdd(&out[(size_t)r1*NOUT + n0],     a[0]*WSCALE_INV);
                atomicAdd(&out[(size_t)(r1+8)*NOUT + n0], a[2]*WSCALE_INV);
            }
            if (n0 + 1 < NOUT) {
                atomicAdd(&out[(size_t)r1*NOUT + n0 + 1],     a[1]*WSCALE_INV);
                atomicAdd(&out[(size_t)(r1+8)*NOUT + n0 + 1], a[3]*WSCALE_INV);
            }
        }
    }
}

// ============================================================================
// launch: fork-join multi-stream DAG (graph-capturable)
// ============================================================================
extern "C" void kernel_launch(void* const* d_in, const int* in_sizes, int n_in,
                              void* d_out, int out_size) {
    const float* seq    = (const float*)d_in[0];
    const float* att    = (const float*)d_in[1];
    const int*   mpos   = (const int*  )d_in[2];
    const int*   hts    = (const int*  )d_in[3];
    const float* W_head = (const float*)d_in[4];
    const float* b_head = (const float*)d_in[5];
    const float* W_tail = (const float*)d_in[6];
    const float* b_tail = (const float*)d_in[7];
    const float* W_bil  = (const float*)d_in[8];
    const float* b_bil  = (const float*)d_in[9];
    float* out = (float*)d_out;

    static cudaStream_t s1, s2, s3;
    static cudaEvent_t evRoot, evA, evB, evC, evD, evF;
    static int inited = 0;
    if (!inited) {
        cudaStreamCreateWithFlags(&s1, cudaStreamNonBlocking);
        cudaStreamCreateWithFlags(&s2, cudaStreamNonBlocking);
        cudaStreamCreateWithFlags(&s3, cudaStreamNonBlocking);
        cudaEventCreateWithFlags(&evRoot, cudaEventDisableTiming);
        cudaEventCreateWithFlags(&evA, cudaEventDisableTiming);
        cudaEventCreateWithFlags(&evB, cudaEventDisableTiming);
        cudaEventCreateWithFlags(&evC, cudaEventDisableTiming);
        cudaEventCreateWithFlags(&evD, cudaEventDisableTiming);
        cudaEventCreateWithFlags(&evF, cudaEventDisableTiming);
        cudaFuncSetAttribute(k_bil_mma, cudaFuncAttributeMaxDynamicSharedMemorySize, BIL_SMEM);
        inited = 1;
    }

    cudaEventRecord(evRoot, 0);
    cudaStreamWaitEvent(s1, evRoot, 0);
    cudaStreamWaitEvent(s2, evRoot, 0);
    cudaStreamWaitEvent(s3, evRoot, 0);

    // s1: bilinear weight pack
    k_wt<<<3072, 128, 0, s1>>>(W_bil);
    cudaEventRecord(evA, s1);

    // s2: seq fragments, then head/tail weight pack
    k_seqf<<<dim3(64, 4), 256, 0, s2>>>(seq);
    cudaEventRecord(evC, s2);
    k_wht<<<dim3(96, 2), 256, 0, s2>>>(W_head, W_tail);
    cudaEventRecord(evB, s2);

    // s3: entity embeddings, output bias init
    k_ent_emb<<<NN*EE, 256, 0, s3>>>(seq, mpos);
    cudaEventRecord(evD, s3);
    k_init_out<<<(RR*NOUT + 255)/256, 256, 0, s3>>>(b_bil, out);
    cudaEventRecord(evF, s3);

    // main stream: critical chain
    k_ent_att<<<NN*EE*HH, 256>>>(att, mpos);
    k_ht_att<<<NN*PP, 256>>>(hts);
    cudaStreamWaitEvent(0, evC, 0);
    k_rs_mma<<<dim3(12, 32), 128>>>();
    cudaStreamWaitEvent(0, evB, 0);
    cudaStreamWaitEvent(0, evD, 0);
    k_ht_mma<<<dim3(12, 32, 2), 128>>>(b_head, b_tail, hts);
    cudaStreamWaitEvent(0, evA, 0);
    cudaStreamWaitEvent(0, evF, 0);
    k_bil_mma<<<dim3(KBL*4, RR/128), 128, BIL_SMEM>>>(out);
}

// round 10
// speedup vs baseline: 4.1026x; 1.0315x over previous
#include <cuda_runtime.h>
#include <math.h>

// ---------------- fixed problem shapes ----------------
#define NN   4
#define CC   1024
#define DD   768
#define HH   12
#define EE   32
#define MM   4
#define PP   256
#define RR   (NN*PP)     // 1024
#define KBL  12
#define NOUT 97

#define WSCALE     1024.0f
#define WSCALE_INV (1.0f/1024.0f)

// ---------------- scratch ----------------
__device__ float g_ent_emb[NN*EE*DD];
__device__ float g_ent_att[NN*EE*HH*CC];
__device__ float g_ht_att [NN*PP*CC];
__device__ float g_rs     [RR*DD];
__device__ float g_hs2    [RR*DD];
__device__ float g_ts2    [RR*DD];

// W_bil fragments (fp16, x1024): 3072 chunks x 13 nt x 32 lanes x uint2
__device__ __align__(16) unsigned char g_Wp[3072UL*13*32*8];
// W_head/W_tail fragments (fp16, x1024): [2][96 kc][96 nt][32] uint2
__device__ __align__(16) unsigned char g_Whtp[2UL*96*96*32*8];
// seq fragments (fp16, unscaled): [4][64 kc][96 nt][32] uint2
__device__ __align__(16) unsigned char g_seqf[4UL*64*96*32*8];

// ---------------- fp16 helpers ----------------
// result: lower16 = f16(lo_f), upper16 = f16(hi_f)
__device__ __forceinline__ unsigned pack_f16x2(float hi_f, float lo_f) {
    unsigned r;
    asm("cvt.rn.f16x2.f32 %0, %1, %2;" : "=r"(r) : "f"(hi_f), "f"(lo_f));
    return r;
}
// split (p0 lower, p1 upper) into f16x2 hi + f16x2 lo residual (~22-bit total)
__device__ __forceinline__ void split2h(float p0, float p1, unsigned& hi, unsigned& lo) {
    hi = pack_f16x2(p1, p0);
    float f0, f1;
    asm("{\n\t.reg .b16 h0, h1;\n\t"
        "mov.b32 {h0, h1}, %2;\n\t"
        "cvt.f32.f16 %0, h0;\n\t"
        "cvt.f32.f16 %1, h1;\n\t}"
        : "=f"(f0), "=f"(f1) : "r"(hi));
    lo = pack_f16x2(p1 - f1, p0 - f0);
}
// warp mma: D += A(f16) * B(f16), m16n8k16, row.col, fp32 accum
__device__ __forceinline__ void mma_f16(float* d, const unsigned* a,
                                        unsigned b0, unsigned b1) {
    asm volatile(
        "mma.sync.aligned.m16n8k16.row.col.f32.f16.f16.f32 "
        "{%0,%1,%2,%3}, {%4,%5,%6,%7}, {%8,%9}, {%0,%1,%2,%3};"
        : "+f"(d[0]), "+f"(d[1]), "+f"(d[2]), "+f"(d[3])
        : "r"(a[0]), "r"(a[1]), "r"(a[2]), "r"(a[3]), "r"(b0), "r"(b1));
}

// ============================================================================
// P0: pack W_bil (x1024, fp16) into B-fragment layout. grid 3072, 128 thr
// ============================================================================
__global__ void k_wt(const float* __restrict__ Wb) {
    __shared__ float Wsm[16*104];
    int chunk = blockIdx.x;
    int tid = threadIdx.x;
    int row0 = chunk * 16;

    for (int idx = tid; idx < 16*104; idx += 128) {
        int r = idx / 104, n = idx - r*104;
        Wsm[idx] = (n < NOUT) ? Wb[(size_t)(row0 + r)*NOUT + n] * WSCALE : 0.0f;
    }
    __syncthreads();

    for (int e = tid; e < 13*32; e += 128) {
        int nt = e >> 5, lane = e & 31;
        int g = lane >> 2, t = lane & 3;
        int n = nt*8 + g, k0 = 2*t;
        unsigned b0 = pack_f16x2(Wsm[(k0 + 1)*104 + n], Wsm[(k0    )*104 + n]);
        unsigned b1 = pack_f16x2(Wsm[(k0 + 9)*104 + n], Wsm[(k0 + 8)*104 + n]);
        *(uint2*)(g_Wp + ((size_t)(chunk*13 + nt)*32 + lane)*8) = make_uint2(b0, b1);
    }
}

// ============================================================================
// P1: pack W_head / W_tail (x1024, fp16). grid (96, 2), 256 thr
// ============================================================================
__global__ void k_wht(const float* __restrict__ Wh, const float* __restrict__ Wt) {
    __shared__ float S[16*768];
    int kc = blockIdx.x;
    int w  = blockIdx.y;
    const float* W = w ? Wt : Wh;
    int tid = threadIdx.x;

    for (int idx = tid; idx < 16*768; idx += 256)
        S[idx] = W[(size_t)kc*16*768 + idx] * WSCALE;
    __syncthreads();

    for (int e = tid; e < 96*32; e += 256) {
        int nt = e >> 5, lane = e & 31;
        int g = lane >> 2, t = lane & 3;
        int n = nt*8 + g, k0 = 2*t;
        unsigned b0 = pack_f16x2(S[(k0 + 1)*768 + n], S[(k0    )*768 + n]);
        unsigned b1 = pack_f16x2(S[(k0 + 9)*768 + n], S[(k0 + 8)*768 + n]);
        *(uint2*)(g_Whtp + ((((size_t)w*96 + kc)*96 + nt)*32 + lane)*8) = make_uint2(b0, b1);
    }
}

// ============================================================================
// P2: pack seq (fp16, unscaled). grid (64, 4), 256 thr
// ============================================================================
__global__ void k_seqf(const float* __restrict__ seq) {
    __shared__ float S[16*768];
    int kc = blockIdx.x;
    int b  = blockIdx.y;
    int tid = threadIdx.x;

    for (int idx = tid; idx < 16*768; idx += 256)
        S[idx] = seq[((size_t)b*CC + kc*16)*768 + idx];
    __syncthreads();

    for (int e = tid; e < 96*32; e += 256) {
        int nt = e >> 5, lane = e & 31;
        int g = lane >> 2, t = lane & 3;
        int n = nt*8 + g, k0 = 2*t;
        unsigned b0 = pack_f16x2(S[(k0 + 1)*768 + n], S[(k0    )*768 + n]);
        unsigned b1 = pack_f16x2(S[(k0 + 9)*768 + n], S[(k0 + 8)*768 + n]);
        *(uint2*)(g_seqf + ((((size_t)b*64 + kc)*96 + nt)*32 + lane)*8) = make_uint2(b0, b1);
    }
}

// ============================================================================
// K1: entity embeddings = logsumexp over M mentions
// ============================================================================
__global__ void k_ent_emb(const float* __restrict__ seq,
                          const int*   __restrict__ mpos) {
    int be = blockIdx.x;
    int b  = be / EE;
    const int* mp = mpos + be*MM;
    int p0 = mp[0], p1 = mp[1], p2 = mp[2], p3 = mp[3];
    const float* sb = seq + (long)b*CC*DD;
    for (int dd = threadIdx.x; dd < DD; dd += blockDim.x) {
        float v0 = sb[p0*DD+dd], v1 = sb[p1*DD+dd];
        float v2 = sb[p2*DD+dd], v3 = sb[p3*DD+dd];
        float mx = fmaxf(fmaxf(v0, v1), fmaxf(v2, v3));
        float s  = expf(v0-mx) + expf(v1-mx) + expf(v2-mx) + expf(v3-mx);
        g_ent_emb[be*DD + dd] = mx + logf(s);
    }
}

// ============================================================================
// K2: entity attention = mean over M mention attention rows
// ============================================================================
__global__ void k_ent_att(const float* __restrict__ att,
                          const int*   __restrict__ mpos) {
    int id = blockIdx.x;
    int hd = id % HH;
    int be = id / HH;
    int b  = be / EE;
    const int* mp = mpos + be*MM;
    const float* ab = att + (long)(b*HH + hd)*CC*CC;
    float* ob = g_ent_att + (long)id*CC;
    int q0 = mp[0]*CC, q1 = mp[1]*CC, q2 = mp[2]*CC, q3 = mp[3]*CC;
    for (int c = threadIdx.x; c < CC; c += blockDim.x) {
        float s = ab[q0+c] + ab[q1+c] + ab[q2+c] + ab[q3+c];
        ob[c] = s * 0.25f;
    }
}

// ============================================================================
// K3: ht_att = mean_h(h_att * t_att), row-normalized
// ============================================================================
__global__ void k_ht_att(const int* __restrict__ hts) {
    int bp = blockIdx.x;
    int b  = bp / PP;
    int eh = hts[bp*2 + 0];
    int et = hts[bp*2 + 1];
    const float* ah = g_ent_att + (long)(b*EE + eh)*HH*CC;
    const float* at = g_ent_att + (long)(b*EE + et)*HH*CC;

    float v[4];
    float lsum = 0.f;
    #pragma unroll
    for (int q = 0; q < 4; q++) {
        int c = q*256 + threadIdx.x;
        float s = 0.f;
        #pragma unroll
        for (int hd = 0; hd < HH; hd++)
            s += ah[hd*CC + c] * at[hd*CC + c];
        s *= (1.0f / HH);
        v[q] = s;
        lsum += s;
    }
    __shared__ float red[256];
    red[threadIdx.x] = lsum;
    __syncthreads();
    for (int st = 128; st > 0; st >>= 1) {
        if (threadIdx.x < st) red[threadIdx.x] += red[threadIdx.x + st];
        __syncthreads();
    }
    float inv = 1.0f / (red[0] + 1e-30f);
    #pragma unroll
    for (int q = 0; q < 4; q++) {
        int c = q*256 + threadIdx.x;
        g_ht_att[(long)bp*CC + c] = v[q] * inv;
    }
}

// ============================================================================
// K4: rs = ht_att @ seq via fp16 2-term mma. grid (12, 32) = 384 CTAs, 128 thr.
// ============================================================================
__global__ void __launch_bounds__(128) k_rs_mma() {
    __shared__ __align__(16) float As[2][32*20];

    int ntg0 = blockIdx.x * 8;
    int r0   = blockIdx.y * 32;
    int b    = r0 >> 8;
    int tid = threadIdx.x, wid = tid >> 5, lane = tid & 31;
    int g = lane >> 2, t = lane & 3;

    int arow = tid >> 2;
    int acol = (tid & 3) * 4;
    const float* Arow = g_ht_att + (size_t)(r0 + arow)*CC + acol;

    const char* Bp0 = (const char*)g_seqf + (((size_t)b*64*96) + ntg0 + wid*2    )*256 + lane*8;
    const char* Bp1 = (const char*)g_seqf + (((size_t)b*64*96) + ntg0 + wid*2 + 1)*256 + lane*8;
    const size_t KSTR = (size_t)96*256;

    float4 pa = *(const float4*)(Arow);
    pa.x *= WSCALE; pa.y *= WSCALE; pa.z *= WSCALE; pa.w *= WSCALE;
    uint2 bc0 = *(const uint2*)(Bp0);
    uint2 bc1 = *(const uint2*)(Bp1);
    *(float4*)&As[0][arow*20 + acol] = pa;
    __syncthreads();

    float acc[2][2][4];
    #pragma unroll
    for (int a = 0; a < 2; a++)
        #pragma unroll
        for (int n = 0; n < 2; n++)
            #pragma unroll
            for (int c = 0; c < 4; c++) acc[a][n][c] = 0.0f;

    uint2 pb0, pb1;
    for (int ks = 0; ks < 64; ks++) {
        int s = ks & 1;
        if (ks + 1 < 64) {
            pa  = *(const float4*)(Arow + (ks + 1)*16);
            pa.x *= WSCALE; pa.y *= WSCALE; pa.z *= WSCALE; pa.w *= WSCALE;
            pb0 = *(const uint2*)(Bp0 + (size_t)(ks + 1)*KSTR);
            pb1 = *(const uint2*)(Bp1 + (size_t)(ks + 1)*KSTR);
        }

        unsigned ahi[2][4], alo[2][4];
        #pragma unroll
        for (int af = 0; af < 2; af++) {
            int ra = af*16 + g, rb = ra + 8;
            float2 a0 = *(const float2*)&As[s][ra*20 + 2*t];
            float2 a1 = *(const float2*)&As[s][rb*20 + 2*t];
            float2 a2 = *(const float2*)&As[s][ra*20 + 2*t + 8];
            float2 a3 = *(const float2*)&As[s][rb*20 + 2*t + 8];
            split2h(a0.x, a0.y, ahi[af][0], alo[af][0]);
            split2h(a1.x, a1.y, ahi[af][1], alo[af][1]);
            split2h(a2.x, a2.y, ahi[af][2], alo[af][2]);
            split2h(a3.x, a3.y, ahi[af][3], alo[af][3]);
        }

        #pragma unroll
        for (int af = 0; af < 2; af++) {
            mma_f16(acc[af][0], ahi[af], bc0.x, bc0.y);
            mma_f16(acc[af][0], alo[af], bc0.x, bc0.y);
            mma_f16(acc[af][1], ahi[af], bc1.x, bc1.y);
            mma_f16(acc[af][1], alo[af], bc1.x, bc1.y);
        }

        if (ks + 1 < 64) {
            *(float4*)&As[s^1][arow*20 + acol] = pa;
            bc0 = pb0; bc1 = pb1;
        }
        __syncthreads();
    }

    #pragma unroll
    for (int af = 0; af < 2; af++) {
        int ra = r0 + af*16 + g;
        #pragma unroll
        for (int nt = 0; nt < 2; nt++) {
            int n0 = (ntg0 + wid*2 + nt)*8 + 2*t;
            *(float2*)(g_rs + (size_t)ra*DD + n0) =
                make_float2(acc[af][nt][0]*WSCALE_INV, acc[af][nt][1]*WSCALE_INV);
            *(float2*)(g_rs + (size_t)(ra+8)*DD + n0) =
                make_float2(acc[af][nt][2]*WSCALE_INV, acc[af][nt][3]*WSCALE_INV);
        }
    }
}

// ============================================================================
// K5: hs2/ts2 = tanh(concat(ent_emb[ent], rs) @ W + b) via fp16 2-term mma.
// grid (12, 32, 2).
// ============================================================================
__global__ void __launch_bounds__(128) k_ht_mma(const float* __restrict__ bh,
                                                const float* __restrict__ bt,
                                                const int* __restrict__ hts) {
    __shared__ __align__(16) float As[2][32*20];
    __shared__ int eOff[32];

    int ntg0 = blockIdx.x * 8;
    int r0   = blockIdx.y * 32;
    int col  = blockIdx.z;
    const float* bias = col ? bt : bh;
    float* outm = col ? g_ts2 : g_hs2;

    int tid = threadIdx.x, wid = tid >> 5, lane = tid & 31;
    int g = lane >> 2, t = lane & 3;

    if (tid < 32) {
        int r = r0 + tid;
        eOff[tid] = ((r >> 8)*EE + hts[r*2 + col])*DD;
    }
    __syncthreads();

    int arow = tid >> 2;
    int acol = (tid & 3) * 4;
    const float* rRow = g_rs + (size_t)(r0 + arow)*DD + acol;
    int eBase = eOff[arow] + acol;

    const char* Bp0 = (const char*)g_Whtp + (((size_t)col*96*96) + ntg0 + wid*2    )*256 + lane*8;
    const char* Bp1 = (const char*)g_Whtp + (((size_t)col*96*96) + ntg0 + wid*2 + 1)*256 + lane*8;
    const size_t KSTR = (size_t)96*256;

    float4 pa = *(const float4*)(g_ent_emb + eBase);
    uint2 bc0 = *(const uint2*)(Bp0);
    uint2 bc1 = *(const uint2*)(Bp1);
    *(float4*)&As[0][arow*20 + acol] = pa;
    __syncthreads();

    float acc[2][2][4];
    #pragma unroll
    for (int a = 0; a < 2; a++)
        #pragma unroll
        for (int n = 0; n < 2; n++)
            #pragma unroll
            for (int c = 0; c < 4; c++) acc[a][n][c] = 0.0f;

    uint2 pb0, pb1;
    const int NK = 96;
    for (int ks = 0; ks < NK; ks++) {
        int s = ks & 1;
        if (ks + 1 < NK) {
            int kc = (ks + 1)*16;
            pa = (kc < DD) ? *(const float4*)(g_ent_emb + eBase + kc)
                           : *(const float4*)(rRow + kc - DD);
            pb0 = *(const uint2*)(Bp0 + (size_t)(ks + 1)*KSTR);
            pb1 = *(const uint2*)(Bp1 + (size_t)(ks + 1)*KSTR);
        }

        unsigned ahi[2][4], alo[2][4];
        #pragma unroll
        for (int af = 0; af < 2; af++) {
            int ra = af*16 + g, rb = ra + 8;
            float2 a0 = *(const float2*)&As[s][ra*20 + 2*t];
            float2 a1 = *(const float2*)&As[s][rb*20 + 2*t];
            float2 a2 = *(const float2*)&As[s][ra*20 + 2*t + 8];
            float2 a3 = *(const float2*)&As[s][rb*20 + 2*t + 8];
            split2h(a0.x, a0.y, ahi[af][0], alo[af][0]);
            split2h(a1.x, a1.y, ahi[af][1], alo[af][1]);
            split2h(a2.x, a2.y, ahi[af][2], alo[af][2]);
            split2h(a3.x, a3.y, ahi[af][3], alo[af][3]);
        }

        #pragma unroll
        for (int af = 0; af < 2; af++) {
            mma_f16(acc[af][0], ahi[af], bc0.x, bc0.y);
            mma_f16(acc[af][0], alo[af], bc0.x, bc0.y);
            mma_f16(acc[af][1], ahi[af], bc1.x, bc1.y);
            mma_f16(acc[af][1], alo[af], bc1.x, bc1.y);
        }

        if (ks + 1 < NK) {
            *(float4*)&As[s^1][arow*20 + acol] = pa;
            bc0 = pb0; bc1 = pb1;
        }
        __syncthreads();
    }

    #pragma unroll
    for (int af = 0; af < 2; af++) {
        int ra = r0 + af*16 + g;
        #pragma unroll
        for (int nt = 0; nt < 2; nt++) {
            int n0 = (ntg0 + wid*2 + nt)*8 + 2*t;
            float b0v = bias[n0], b1v = bias[n0 + 1];
            *(float2*)(outm + (size_t)ra*DD + n0) =
                make_float2(tanhf(acc[af][nt][0]*WSCALE_INV + b0v),
                            tanhf(acc[af][nt][1]*WSCALE_INV + b1v));
            *(float2*)(outm + (size_t)(ra+8)*DD + n0) =
                make_float2(tanhf(acc[af][nt][2]*WSCALE_INV + b0v),
                            tanhf(acc[af][nt][3]*WSCALE_INV + b1v));
        }
    }
}

// ============================================================================
// K6: init output with bias
// ============================================================================
__global__ void k_init_out(const float* __restrict__ b_bil, float* __restrict__ out) {
    int i = blockIdx.x*256 + threadIdx.x;
    if (i < RR*NOUT) out[i] = b_bil[i % NOUT];
}

// ============================================================================
// K7: bilinear via fp16 SINGLE-term A mma (W already single fp16 x1024).
// grid (48, 16) = 768 CTAs, 128 thr, 64-row r-tiles, each warp 16 rows.
// ============================================================================
#define TS_OFF  0
#define HS_OFF  16896                       // 64*66*4
#define WB_OFF  (HS_OFF + 64*17*4)          // 21248
#define CHUNK_BYTES 3328                    // 13 nt * 32 lanes * 8B
#define BIL_SMEM (WB_OFF + 2*CHUNK_BYTES)   // 27904

__global__ void __launch_bounds__(128) k_bil_mma(float* __restrict__ out) {
    extern __shared__ __align__(16) char smem[];
    float* tsS = (float*)(smem + TS_OFF);   // [64 r][66]
    float* hsS = (float*)(smem + HS_OFF);   // [64 r][17]
    char*  Wbuf = smem + WB_OFF;

    const int kb = blockIdx.x >> 2;
    const int qt = blockIdx.x & 3;
    const int r0 = blockIdx.y * 64;
    const int tid  = threadIdx.x;
    const int wid  = tid >> 5;
    const int lane = tid & 31;
    const int g = lane >> 2, t = lane & 3;

    for (int idx = tid; idx < 64*64; idx += 128) {
        int rr = idx >> 6, j = idx & 63;
        tsS[rr*66 + j] = g_ts2[(size_t)(r0 + rr)*DD + kb*64 + j];
    }
    for (int idx = tid; idx < 64*16; idx += 128) {
        int rr = idx >> 4, ii = idx & 15;
        hsS[rr*17 + ii] = g_hs2[(size_t)(r0 + rr)*DD + kb*64 + qt*16 + ii];
    }
    const size_t chunk0 = (size_t)(kb*256 + qt*64);
    {
        const char* src = (const char*)g_Wp + chunk0*CHUNK_BYTES;
        for (int e = tid; e < 416; e += 128)
            *(uint2*)(Wbuf + e*8) = *(const uint2*)(src + e*8);
    }
    __syncthreads();

    float acc[13][4];
    #pragma unroll
    for (int n = 0; n < 13; n++)
        #pragma unroll
        for (int c = 0; c < 4; c++) acc[n][c] = 0.0f;

    for (int cc = 0; cc < 64; cc++) {
        int s = cc & 1;
        uint2 pw0, pw1, pw2, pw3;
        if (cc + 1 < 64) {
            const char* src = (const char*)g_Wp + (chunk0 + cc + 1)*CHUNK_BYTES;
            pw0 = *(const uint2*)(src + (tid      )*8);
            pw1 = *(const uint2*)(src + (tid + 128)*8);
            pw2 = *(const uint2*)(src + (tid + 256)*8);
            if (tid < 32) pw3 = *(const uint2*)(src + (tid + 384)*8);
        }

        int i_loc = cc >> 2;
        int j0    = (cc & 3) * 16;
        // single-term A fragment: rows wid*16+g, +8
        unsigned a[4];
        {
            int ra = wid*16 + g, rb = ra + 8;
            float hA = hsS[ra*17 + i_loc];
            float hB = hsS[rb*17 + i_loc];
            float2 tA0 = *(const float2*)&tsS[ra*66 + j0 + 2*t];
            float2 tA1 = *(const float2*)&tsS[ra*66 + j0 + 2*t + 8];
            float2 tB0 = *(const float2*)&tsS[rb*66 + j0 + 2*t];
            float2 tB1 = *(const float2*)&tsS[rb*66 + j0 + 2*t + 8];
            a[0] = pack_f16x2(hA*tA0.y, hA*tA0.x);
            a[1] = pack_f16x2(hB*tB0.y, hB*tB0.x);
            a[2] = pack_f16x2(hA*tA1.y, hA*tA1.x);
            a[3] = pack_f16x2(hB*tB1.y, hB*tB1.x);
        }

        #pragma unroll
        for (int nt = 0; nt < 13; nt++) {
            uint2 w = *(const uint2*)(Wbuf + s*CHUNK_BYTES + (nt*32 + lane)*8);
            mma_f16(acc[nt], a, w.x, w.y);
        }

        __syncthreads();
        if (cc + 1 < 64) {
            char* dst = Wbuf + (s^1)*CHUNK_BYTES;
            *(uint2*)(dst + (tid      )*8) = pw0;
            *(uint2*)(dst + (tid + 128)*8) = pw1;
            *(uint2*)(dst + (tid + 256)*8) = pw2;
            if (tid < 32) *(uint2*)(dst + (tid + 384)*8) = pw3;
        }
        __syncthreads();
    }

    {
        int r1 = r0 + wid*16 + g;
        #pragma unroll
        for (int nt = 0; nt < 13; nt++) {
            int n0 = nt*8 + 2*t;
            const float* av = acc[nt];
            if (n0 < NOUT) {
                atomicAdd(&out[(size_t)r1*NOUT + n0],     av[0]*WSCALE_INV);
                atomicAdd(&out[(size_t)(r1+8)*NOUT + n0], av[2]*WSCALE_INV);
            }
            if (n0 + 1 < NOUT) {
                atomicAdd(&out[(size_t)r1*NOUT + n0 + 1],     av[1]*WSCALE_INV);
                atomicAdd(&out[(size_t)(r1+8)*NOUT + n0 + 1], av[3]*WSCALE_INV);
            }
        }
    }
}

// ============================================================================
// launch: fork-join multi-stream DAG (graph-capturable)
// ============================================================================
extern "C" void kernel_launch(void* const* d_in, const int* in_sizes, int n_in,
                              void* d_out, int out_size) {
    const float* seq    = (const float*)d_in[0];
    const float* att    = (const float*)d_in[1];
    const int*   mpos   = (const int*  )d_in[2];
    const int*   hts    = (const int*  )d_in[3];
    const float* W_head = (const float*)d_in[4];
    const float* b_head = (const float*)d_in[5];
    const float* W_tail = (const float*)d_in[6];
    const float* b_tail = (const float*)d_in[7];
    const float* W_bil  = (const float*)d_in[8];
    const float* b_bil  = (const float*)d_in[9];
    float* out = (float*)d_out;

    static cudaStream_t s1, s2, s3;
    static cudaEvent_t evRoot, evA, evB, evC, evD, evF;
    static int inited = 0;
    if (!inited) {
        cudaStreamCreateWithFlags(&s1, cudaStreamNonBlocking);
        cudaStreamCreateWithFlags(&s2, cudaStreamNonBlocking);
        cudaStreamCreateWithFlags(&s3, cudaStreamNonBlocking);
        cudaEventCreateWithFlags(&evRoot, cudaEventDisableTiming);
        cudaEventCreateWithFlags(&evA, cudaEventDisableTiming);
        cudaEventCreateWithFlags(&evB, cudaEventDisableTiming);
        cudaEventCreateWithFlags(&evC, cudaEventDisableTiming);
        cudaEventCreateWithFlags(&evD, cudaEventDisableTiming);
        cudaEventCreateWithFlags(&evF, cudaEventDisableTiming);
        cudaFuncSetAttribute(k_bil_mma, cudaFuncAttributeMaxDynamicSharedMemorySize, BIL_SMEM);
        inited = 1;
    }

    cudaEventRecord(evRoot, 0);
    cudaStreamWaitEvent(s1, evRoot, 0);
    cudaStreamWaitEvent(s2, evRoot, 0);
    cudaStreamWaitEvent(s3, evRoot, 0);

    // s1: bilinear weight pack
    k_wt<<<3072, 128, 0, s1>>>(W_bil);
    cudaEventRecord(evA, s1);

    // s2: seq fragments, then head/tail weight pack
    k_seqf<<<dim3(64, 4), 256, 0, s2>>>(seq);
    cudaEventRecord(evC, s2);
    k_wht<<<dim3(96, 2), 256, 0, s2>>>(W_head, W_tail);
    cudaEventRecord(evB, s2);

    // s3: entity embeddings, output bias init
    k_ent_emb<<<NN*EE, 256, 0, s3>>>(seq, mpos);
    cudaEventRecord(evD, s3);
    k_init_out<<<(RR*NOUT + 255)/256, 256, 0, s3>>>(b_bil, out);
    cudaEventRecord(evF, s3);

    // main stream: critical chain
    k_ent_att<<<NN*EE*HH, 256>>>(att, mpos);
    k_ht_att<<<NN*PP, 256>>>(hts);
    cudaStreamWaitEvent(0, evC, 0);
    k_rs_mma<<<dim3(12, 32), 128>>>();
    cudaStreamWaitEvent(0, evB, 0);
    cudaStreamWaitEvent(0, evD, 0);
    k_ht_mma<<<dim3(12, 32, 2), 128>>>(b_head, b_tail, hts);
    cudaStreamWaitEvent(0, evA, 0);
    cudaStreamWaitEvent(0, evF, 0);
    k_bil_mma<<<dim3(KBL*4, RR/64), 128, BIL_SMEM>>>(out);
}

// round 11
// speedup vs baseline: 4.1381x; 1.0087x over previous
#include <cuda_runtime.h>
#include <math.h>

// ---------------- fixed problem shapes ----------------
#define NN   4
#define CC   1024
#define DD   768
#define HH   12
#define EE   32
#define MM   4
#define PP   256
#define RR   (NN*PP)     // 1024
#define KBL  12
#define NOUT 97

#define WSCALE     1024.0f
#define WSCALE_INV (1.0f/1024.0f)

// ---------------- scratch ----------------
__device__ float g_ent_emb[NN*EE*DD];
__device__ float g_ent_att[NN*EE*HH*CC];
__device__ float g_ht_att [NN*PP*CC];
__device__ float g_rs     [RR*DD];
__device__ float g_hs2    [RR*DD];
__device__ float g_ts2    [RR*DD];

// W_bil fragments (fp16, x1024): 3072 chunks x 13 nt x 32 lanes x uint2
__device__ __align__(16) unsigned char g_Wp[3072UL*13*32*8];
// W_head/W_tail fragments (fp16, x1024): [2][96 kc][96 nt][32] uint2
__device__ __align__(16) unsigned char g_Whtp[2UL*96*96*32*8];
// seq fragments (fp16, unscaled): [4][64 kc][96 nt][32] uint2
__device__ __align__(16) unsigned char g_seqf[4UL*64*96*32*8];

// ---------------- fp16 helpers ----------------
__device__ __forceinline__ unsigned pack_f16x2(float hi_f, float lo_f) {
    unsigned r;
    asm("cvt.rn.f16x2.f32 %0, %1, %2;" : "=r"(r) : "f"(hi_f), "f"(lo_f));
    return r;
}
// split (p0 lower, p1 upper) into f16x2 hi + f16x2 lo residual (~22-bit total)
__device__ __forceinline__ void split2h(float p0, float p1, unsigned& hi, unsigned& lo) {
    hi = pack_f16x2(p1, p0);
    float f0, f1;
    asm("{\n\t.reg .b16 h0, h1;\n\t"
        "mov.b32 {h0, h1}, %2;\n\t"
        "cvt.f32.f16 %0, h0;\n\t"
        "cvt.f32.f16 %1, h1;\n\t}"
        : "=f"(f0), "=f"(f1) : "r"(hi));
    lo = pack_f16x2(p1 - f1, p0 - f0);
}
// warp mma: D += A(f16) * B(f16), m16n8k16, row.col, fp32 accum
__device__ __forceinline__ void mma_f16(float* d, const unsigned* a,
                                        unsigned b0, unsigned b1) {
    asm volatile(
        "mma.sync.aligned.m16n8k16.row.col.f32.f16.f16.f32 "
        "{%0,%1,%2,%3}, {%4,%5,%6,%7}, {%8,%9}, {%0,%1,%2,%3};"
        : "+f"(d[0]), "+f"(d[1]), "+f"(d[2]), "+f"(d[3])
        : "r"(a[0]), "r"(a[1]), "r"(a[2]), "r"(a[3]), "r"(b0), "r"(b1));
}

// stage one float4 (pairs p0=2*quad, p0+1) into packed fragment row.
// slot(q) = q<4 ? 4q : 4(q-4)+1 ; hi at slot, lo at slot+2.
__device__ __forceinline__ void stage_pairs(unsigned* dst_row, int quad, float4 v) {
    unsigned hi0, lo0, hi1, lo1;
    split2h(v.x, v.y, hi0, lo0);
    split2h(v.z, v.w, hi1, lo1);
    int p0 = quad*2, p1 = p0 + 1;
    int s0 = (p0 < 4) ? 4*p0 : 4*(p0 - 4) + 1;
    int s1 = (p1 < 4) ? 4*p1 : 4*(p1 - 4) + 1;
    dst_row[s0] = hi0; dst_row[s0 + 2] = lo0;
    dst_row[s1] = hi1; dst_row[s1 + 2] = lo1;
}

// ============================================================================
// P0: pack W_bil (x1024, fp16) into B-fragment layout. grid 3072, 128 thr
// ============================================================================
__global__ void k_wt(const float* __restrict__ Wb) {
    __shared__ float Wsm[16*104];
    int chunk = blockIdx.x;
    int tid = threadIdx.x;
    int row0 = chunk * 16;

    for (int idx = tid; idx < 16*104; idx += 128) {
        int r = idx / 104, n = idx - r*104;
        Wsm[idx] = (n < NOUT) ? Wb[(size_t)(row0 + r)*NOUT + n] * WSCALE : 0.0f;
    }
    __syncthreads();

    for (int e = tid; e < 13*32; e += 128) {
        int nt = e >> 5, lane = e & 31;
        int g = lane >> 2, t = lane & 3;
        int n = nt*8 + g, k0 = 2*t;
        unsigned b0 = pack_f16x2(Wsm[(k0 + 1)*104 + n], Wsm[(k0    )*104 + n]);
        unsigned b1 = pack_f16x2(Wsm[(k0 + 9)*104 + n], Wsm[(k0 + 8)*104 + n]);
        *(uint2*)(g_Wp + ((size_t)(chunk*13 + nt)*32 + lane)*8) = make_uint2(b0, b1);
    }
}

// ============================================================================
// P1: pack W_head / W_tail (x1024, fp16). grid (96, 2), 256 thr
// ============================================================================
__global__ void k_wht(const float* __restrict__ Wh, const float* __restrict__ Wt) {
    __shared__ float S[16*768];
    int kc = blockIdx.x;
    int w  = blockIdx.y;
    const float* W = w ? Wt : Wh;
    int tid = threadIdx.x;

    for (int idx = tid; idx < 16*768; idx += 256)
        S[idx] = W[(size_t)kc*16*768 + idx] * WSCALE;
    __syncthreads();

    for (int e = tid; e < 96*32; e += 256) {
        int nt = e >> 5, lane = e & 31;
        int g = lane >> 2, t = lane & 3;
        int n = nt*8 + g, k0 = 2*t;
        unsigned b0 = pack_f16x2(S[(k0 + 1)*768 + n], S[(k0    )*768 + n]);
        unsigned b1 = pack_f16x2(S[(k0 + 9)*768 + n], S[(k0 + 8)*768 + n]);
        *(uint2*)(g_Whtp + ((((size_t)w*96 + kc)*96 + nt)*32 + lane)*8) = make_uint2(b0, b1);
    }
}

// ============================================================================
// P2: pack seq (fp16, unscaled). grid (64, 4), 256 thr
// ============================================================================
__global__ void k_seqf(const float* __restrict__ seq) {
    __shared__ float S[16*768];
    int kc = blockIdx.x;
    int b  = blockIdx.y;
    int tid = threadIdx.x;

    for (int idx = tid; idx < 16*768; idx += 256)
        S[idx] = seq[((size_t)b*CC + kc*16)*768 + idx];
    __syncthreads();

    for (int e = tid; e < 96*32; e += 256) {
        int nt = e >> 5, lane = e & 31;
        int g = lane >> 2, t = lane & 3;
        int n = nt*8 + g, k0 = 2*t;
        unsigned b0 = pack_f16x2(S[(k0 + 1)*768 + n], S[(k0    )*768 + n]);
        unsigned b1 = pack_f16x2(S[(k0 + 9)*768 + n], S[(k0 + 8)*768 + n]);
        *(uint2*)(g_seqf + ((((size_t)b*64 + kc)*96 + nt)*32 + lane)*8) = make_uint2(b0, b1);
    }
}

// ============================================================================
// K1: entity embeddings = logsumexp over M mentions
// ============================================================================
__global__ void k_ent_emb(const float* __restrict__ seq,
                          const int*   __restrict__ mpos) {
    int be = blockIdx.x;
    int b  = be / EE;
    const int* mp = mpos + be*MM;
    int p0 = mp[0], p1 = mp[1], p2 = mp[2], p3 = mp[3];
    const float* sb = seq + (long)b*CC*DD;
    for (int dd = threadIdx.x; dd < DD; dd += blockDim.x) {
        float v0 = sb[p0*DD+dd], v1 = sb[p1*DD+dd];
        float v2 = sb[p2*DD+dd], v3 = sb[p3*DD+dd];
        float mx = fmaxf(fmaxf(v0, v1), fmaxf(v2, v3));
        float s  = expf(v0-mx) + expf(v1-mx) + expf(v2-mx) + expf(v3-mx);
        g_ent_emb[be*DD + dd] = mx + logf(s);
    }
}

// ============================================================================
// K2: entity attention = mean over M mention attention rows
// ============================================================================
__global__ void k_ent_att(const float* __restrict__ att,
                          const int*   __restrict__ mpos) {
    int id = blockIdx.x;
    int hd = id % HH;
    int be = id / HH;
    int b  = be / EE;
    const int* mp = mpos + be*MM;
    const float* ab = att + (long)(b*HH + hd)*CC*CC;
    float* ob = g_ent_att + (long)id*CC;
    int q0 = mp[0]*CC, q1 = mp[1]*CC, q2 = mp[2]*CC, q3 = mp[3]*CC;
    for (int c = threadIdx.x; c < CC; c += blockDim.x) {
        float s = ab[q0+c] + ab[q1+c] + ab[q2+c] + ab[q3+c];
        ob[c] = s * 0.25f;
    }
}

// ============================================================================
// K3: ht_att = mean_h(h_att * t_att), row-normalized
// ============================================================================
__global__ void k_ht_att(const int* __restrict__ hts) {
    int bp = blockIdx.x;
    int b  = bp / PP;
    int eh = hts[bp*2 + 0];
    int et = hts[bp*2 + 1];
    const float* ah = g_ent_att + (long)(b*EE + eh)*HH*CC;
    const float* at = g_ent_att + (long)(b*EE + et)*HH*CC;

    float v[4];
    float lsum = 0.f;
    #pragma unroll
    for (int q = 0; q < 4; q++) {
        int c = q*256 + threadIdx.x;
        float s = 0.f;
        #pragma unroll
        for (int hd = 0; hd < HH; hd++)
            s += ah[hd*CC + c] * at[hd*CC + c];
        s *= (1.0f / HH);
        v[q] = s;
        lsum += s;
    }
    __shared__ float red[256];
    red[threadIdx.x] = lsum;
    __syncthreads();
    for (int st = 128; st > 0; st >>= 1) {
        if (threadIdx.x < st) red[threadIdx.x] += red[threadIdx.x + st];
        __syncthreads();
    }
    float inv = 1.0f / (red[0] + 1e-30f);
    #pragma unroll
    for (int q = 0; q < 4; q++) {
        int c = q*256 + threadIdx.x;
        g_ht_att[(long)bp*CC + c] = v[q] * inv;
    }
}

// ============================================================================
// K4: rs = ht_att @ seq via fp16 2-term mma, A pre-split at staging.
// grid (12, 32) = 384 CTAs, 128 thr. A fragments in smem (pitch 20 u32).
// ============================================================================
#define APITCH 20
__global__ void __launch_bounds__(128) k_rs_mma() {
    __shared__ __align__(16) unsigned As[2][32*APITCH];

    int ntg0 = blockIdx.x * 8;
    int r0   = blockIdx.y * 32;
    int b    = r0 >> 8;
    int tid = threadIdx.x, wid = tid >> 5, lane = tid & 31;
    int g = lane >> 2, t = lane & 3;

    int arow = tid >> 2;
    int quad = tid & 3;
    const float* Arow = g_ht_att + (size_t)(r0 + arow)*CC + quad*4;

    const char* Bp0 = (const char*)g_seqf + (((size_t)b*64*96) + ntg0 + wid*2    )*256 + lane*8;
    const char* Bp1 = (const char*)g_seqf + (((size_t)b*64*96) + ntg0 + wid*2 + 1)*256 + lane*8;
    const size_t KSTR = (size_t)96*256;

    float4 pa = *(const float4*)(Arow);
    pa.x *= WSCALE; pa.y *= WSCALE; pa.z *= WSCALE; pa.w *= WSCALE;
    uint2 bc0 = *(const uint2*)(Bp0);
    uint2 bc1 = *(const uint2*)(Bp1);
    stage_pairs(&As[0][arow*APITCH], quad, pa);
    __syncthreads();

    float acc[2][2][4];
    #pragma unroll
    for (int a = 0; a < 2; a++)
        #pragma unroll
        for (int n = 0; n < 2; n++)
            #pragma unroll
            for (int c = 0; c < 4; c++) acc[a][n][c] = 0.0f;

    uint2 pb0, pb1;
    for (int ks = 0; ks < 64; ks++) {
        int s = ks & 1;
        if (ks + 1 < 64) {
            pa  = *(const float4*)(Arow + (ks + 1)*16);
            pa.x *= WSCALE; pa.y *= WSCALE; pa.z *= WSCALE; pa.w *= WSCALE;
            pb0 = *(const uint2*)(Bp0 + (size_t)(ks + 1)*KSTR);
            pb1 = *(const uint2*)(Bp1 + (size_t)(ks + 1)*KSTR);
        }

        #pragma unroll
        for (int af = 0; af < 2; af++) {
            int ra = af*16 + g, rb = ra + 8;
            uint4 ua = *(const uint4*)&As[s][ra*APITCH + 4*t];
            uint4 ub = *(const uint4*)&As[s][rb*APITCH + 4*t];
            unsigned ahi[4] = {ua.x, ub.x, ua.y, ub.y};
            unsigned alo[4] = {ua.z, ub.z, ua.w, ub.w};
            mma_f16(acc[af][0], ahi, bc0.x, bc0.y);
            mma_f16(acc[af][0], alo, bc0.x, bc0.y);
            mma_f16(acc[af][1], ahi, bc1.x, bc1.y);
            mma_f16(acc[af][1], alo, bc1.x, bc1.y);
        }

        if (ks + 1 < 64) {
            stage_pairs(&As[s^1][arow*APITCH], quad, pa);
            bc0 = pb0; bc1 = pb1;
        }
        __syncthreads();
    }

    #pragma unroll
    for (int af = 0; af < 2; af++) {
        int ra = r0 + af*16 + g;
        #pragma unroll
        for (int nt = 0; nt < 2; nt++) {
            int n0 = (ntg0 + wid*2 + nt)*8 + 2*t;
            *(float2*)(g_rs + (size_t)ra*DD + n0) =
                make_float2(acc[af][nt][0]*WSCALE_INV, acc[af][nt][1]*WSCALE_INV);
            *(float2*)(g_rs + (size_t)(ra+8)*DD + n0) =
                make_float2(acc[af][nt][2]*WSCALE_INV, acc[af][nt][3]*WSCALE_INV);
        }
    }
}

// ============================================================================
// K5: hs2/ts2 = tanh(concat(ent_emb[ent], rs) @ W + b), A pre-split at staging.
// grid (12, 32, 2).
// ============================================================================
__global__ void __launch_bounds__(128) k_ht_mma(const float* __restrict__ bh,
                                                const float* __restrict__ bt,
                                                const int* __restrict__ hts) {
    __shared__ __align__(16) unsigned As[2][32*APITCH];
    __shared__ int eOff[32];

    int ntg0 = blockIdx.x * 8;
    int r0   = blockIdx.y * 32;
    int col  = blockIdx.z;
    const float* bias = col ? bt : bh;
    float* outm = col ? g_ts2 : g_hs2;

    int tid = threadIdx.x, wid = tid >> 5, lane = tid & 31;
    int g = lane >> 2, t = lane & 3;

    if (tid < 32) {
        int r = r0 + tid;
        eOff[tid] = ((r >> 8)*EE + hts[r*2 + col])*DD;
    }
    __syncthreads();

    int arow = tid >> 2;
    int quad = tid & 3;
    const float* rRow = g_rs + (size_t)(r0 + arow)*DD + quad*4;
    int eBase = eOff[arow] + quad*4;

    const char* Bp0 = (const char*)g_Whtp + (((size_t)col*96*96) + ntg0 + wid*2    )*256 + lane*8;
    const char* Bp1 = (const char*)g_Whtp + (((size_t)col*96*96) + ntg0 + wid*2 + 1)*256 + lane*8;
    const size_t KSTR = (size_t)96*256;

    float4 pa = *(const float4*)(g_ent_emb + eBase);
    uint2 bc0 = *(const uint2*)(Bp0);
    uint2 bc1 = *(const uint2*)(Bp1);
    stage_pairs(&As[0][arow*APITCH], quad, pa);
    __syncthreads();

    float acc[2][2][4];
    #pragma unroll
    for (int a = 0; a < 2; a++)
        #pragma unroll
        for (int n = 0; n < 2; n++)
            #pragma unroll
            for (int c = 0; c < 4; c++) acc[a][n][c] = 0.0f;

    uint2 pb0, pb1;
    const int NK = 96;
    for (int ks = 0; ks < NK; ks++) {
        int s = ks & 1;
        if (ks + 1 < NK) {
            int kc = (ks + 1)*16;
            pa = (kc < DD) ? *(const float4*)(g_ent_emb + eBase + kc)
                           : *(const float4*)(rRow + kc - DD);
            pb0 = *(const uint2*)(Bp0 + (size_t)(ks + 1)*KSTR);
            pb1 = *(const uint2*)(Bp1 + (size_t)(ks + 1)*KSTR);
        }

        #pragma unroll
        for (int af = 0; af < 2; af++) {
            int ra = af*16 + g, rb = ra + 8;
            uint4 ua = *(const uint4*)&As[s][ra*APITCH + 4*t];
            uint4 ub = *(const uint4*)&As[s][rb*APITCH + 4*t];
            unsigned ahi[4] = {ua.x, ub.x, ua.y, ub.y};
            unsigned alo[4] = {ua.z, ub.z, ua.w, ub.w};
            mma_f16(acc[af][0], ahi, bc0.x, bc0.y);
            mma_f16(acc[af][0], alo, bc0.x, bc0.y);
            mma_f16(acc[af][1], ahi, bc1.x, bc1.y);
            mma_f16(acc[af][1], alo, bc1.x, bc1.y);
        }

        if (ks + 1 < NK) {
            stage_pairs(&As[s^1][arow*APITCH], quad, pa);
            bc0 = pb0; bc1 = pb1;
        }
        __syncthreads();
    }

    #pragma unroll
    for (int af = 0; af < 2; af++) {
        int ra = r0 + af*16 + g;
        #pragma unroll
        for (int nt = 0; nt < 2; nt++) {
            int n0 = (ntg0 + wid*2 + nt)*8 + 2*t;
            float b0v = bias[n0], b1v = bias[n0 + 1];
            *(float2*)(outm + (size_t)ra*DD + n0) =
                make_float2(tanhf(acc[af][nt][0]*WSCALE_INV + b0v),
                            tanhf(acc[af][nt][1]*WSCALE_INV + b1v));
            *(float2*)(outm + (size_t)(ra+8)*DD + n0) =
                make_float2(tanhf(acc[af][nt][2]*WSCALE_INV + b0v),
                            tanhf(acc[af][nt][3]*WSCALE_INV + b1v));
        }
    }
}

// ============================================================================
// K6: init output with bias
// ============================================================================
__global__ void k_init_out(const float* __restrict__ b_bil, float* __restrict__ out) {
    int i = blockIdx.x*256 + threadIdx.x;
    if (i < RR*NOUT) out[i] = b_bil[i % NOUT];
}

// ============================================================================
// K7: bilinear via fp16 single-term A mma (unchanged from R10 pass).
// grid (48, 16) = 768 CTAs, 128 thr, 64-row r-tiles.
// ============================================================================
#define TS_OFF  0
#define HS_OFF  16896                       // 64*66*4
#define WB_OFF  (HS_OFF + 64*17*4)          // 21248
#define CHUNK_BYTES 3328                    // 13 nt * 32 lanes * 8B
#define BIL_SMEM (WB_OFF + 2*CHUNK_BYTES)   // 27904

__global__ void __launch_bounds__(128) k_bil_mma(float* __restrict__ out) {
    extern __shared__ __align__(16) char smem[];
    float* tsS = (float*)(smem + TS_OFF);   // [64 r][66]
    float* hsS = (float*)(smem + HS_OFF);   // [64 r][17]
    char*  Wbuf = smem + WB_OFF;

    const int kb = blockIdx.x >> 2;
    const int qt = blockIdx.x & 3;
    const int r0 = blockIdx.y * 64;
    const int tid  = threadIdx.x;
    const int wid  = tid >> 5;
    const int lane = tid & 31;
    const int g = lane >> 2, t = lane & 3;

    for (int idx = tid; idx < 64*64; idx += 128) {
        int rr = idx >> 6, j = idx & 63;
        tsS[rr*66 + j] = g_ts2[(size_t)(r0 + rr)*DD + kb*64 + j];
    }
    for (int idx = tid; idx < 64*16; idx += 128) {
        int rr = idx >> 4, ii = idx & 15;
        hsS[rr*17 + ii] = g_hs2[(size_t)(r0 + rr)*DD + kb*64 + qt*16 + ii];
    }
    const size_t chunk0 = (size_t)(kb*256 + qt*64);
    {
        const char* src = (const char*)g_Wp + chunk0*CHUNK_BYTES;
        for (int e = tid; e < 416; e += 128)
            *(uint2*)(Wbuf + e*8) = *(const uint2*)(src + e*8);
    }
    __syncthreads();

    float acc[13][4];
    #pragma unroll
    for (int n = 0; n < 13; n++)
        #pragma unroll
        for (int c = 0; c < 4; c++) acc[n][c] = 0.0f;

    for (int cc = 0; cc < 64; cc++) {
        int s = cc & 1;
        uint2 pw0, pw1, pw2, pw3;
        if (cc + 1 < 64) {
            const char* src = (const char*)g_Wp + (chunk0 + cc + 1)*CHUNK_BYTES;
            pw0 = *(const uint2*)(src + (tid      )*8);
            pw1 = *(const uint2*)(src + (tid + 128)*8);
            pw2 = *(const uint2*)(src + (tid + 256)*8);
            if (tid < 32) pw3 = *(const uint2*)(src + (tid + 384)*8);
        }

        int i_loc = cc >> 2;
        int j0    = (cc & 3) * 16;
        unsigned a[4];
        {
            int ra = wid*16 + g, rb = ra + 8;
            float hA = hsS[ra*17 + i_loc];
            float hB = hsS[rb*17 + i_loc];
            float2 tA0 = *(const float2*)&tsS[ra*66 + j0 + 2*t];
            float2 tA1 = *(const float2*)&tsS[ra*66 + j0 + 2*t + 8];
            float2 tB0 = *(const float2*)&tsS[rb*66 + j0 + 2*t];
            float2 tB1 = *(const float2*)&tsS[rb*66 + j0 + 2*t + 8];
            a[0] = pack_f16x2(hA*tA0.y, hA*tA0.x);
            a[1] = pack_f16x2(hB*tB0.y, hB*tB0.x);
            a[2] = pack_f16x2(hA*tA1.y, hA*tA1.x);
            a[3] = pack_f16x2(hB*tB1.y, hB*tB1.x);
        }

        #pragma unroll
        for (int nt = 0; nt < 13; nt++) {
            uint2 w = *(const uint2*)(Wbuf + s*CHUNK_BYTES + (nt*32 + lane)*8);
            mma_f16(acc[nt], a, w.x, w.y);
        }

        __syncthreads();
        if (cc + 1 < 64) {
            char* dst = Wbuf + (s^1)*CHUNK_BYTES;
            *(uint2*)(dst + (tid      )*8) = pw0;
            *(uint2*)(dst + (tid + 128)*8) = pw1;
            *(uint2*)(dst + (tid + 256)*8) = pw2;
            if (tid < 32) *(uint2*)(dst + (tid + 384)*8) = pw3;
        }
        __syncthreads();
    }

    {
        int r1 = r0 + wid*16 + g;
        #pragma unroll
        for (int nt = 0; nt < 13; nt++) {
            int n0 = nt*8 + 2*t;
            const float* av = acc[nt];
            if (n0 < NOUT) {
                atomicAdd(&out[(size_t)r1*NOUT + n0],     av[0]*WSCALE_INV);
                atomicAdd(&out[(size_t)(r1+8)*NOUT + n0], av[2]*WSCALE_INV);
            }
            if (n0 + 1 < NOUT) {
                atomicAdd(&out[(size_t)r1*NOUT + n0 + 1],     av[1]*WSCALE_INV);
                atomicAdd(&out[(size_t)(r1+8)*NOUT + n0 + 1], av[3]*WSCALE_INV);
            }
        }
    }
}

// ============================================================================
// launch: fork-join multi-stream DAG (graph-capturable)
// ============================================================================
extern "C" void kernel_launch(void* const* d_in, const int* in_sizes, int n_in,
                              void* d_out, int out_size) {
    const float* seq    = (const float*)d_in[0];
    const float* att    = (const float*)d_in[1];
    const int*   mpos   = (const int*  )d_in[2];
    const int*   hts    = (const int*  )d_in[3];
    const float* W_head = (const float*)d_in[4];
    const float* b_head = (const float*)d_in[5];
    const float* W_tail = (const float*)d_in[6];
    const float* b_tail = (const float*)d_in[7];
    const float* W_bil  = (const float*)d_in[8];
    const float* b_bil  = (const float*)d_in[9];
    float* out = (float*)d_out;

    static cudaStream_t s1, s2, s3;
    static cudaEvent_t evRoot, evA, evB, evC, evD, evF;
    static int inited = 0;
    if (!inited) {
        cudaStreamCreateWithFlags(&s1, cudaStreamNonBlocking);
        cudaStreamCreateWithFlags(&s2, cudaStreamNonBlocking);
        cudaStreamCreateWithFlags(&s3, cudaStreamNonBlocking);
        cudaEventCreateWithFlags(&evRoot, cudaEventDisableTiming);
        cudaEventCreateWithFlags(&evA, cudaEventDisableTiming);
        cudaEventCreateWithFlags(&evB, cudaEventDisableTiming);
        cudaEventCreateWithFlags(&evC, cudaEventDisableTiming);
        cudaEventCreateWithFlags(&evD, cudaEventDisableTiming);
        cudaEventCreateWithFlags(&evF, cudaEventDisableTiming);
        cudaFuncSetAttribute(k_bil_mma, cudaFuncAttributeMaxDynamicSharedMemorySize, BIL_SMEM);
        inited = 1;
    }

    cudaEventRecord(evRoot, 0);
    cudaStreamWaitEvent(s1, evRoot, 0);
    cudaStreamWaitEvent(s2, evRoot, 0);
    cudaStreamWaitEvent(s3, evRoot, 0);

    // s1: bilinear weight pack
    k_wt<<<3072, 128, 0, s1>>>(W_bil);
    cudaEventRecord(evA, s1);

    // s2: seq fragments, then head/tail weight pack
    k_seqf<<<dim3(64, 4), 256, 0, s2>>>(seq);
    cudaEventRecord(evC, s2);
    k_wht<<<dim3(96, 2), 256, 0, s2>>>(W_head, W_tail);
    cudaEventRecord(evB, s2);

    // s3: entity embeddings, output bias init
    k_ent_emb<<<NN*EE, 256, 0, s3>>>(seq, mpos);
    cudaEventRecord(evD, s3);
    k_init_out<<<(RR*NOUT + 255)/256, 256, 0, s3>>>(b_bil, out);
    cudaEventRecord(evF, s3);

    // main stream: critical chain
    k_ent_att<<<NN*EE*HH, 256>>>(att, mpos);
    k_ht_att<<<NN*PP, 256>>>(hts);
    cudaStreamWaitEvent(0, evC, 0);
    k_rs_mma<<<dim3(12, 32), 128>>>();
    cudaStreamWaitEvent(0, evB, 0);
    cudaStreamWaitEvent(0, evD, 0);
    k_ht_mma<<<dim3(12, 32, 2), 128>>>(b_head, b_tail, hts);
    cudaStreamWaitEvent(0, evA, 0);
    cudaStreamWaitEvent(0, evF, 0);
    k_bil_mma<<<dim3(KBL*4, RR/64), 128, BIL_SMEM>>>(out);
}